// round 8
// baseline (speedup 1.0000x reference)
#include <cuda_runtime.h>
#include <cuda_bf16.h>
#include <math.h>
#include <stdint.h>

#define N_NODES 8192
#define H 256
#define NF 256
#define R_MIX 0.3f
#define C_SIM 0.8f
#define LOG2F_ 0.69314718055994530942f
#define MAXM 128
#define ROWSTRIDE 260

// ---------------- scratch (static device globals) ----------------
__device__ uint16_t g_tsh[ 8192 * 256], g_tsl[ 8192 * 256];   // layer-1 scalar out (bf16 hi/lo)
__device__ uint16_t g_tvh[24576 * 256], g_tvl[24576 * 256];   // layer-1 vector out
__device__ float g_si[ 8192 * 256];   // scalar branch output [N,H]
__device__ float g_vi[24576 * 256];   // vector branch output [N,3,H]
__device__ uint16_t g_wh[4][65536];   // weights bf16 hi (k-major, orig layout)
__device__ uint16_t g_wl[4][65536];   // weights bf16 lo
__device__ int   g_chunk[256 * 256];
__device__ int   g_counts [NF];
__device__ int   g_offsets[NF + 1];
__device__ int   g_nodes  [N_NODES];
__device__ float g_svar[NF], g_vvar[NF], g_ssim[NF], g_dir[NF];
__device__ float g_inv_s[N_NODES];
__device__ float g_inv_v[N_NODES * 3];

__device__ __forceinline__ float sspf(float x) {
    float ax = fabsf(x);
    return fmaxf(x, 0.f) + log1pf(__expf(-ax)) - LOG2F_;
}
__device__ __forceinline__ uint32_t pk2(float a, float b) {
    __nv_bfloat162 t = __floats2bfloat162_rn(a, b);
    return *reinterpret_cast<uint32_t*>(&t);
}
__device__ __forceinline__ float bres(float x) {
    __nv_bfloat16 h = __float2bfloat16(x);
    return x - __bfloat162float(h);
}

// ---------------- mma/ldmatrix/cp.async wrappers (sm_103-safe) ----------------
__device__ __forceinline__ void ldsm4(uint32_t addr, uint32_t* r) {
    asm volatile("ldmatrix.sync.aligned.m8n8.x4.shared.b16 {%0,%1,%2,%3}, [%4];"
                 : "=r"(r[0]), "=r"(r[1]), "=r"(r[2]), "=r"(r[3]) : "r"(addr));
}
__device__ __forceinline__ void ldsm4t(uint32_t addr, uint32_t* r) {
    asm volatile("ldmatrix.sync.aligned.m8n8.x4.trans.shared.b16 {%0,%1,%2,%3}, [%4];"
                 : "=r"(r[0]), "=r"(r[1]), "=r"(r[2]), "=r"(r[3]) : "r"(addr));
}
__device__ __forceinline__ void mma16816(float* c, const uint32_t* a, uint32_t b0, uint32_t b1) {
    asm volatile(
        "mma.sync.aligned.m16n8k16.row.col.f32.bf16.bf16.f32 "
        "{%0,%1,%2,%3},{%4,%5,%6,%7},{%8,%9},{%0,%1,%2,%3};"
        : "+f"(c[0]), "+f"(c[1]), "+f"(c[2]), "+f"(c[3])
        : "r"(a[0]), "r"(a[1]), "r"(a[2]), "r"(a[3]), "r"(b0), "r"(b1));
}
__device__ __forceinline__ void cpa16(uint32_t dst, const void* src) {
    asm volatile("cp.async.cg.shared.global [%0], [%1], 16;" :: "r"(dst), "l"(src) : "memory");
}
__device__ __forceinline__ void cpa_commit() {
    asm volatile("cp.async.commit_group;" ::: "memory");
}
__device__ __forceinline__ void cpa_wait0() {
    asm volatile("cp.async.wait_group 0;" ::: "memory");
}

// ---------------- fragment bookkeeping (deterministic counting sort) -----------
__global__ void k_hist(const int* __restrict__ frag) {
    int chunk = blockIdx.x * 8 + (threadIdx.x >> 5);
    int lane = threadIdx.x & 31;
    int i = chunk * 32 + lane;
    int f = frag[i];
    unsigned mask = __match_any_sync(0xffffffffu, f);
    int lr = __popc(mask & ((1u << lane) - 1u));
    if (lr == 0 && f >= 0 && f < NF) g_chunk[chunk * 256 + f] = __popc(mask);
}

__global__ void k_scan2() {
    int t = threadIdx.x;
    int running = 0;
    for (int c = 0; c < 256; c++) {
        int idx = c * 256 + t;
        int v = g_chunk[idx];
        g_chunk[idx] = running;
        running += v;
    }
    g_counts[t] = running;
    __shared__ int s[256];
    s[t] = running;
    __syncthreads();
    for (int d = 1; d < 256; d <<= 1) {
        int v = (t >= d) ? s[t - d] : 0;
        __syncthreads();
        s[t] += v;
        __syncthreads();
    }
    g_offsets[t] = s[t] - running;
    if (t == 255) g_offsets[256] = s[255];
}

__global__ void k_scatter(const int* __restrict__ frag) {
    int chunk = blockIdx.x * 8 + (threadIdx.x >> 5);
    int lane = threadIdx.x & 31;
    int i = chunk * 32 + lane;
    int f = frag[i];
    unsigned mask = __match_any_sync(0xffffffffu, f);
    int lr = __popc(mask & ((1u << lane) - 1u));
    if (f >= 0 && f < NF) {
        int pos = g_offsets[f] + g_chunk[chunk * 256 + f] + lr;
        if (pos >= 0 && pos < N_NODES) g_nodes[pos] = i;
    }
}

// ---------------- weight pre-split to bf16 hi/lo (once) ----------------
__global__ void k_prepw(const float* __restrict__ W1, const float* __restrict__ W2,
                        const float* __restrict__ V1, const float* __restrict__ V2)
{
    int m = blockIdx.y;
    const float* src = (m == 0) ? W1 : (m == 1) ? W2 : (m == 2) ? V1 : V2;
    int i0 = (blockIdx.x * 256 + threadIdx.x) * 4;
    float4 v = *(const float4*)(src + i0);
    uint16_t* oh = g_wh[m];
    uint16_t* ol = g_wl[m];
    *(uint32_t*)&oh[i0]     = pk2(v.x, v.y);
    *(uint32_t*)&oh[i0 + 2] = pk2(v.z, v.w);
    *(uint32_t*)&ol[i0]     = pk2(bres(v.x), bres(v.y));
    *(uint32_t*)&ol[i0 + 2] = pk2(bres(v.z), bres(v.w));
}

// ------------- shared GEMM pieces -------------
#define AROW 24
#define BROW 136
#define A_HL (128 * AROW)
#define B_HL (16 * BROW)
#define NSCALAR_BLOCKS 64

// per-warp 3-term mma over one 16-k chunk. aOff/bOff point at hi plane of buffer.
__device__ __forceinline__ void mma_chunk(uint32_t aOff, uint32_t bOff, float acc[4][4][4]) {
    uint32_t ah[4][4], bh[2][4], tmp[2][4], al4[4];
#pragma unroll
    for (int mt = 0; mt < 4; mt++) ldsm4(aOff + mt * (16 * AROW * 2), ah[mt]);
#pragma unroll
    for (int st = 0; st < 2; st++) ldsm4t(bOff + st * 32, bh[st]);
#pragma unroll
    for (int mt = 0; mt < 4; mt++)
#pragma unroll
        for (int nt = 0; nt < 4; nt++)
            mma16816(acc[mt][nt], ah[mt], bh[nt >> 1][(nt & 1) * 2],
                     bh[nt >> 1][(nt & 1) * 2 + 1]);
#pragma unroll
    for (int st = 0; st < 2; st++) ldsm4t(bOff + B_HL * 2 + st * 32, tmp[st]);
#pragma unroll
    for (int mt = 0; mt < 4; mt++)
#pragma unroll
        for (int nt = 0; nt < 4; nt++)
            mma16816(acc[mt][nt], ah[mt], tmp[nt >> 1][(nt & 1) * 2],
                     tmp[nt >> 1][(nt & 1) * 2 + 1]);
#pragma unroll
    for (int mt = 0; mt < 4; mt++) {
        ldsm4(aOff + A_HL * 2 + mt * (16 * AROW * 2), al4);
#pragma unroll
        for (int nt = 0; nt < 4; nt++)
            mma16816(acc[mt][nt], al4, bh[nt >> 1][(nt & 1) * 2],
                     bh[nt >> 1][(nt & 1) * 2 + 1]);
    }
}

__device__ __forceinline__ void gloadA(const float* __restrict__ a1p,
                                       const float* __restrict__ a2p,
                                       int k0, float4& x, float4& y) {
    x = *(const float4*)(a1p + k0);
    y = *(const float4*)(a1p + k0 + 4);
    float4 u = *(const float4*)(a2p + k0);
    float4 v = *(const float4*)(a2p + k0 + 4);
    const float w = 1.f - R_MIX;
    x.x = fmaf(x.x, R_MIX, u.x * w); x.y = fmaf(x.y, R_MIX, u.y * w);
    x.z = fmaf(x.z, R_MIX, u.z * w); x.w = fmaf(x.w, R_MIX, u.w * w);
    y.x = fmaf(y.x, R_MIX, v.x * w); y.y = fmaf(y.y, R_MIX, v.y * w);
    y.z = fmaf(y.z, R_MIX, v.z * w); y.w = fmaf(y.w, R_MIX, v.w * w);
}

__device__ __forceinline__ void cvt_store8(uint16_t* hi_p, uint16_t* lo_p,
                                           const float4& x, const float4& y) {
    uint4 hv, lv;
    hv.x = pk2(x.x, x.y); hv.y = pk2(x.z, x.w);
    hv.z = pk2(y.x, y.y); hv.w = pk2(y.z, y.w);
    lv.x = pk2(bres(x.x), bres(x.y)); lv.y = pk2(bres(x.z), bres(x.w));
    lv.z = pk2(bres(y.x), bres(y.y)); lv.w = pk2(bres(y.z), bres(y.w));
    *reinterpret_cast<uint4*>(hi_p) = hv;
    *reinterpret_cast<uint4*>(lo_p) = lv;
}

// ---------------- layer-1 GEMM: fp32 A (mix) -> ssp -> bf16 hi/lo out ----------------
__global__ __launch_bounds__(256, 2)
void k_gemm1(const float* __restrict__ A1s, const float* __restrict__ A2s,
             const float* __restrict__ A1v, const float* __restrict__ A2v,
             const uint16_t* __restrict__ Bhs, const uint16_t* __restrict__ Bls,
             const uint16_t* __restrict__ Bhv, const uint16_t* __restrict__ Blv,
             const float* __restrict__ biass,
             uint16_t* __restrict__ Csh, uint16_t* __restrict__ Csl,
             uint16_t* __restrict__ Cvh, uint16_t* __restrict__ Cvl)
{
    __shared__ __align__(16) uint16_t sA[2][2][A_HL];
    __shared__ __align__(16) uint16_t sB[2][2][B_HL];

    const int tid = threadIdx.x, lane = tid & 31, wid = tid >> 5;
    const int warp_m = wid >> 2, warp_n = wid & 3;
    const bool isS = (blockIdx.y < NSCALAR_BLOCKS);
    const size_t rowBase = (size_t)(isS ? blockIdx.y : blockIdx.y - NSCALAR_BLOCKS) * 128;
    const int colBase = blockIdx.x * 128;
    const float* A1 = isS ? A1s : A1v;
    const float* A2 = isS ? A2s : A2v;
    const uint16_t* Bh = isS ? Bhs : Bhv;
    const uint16_t* Bl = isS ? Bls : Blv;
    const float* bias = isS ? biass : nullptr;
    uint16_t* Ch = isS ? Csh : Cvh;
    uint16_t* Cl = isS ? Csl : Cvl;

    const int am = tid >> 1, ak = (tid & 1) * 8;
    const int bk = tid >> 4, bn = (tid & 15) * 8;

    const float* a1p = A1 + (rowBase + am) * H + ak;
    const float* a2p = A2 + (rowBase + am) * H + ak;
    const uint16_t* bhp = Bh + (size_t)bk * H + colBase + bn;
    const uint16_t* blp = Bl + (size_t)bk * H + colBase + bn;

    uint32_t sB0 = (uint32_t)__cvta_generic_to_shared(&sB[0][0][0]);
    uint32_t bDst = sB0 + (uint32_t)((bk * BROW + bn) * 2);

    const int a_row0 = warp_m * 64 + (lane & 7) + ((lane >> 3) & 1) * 8;
    const int a_kgrp = lane >> 4;
    uint32_t aBase = (uint32_t)__cvta_generic_to_shared(&sA[0][0][0])
                   + (uint32_t)((a_row0 * AROW + a_kgrp * 8) * 2);
    const int b_krow = (lane & 7) + ((lane >> 3) & 1) * 8;
    const int b_ngrp = lane >> 4;
    uint32_t bBase = sB0 + (uint32_t)((b_krow * BROW + warp_n * 32 + b_ngrp * 8) * 2);

    float acc[4][4][4];
#pragma unroll
    for (int i = 0; i < 4; i++)
#pragma unroll
        for (int j = 0; j < 4; j++)
#pragma unroll
            for (int q = 0; q < 4; q++) acc[i][j][q] = 0.f;

    // prologue: B chunk 0 via cp.async (hi -> plane 0, lo -> plane 1), A chunk 0 via RF
    cpa16(bDst, bhp);
    cpa16(bDst + B_HL * 2, blp);          // FIX: plane 1 (buffer-0 lo), was plane 2
    cpa_commit();
    {
        float4 ax, ay;
        gloadA(a1p, a2p, 0, ax, ay);
        cvt_store8(&sA[0][0][am * AROW + ak], &sA[0][1][am * AROW + ak], ax, ay);
    }
    cpa_wait0();
    __syncthreads();

    const int NT = H / 16;
    float4 ax, ay;
    for (int t = 0; t < NT; t++) {
        int buf = t & 1, nb = (t + 1) & 1;
        if (t + 1 < NT) {
            int k0 = (t + 1) * 16;
            cpa16(bDst + (uint32_t)(nb * 2 * B_HL * 2), bhp + (size_t)k0 * H);
            cpa16(bDst + (uint32_t)((nb * 2 + 1) * B_HL * 2), blp + (size_t)k0 * H);
            cpa_commit();
            gloadA(a1p, a2p, k0, ax, ay);
        }
        mma_chunk(aBase + (uint32_t)(buf * 2 * A_HL * 2),
                  bBase + (uint32_t)(buf * 2 * B_HL * 2), acc);
        if (t + 1 < NT) {
            cvt_store8(&sA[nb][0][am * AROW + ak], &sA[nb][1][am * AROW + ak], ax, ay);
            cpa_wait0();
            __syncthreads();
        }
    }

    // epilogue: bias + ssp, split to bf16 hi/lo planes
#pragma unroll
    for (int mt = 0; mt < 4; mt++) {
        size_t r0 = rowBase + warp_m * 64 + mt * 16 + (lane >> 2);
#pragma unroll
        for (int nt = 0; nt < 4; nt++) {
            int col = colBase + warp_n * 32 + nt * 8 + (lane & 3) * 2;
            float v0 = acc[mt][nt][0], v1 = acc[mt][nt][1];
            float v2 = acc[mt][nt][2], v3 = acc[mt][nt][3];
            if (bias) {
                float2 bb = *(const float2*)&bias[col];
                v0 += bb.x; v1 += bb.y; v2 += bb.x; v3 += bb.y;
            }
            v0 = sspf(v0); v1 = sspf(v1); v2 = sspf(v2); v3 = sspf(v3);
            *(uint32_t*)&Ch[r0 * H + col]       = pk2(v0, v1);
            *(uint32_t*)&Cl[r0 * H + col]       = pk2(bres(v0), bres(v1));
            *(uint32_t*)&Ch[(r0 + 8) * H + col] = pk2(v2, v3);
            *(uint32_t*)&Cl[(r0 + 8) * H + col] = pk2(bres(v2), bres(v3));
        }
    }
}

// ---------------- layer-2 GEMM: bf16 hi/lo A planes -> fp32 out ----------------
__global__ __launch_bounds__(256, 2)
void k_gemm2(const uint16_t* __restrict__ Ahs, const uint16_t* __restrict__ Als,
             const uint16_t* __restrict__ Ahv, const uint16_t* __restrict__ Alv,
             const uint16_t* __restrict__ Bhs, const uint16_t* __restrict__ Bls,
             const uint16_t* __restrict__ Bhv, const uint16_t* __restrict__ Blv,
             const float* __restrict__ biass,
             float* __restrict__ Cs, float* __restrict__ Cv)
{
    __shared__ __align__(16) uint16_t sA[2][2][A_HL];
    __shared__ __align__(16) uint16_t sB[2][2][B_HL];

    const int tid = threadIdx.x, lane = tid & 31, wid = tid >> 5;
    const int warp_m = wid >> 2, warp_n = wid & 3;
    const bool isS = (blockIdx.y < NSCALAR_BLOCKS);
    const size_t rowBase = (size_t)(isS ? blockIdx.y : blockIdx.y - NSCALAR_BLOCKS) * 128;
    const int colBase = blockIdx.x * 128;
    const uint16_t* Ah = isS ? Ahs : Ahv;
    const uint16_t* Al = isS ? Als : Alv;
    const uint16_t* Bh = isS ? Bhs : Bhv;
    const uint16_t* Bl = isS ? Bls : Blv;
    const float* bias = isS ? biass : nullptr;
    float* Cc = isS ? Cs : Cv;

    const int am = tid >> 1, ak = (tid & 1) * 8;
    const int bk = tid >> 4, bn = (tid & 15) * 8;

    const uint16_t* ahp = Ah + (rowBase + am) * H + ak;
    const uint16_t* alp = Al + (rowBase + am) * H + ak;
    const uint16_t* bhp = Bh + (size_t)bk * H + colBase + bn;
    const uint16_t* blp = Bl + (size_t)bk * H + colBase + bn;

    uint32_t sA0 = (uint32_t)__cvta_generic_to_shared(&sA[0][0][0]);
    uint32_t sB0 = (uint32_t)__cvta_generic_to_shared(&sB[0][0][0]);
    uint32_t aDst = sA0 + (uint32_t)((am * AROW + ak) * 2);
    uint32_t bDst = sB0 + (uint32_t)((bk * BROW + bn) * 2);

    const int a_row0 = warp_m * 64 + (lane & 7) + ((lane >> 3) & 1) * 8;
    const int a_kgrp = lane >> 4;
    uint32_t aBase = sA0 + (uint32_t)((a_row0 * AROW + a_kgrp * 8) * 2);
    const int b_krow = (lane & 7) + ((lane >> 3) & 1) * 8;
    const int b_ngrp = lane >> 4;
    uint32_t bBase = sB0 + (uint32_t)((b_krow * BROW + warp_n * 32 + b_ngrp * 8) * 2);

    float acc[4][4][4];
#pragma unroll
    for (int i = 0; i < 4; i++)
#pragma unroll
        for (int j = 0; j < 4; j++)
#pragma unroll
            for (int q = 0; q < 4; q++) acc[i][j][q] = 0.f;

    // prologue: chunk 0 via cp.async (hi -> plane 0, lo -> plane 1 of each array)
    cpa16(aDst, ahp);
    cpa16(aDst + A_HL * 2, alp);          // FIX: plane 1 (buffer-0 lo), was plane 2
    cpa16(bDst, bhp);
    cpa16(bDst + B_HL * 2, blp);          // FIX: plane 1 (buffer-0 lo), was plane 2
    cpa_commit();
    cpa_wait0();
    __syncthreads();

    const int NT = H / 16;
    for (int t = 0; t < NT; t++) {
        int buf = t & 1, nb = (t + 1) & 1;
        if (t + 1 < NT) {
            int k0 = (t + 1) * 16;
            cpa16(aDst + (uint32_t)(nb * 2 * A_HL * 2), ahp + (size_t)k0);
            cpa16(aDst + (uint32_t)((nb * 2 + 1) * A_HL * 2), alp + (size_t)k0);
            cpa16(bDst + (uint32_t)(nb * 2 * B_HL * 2), bhp + (size_t)k0 * H);
            cpa16(bDst + (uint32_t)((nb * 2 + 1) * B_HL * 2), blp + (size_t)k0 * H);
            cpa_commit();
        }
        mma_chunk(aBase + (uint32_t)(buf * 2 * A_HL * 2),
                  bBase + (uint32_t)(buf * 2 * B_HL * 2), acc);
        if (t + 1 < NT) {
            cpa_wait0();
            __syncthreads();
        }
    }

#pragma unroll
    for (int mt = 0; mt < 4; mt++) {
        size_t r0 = rowBase + warp_m * 64 + mt * 16 + (lane >> 2);
#pragma unroll
        for (int nt = 0; nt < 4; nt++) {
            int col = colBase + warp_n * 32 + nt * 8 + (lane & 3) * 2;
            float v0 = acc[mt][nt][0], v1 = acc[mt][nt][1];
            float v2 = acc[mt][nt][2], v3 = acc[mt][nt][3];
            if (bias) {
                float2 bb = *(const float2*)&bias[col];
                v0 += bb.x; v1 += bb.y; v2 += bb.x; v3 += bb.y;
            }
            float2 o0; o0.x = v0; o0.y = v1;
            float2 o1; o1.x = v2; o1.y = v3;
            *(float2*)&Cc[r0 * H + col] = o0;
            *(float2*)&Cc[(r0 + 8) * H + col] = o1;
        }
    }
}

// ---------------- per-node inverse L2 norms (warp per node) ----------------
__global__ void k_norms() {
    int gw = (blockIdx.x * blockDim.x + threadIdx.x) >> 5;
    int lane = threadIdx.x & 31;
    if (gw >= N_NODES) return;
    const float* p = g_si + (size_t)gw * H;
    float s = 0.f;
    for (int j = lane; j < H; j += 32) { float v = p[j]; s = fmaf(v, v, s); }
    for (int o = 16; o; o >>= 1) s += __shfl_xor_sync(0xffffffffu, s, o);
    if (lane == 0) g_inv_s[gw] = 1.f / fmaxf(sqrtf(s), 1e-12f);
#pragma unroll
    for (int d = 0; d < 3; d++) {
        const float* q = g_vi + ((size_t)gw * 3 + d) * H;
        float t = 0.f;
        for (int j = lane; j < H; j += 32) { float v = q[j]; t = fmaf(v, v, t); }
        for (int o = 16; o; o >>= 1) t += __shfl_xor_sync(0xffffffffu, t, o);
        if (lane == 0) g_inv_v[gw * 3 + d] = 1.f / fmaxf(sqrtf(t), 1e-12f);
    }
}

// ---------------- per-fragment mean + variance ----------------
__global__ void k_meanvar() {
    __shared__ float mean[1024];
    int f = blockIdx.x, t = threadIdx.x;
    int cnt = g_counts[f], off = g_offsets[f];
    float as = 0.f, a0 = 0.f, a1 = 0.f, a2 = 0.f;
    for (int m = 0; m < cnt; m++) {
        int nd = g_nodes[off + m];
        as += g_si[(size_t)nd * H + t];
        const float* v = g_vi + (size_t)nd * 3 * H;
        a0 += v[t]; a1 += v[H + t]; a2 += v[2 * H + t];
    }
    float invn = 1.f / (float)(cnt > 1 ? cnt : 1);
    mean[t] = as * invn; mean[256 + t] = a0 * invn;
    mean[512 + t] = a1 * invn; mean[768 + t] = a2 * invn;
    __syncthreads();
    float sv = 0.f, vv = 0.f;
    for (int m = 0; m < cnt; m++) {
        int nd = g_nodes[off + m];
        float d0 = g_si[(size_t)nd * H + t] - mean[t];
        sv = fmaf(d0, d0, sv);
        const float* v = g_vi + (size_t)nd * 3 * H;
        float d1 = v[t] - mean[256 + t];
        float d2 = v[H + t] - mean[512 + t];
        float d3 = v[2 * H + t] - mean[768 + t];
        vv = fmaf(d1, d1, vv); vv = fmaf(d2, d2, vv); vv = fmaf(d3, d3, vv);
    }
    __shared__ float red[64];
    for (int o = 16; o; o >>= 1) {
        sv += __shfl_xor_sync(0xffffffffu, sv, o);
        vv += __shfl_xor_sync(0xffffffffu, vv, o);
    }
    int w = t >> 5, lane = t & 31;
    if (lane == 0) { red[w] = sv; red[32 + w] = vv; }
    __syncthreads();
    if (t == 0) {
        float a = 0.f, b = 0.f;
        for (int i = 0; i < 8; i++) { a += red[i]; b += red[32 + i]; }
        g_svar[f] = a; g_vvar[f] = b;
    }
}

// ---------------- intra-fragment pair cosine error ----------------
__global__ void k_pairs() {
    extern __shared__ float rows[];
    int f = blockIdx.x, t = threadIdx.x;
    int cnt = g_counts[f], off = g_offsets[f];
    int w = t >> 5, lane = t & 31;
    float sacc = 0.f, dacc = 0.f;

    if (cnt >= 2 && cnt <= MAXM) {
        for (int feat = 0; feat < 4; feat++) {
            for (int r = 0; r < cnt; r++) {
                int nd = g_nodes[off + r];
                const float* src; float inv;
                if (feat == 0) { src = g_si + (size_t)nd * H; inv = g_inv_s[nd]; }
                else { src = g_vi + ((size_t)nd * 3 + (feat - 1)) * H; inv = g_inv_v[nd * 3 + feat - 1]; }
                rows[r * ROWSTRIDE + t] = src[t] * inv;
            }
            __syncthreads();
            float acc = 0.f;
            for (int a = w; a < cnt - 1; a += 8) {
                const float4* ra = (const float4*)(rows + a * ROWSTRIDE);
                for (int b = a + 1 + lane; b < cnt; b += 32) {
                    const float4* rb = (const float4*)(rows + b * ROWSTRIDE);
                    float dot = 0.f;
#pragma unroll 8
                    for (int k = 0; k < H / 4; k++) {
                        float4 u = ra[k], v = rb[k];
                        dot = fmaf(u.x, v.x, dot);
                        dot = fmaf(u.y, v.y, dot);
                        dot = fmaf(u.z, v.z, dot);
                        dot = fmaf(u.w, v.w, dot);
                    }
                    float e = dot - C_SIM;
                    acc = fmaf(e, e, acc);
                }
            }
            if (feat == 0) sacc = acc; else dacc += acc;
            __syncthreads();
        }
    } else if (cnt > MAXM) {
        for (int feat = 0; feat < 4; feat++) {
            float acc = 0.f;
            for (int a = w; a < cnt - 1; a += 8) {
                int na = g_nodes[off + a];
                const float* ra; float inva;
                if (feat == 0) { ra = g_si + (size_t)na * H; inva = g_inv_s[na]; }
                else { ra = g_vi + ((size_t)na * 3 + (feat - 1)) * H; inva = g_inv_v[na * 3 + feat - 1]; }
                for (int b = a + 1 + lane; b < cnt; b += 32) {
                    int nb = g_nodes[off + b];
                    const float* rb; float invb;
                    if (feat == 0) { rb = g_si + (size_t)nb * H; invb = g_inv_s[nb]; }
                    else { rb = g_vi + ((size_t)nb * 3 + (feat - 1)) * H; invb = g_inv_v[nb * 3 + feat - 1]; }
                    float dot = 0.f;
                    for (int k = 0; k < H; k++) dot = fmaf(ra[k], rb[k], dot);
                    float e = dot * inva * invb - C_SIM;
                    acc = fmaf(e, e, acc);
                }
            }
            if (feat == 0) sacc = acc; else dacc += acc;
        }
    }

    __shared__ float red[64];
    for (int o = 16; o; o >>= 1) {
        sacc += __shfl_xor_sync(0xffffffffu, sacc, o);
        dacc += __shfl_xor_sync(0xffffffffu, dacc, o);
    }
    if (lane == 0) { red[w] = sacc; red[32 + w] = dacc; }
    __syncthreads();
    if (t == 0) {
        float a = 0.f, b = 0.f;
        for (int i = 0; i < 8; i++) { a += red[i]; b += red[32 + i]; }
        g_ssim[f] = a; g_dir[f] = b;
    }
}

// ---------------- final scalar ----------------
__global__ void k_final(float* __restrict__ out) {
    int f = threadIdx.x;
    float n  = (float)g_counts[f];
    float pc = n * (n - 1.f) * 0.5f;
    float ns  = fmaxf(n, 1.f);
    float pcs = fmaxf(pc, 1.f);
    float sl = g_svar[f] / ns + g_ssim[f] / pcs;
    float vl = g_vvar[f] / ns + g_dir[f] / (3.f * pcs);
    float fl = 0.5f * sl + 0.5f * vl;
    float val  = (pc > 0.f) ? fl : 0.f;
    float cntv = (pc > 0.f) ? 1.f : 0.f;
    __shared__ float red[64];
    for (int o = 16; o; o >>= 1) {
        val  += __shfl_xor_sync(0xffffffffu, val, o);
        cntv += __shfl_xor_sync(0xffffffffu, cntv, o);
    }
    int w = f >> 5, lane = f & 31;
    if (lane == 0) { red[w] = val; red[32 + w] = cntv; }
    __syncthreads();
    if (f == 0) {
        float tot = 0.f, tc = 0.f;
        for (int i = 0; i < 8; i++) { tot += red[i]; tc += red[32 + i]; }
        out[0] = (tc > 0.f) ? tot / fmaxf(tc, 1.f) : 0.f;
    }
}

// ---------------- launch ----------------
extern "C" void kernel_launch(void* const* d_in, const int* in_sizes, int n_in,
                              void* d_out, int out_size)
{
    const float* ss = (const float*)d_in[0];
    const float* sl = (const float*)d_in[1];
    const float* vs = (const float*)d_in[2];
    const float* vl = (const float*)d_in[3];
    const float* W1 = (const float*)d_in[4];
    const float* b1 = (const float*)d_in[5];
    const float* W2 = (const float*)d_in[6];
    const float* b2 = (const float*)d_in[7];
    const float* V1 = (const float*)d_in[8];
    const float* V2 = (const float*)d_in[9];
    const int*   frag = (const int*)d_in[10];
    float* out = (float*)d_out;

    void *psi, *pvi, *pch, *pwh, *pwl, *ptsh, *ptsl, *ptvh, *ptvl;
    cudaGetSymbolAddress(&psi, g_si);
    cudaGetSymbolAddress(&pvi, g_vi);
    cudaGetSymbolAddress(&pch, g_chunk);
    cudaGetSymbolAddress(&pwh, g_wh);
    cudaGetSymbolAddress(&pwl, g_wl);
    cudaGetSymbolAddress(&ptsh, g_tsh);
    cudaGetSymbolAddress(&ptsl, g_tsl);
    cudaGetSymbolAddress(&ptvh, g_tvh);
    cudaGetSymbolAddress(&ptvl, g_tvl);
    const uint16_t* wh = (const uint16_t*)pwh;
    const uint16_t* wl = (const uint16_t*)pwl;
    uint16_t* tsh = (uint16_t*)ptsh;
    uint16_t* tsl = (uint16_t*)ptsl;
    uint16_t* tvh = (uint16_t*)ptvh;
    uint16_t* tvl = (uint16_t*)ptvl;

    cudaMemsetAsync(pch, 0, 256 * 256 * sizeof(int));
    k_hist<<<32, 256>>>(frag);
    k_scan2<<<1, 256>>>();
    k_scatter<<<32, 256>>>(frag);

    k_prepw<<<dim3(64, 4), 256>>>(W1, W2, V1, V2);

    dim3 g(2, NSCALAR_BLOCKS + 192);
    // layer 1: bf16 planes out
    k_gemm1<<<g, 256>>>(ss, sl, vs, vl,
                        wh + 0 * 65536, wl + 0 * 65536,   // W1
                        wh + 2 * 65536, wl + 2 * 65536,   // V1
                        b1, tsh, tsl, tvh, tvl);
    // layer 2: fp32 out
    k_gemm2<<<g, 256>>>(tsh, tsl, tvh, tvl,
                        wh + 1 * 65536, wl + 1 * 65536,   // W2
                        wh + 3 * 65536, wl + 3 * 65536,   // V2
                        b2, (float*)psi, (float*)pvi);

    k_norms<<<N_NODES * 32 / 256, 256>>>();
    k_meanvar<<<NF, 256>>>();

    cudaFuncSetAttribute(k_pairs, cudaFuncAttributeMaxDynamicSharedMemorySize,
                         MAXM * ROWSTRIDE * 4);
    k_pairs<<<NF, 256, MAXM * ROWSTRIDE * 4>>>();

    k_final<<<1, 256>>>(out);
}

// round 9
// speedup vs baseline: 1.0235x; 1.0235x over previous
#include <cuda_runtime.h>
#include <cuda_bf16.h>
#include <math.h>
#include <stdint.h>

#define N_NODES 8192
#define H 256
#define NF 256
#define R_MIX 0.3f
#define C_SIM 0.8f
#define LOG2F_ 0.69314718055994530942f
#define MAXM 128
#define ROWSTRIDE 260

// ---------------- scratch (static device globals) ----------------
__device__ uint16_t g_tsh[ 8192 * 256], g_tsl[ 8192 * 256];   // layer-1 scalar out (bf16 hi/lo)
__device__ uint16_t g_tvh[24576 * 256], g_tvl[24576 * 256];   // layer-1 vector out
__device__ float g_si[ 8192 * 256];
__device__ float g_vi[24576 * 256];
__device__ uint16_t g_wh[4][65536];
__device__ uint16_t g_wl[4][65536];
__device__ int   g_chunk[256 * 256];
__device__ int   g_counts [NF];
__device__ int   g_offsets[NF + 1];
__device__ int   g_nodes  [N_NODES];
__device__ float g_svar[NF], g_vvar[NF], g_ssim[NF], g_dir[NF];

__device__ __forceinline__ float sspf(float x) {
    float ax = fabsf(x);
    return fmaxf(x, 0.f) + log1pf(__expf(-ax)) - LOG2F_;
}
__device__ __forceinline__ uint32_t pk2(float a, float b) {
    __nv_bfloat162 t = __floats2bfloat162_rn(a, b);
    return *reinterpret_cast<uint32_t*>(&t);
}
__device__ __forceinline__ float bres(float x) {
    __nv_bfloat16 h = __float2bfloat16(x);
    return x - __bfloat162float(h);
}

// ---------------- mma/ldmatrix/cp.async wrappers (sm_103-safe) ----------------
__device__ __forceinline__ void ldsm4(uint32_t addr, uint32_t* r) {
    asm volatile("ldmatrix.sync.aligned.m8n8.x4.shared.b16 {%0,%1,%2,%3}, [%4];"
                 : "=r"(r[0]), "=r"(r[1]), "=r"(r[2]), "=r"(r[3]) : "r"(addr));
}
__device__ __forceinline__ void ldsm4t(uint32_t addr, uint32_t* r) {
    asm volatile("ldmatrix.sync.aligned.m8n8.x4.trans.shared.b16 {%0,%1,%2,%3}, [%4];"
                 : "=r"(r[0]), "=r"(r[1]), "=r"(r[2]), "=r"(r[3]) : "r"(addr));
}
__device__ __forceinline__ void mma16816(float* c, const uint32_t* a, uint32_t b0, uint32_t b1) {
    asm volatile(
        "mma.sync.aligned.m16n8k16.row.col.f32.bf16.bf16.f32 "
        "{%0,%1,%2,%3},{%4,%5,%6,%7},{%8,%9},{%0,%1,%2,%3};"
        : "+f"(c[0]), "+f"(c[1]), "+f"(c[2]), "+f"(c[3])
        : "r"(a[0]), "r"(a[1]), "r"(a[2]), "r"(a[3]), "r"(b0), "r"(b1));
}
__device__ __forceinline__ void cpa16(uint32_t dst, const void* src) {
    asm volatile("cp.async.cg.shared.global [%0], [%1], 16;" :: "r"(dst), "l"(src) : "memory");
}
__device__ __forceinline__ void cpa_commit() {
    asm volatile("cp.async.commit_group;" ::: "memory");
}
__device__ __forceinline__ void cpa_wait0() {
    asm volatile("cp.async.wait_group 0;" ::: "memory");
}
__device__ __forceinline__ void cpa_wait1() {
    asm volatile("cp.async.wait_group 1;" ::: "memory");
}

// ---------------- fragment bookkeeping (deterministic counting sort) -----------
__global__ void k_hist(const int* __restrict__ frag) {
    int chunk = blockIdx.x * 8 + (threadIdx.x >> 5);
    int lane = threadIdx.x & 31;
    // self-zero this chunk's histogram row (replaces the memset launch)
    for (int j = lane; j < 256; j += 32) g_chunk[chunk * 256 + j] = 0;
    __syncwarp();
    __threadfence_block();
    int i = chunk * 32 + lane;
    int f = frag[i];
    unsigned mask = __match_any_sync(0xffffffffu, f);
    int lr = __popc(mask & ((1u << lane) - 1u));
    if (lr == 0 && f >= 0 && f < NF) g_chunk[chunk * 256 + f] = __popc(mask);
}

__global__ void k_scan2() {
    int t = threadIdx.x;
    int running = 0;
#pragma unroll 4
    for (int c = 0; c < 256; c++) {
        int idx = c * 256 + t;
        int v = g_chunk[idx];
        g_chunk[idx] = running;
        running += v;
    }
    g_counts[t] = running;
    __shared__ int s[256];
    s[t] = running;
    __syncthreads();
    for (int d = 1; d < 256; d <<= 1) {
        int v = (t >= d) ? s[t - d] : 0;
        __syncthreads();
        s[t] += v;
        __syncthreads();
    }
    g_offsets[t] = s[t] - running;
    if (t == 255) g_offsets[256] = s[255];
}

__global__ void k_scatter(const int* __restrict__ frag) {
    int chunk = blockIdx.x * 8 + (threadIdx.x >> 5);
    int lane = threadIdx.x & 31;
    int i = chunk * 32 + lane;
    int f = frag[i];
    unsigned mask = __match_any_sync(0xffffffffu, f);
    int lr = __popc(mask & ((1u << lane) - 1u));
    if (f >= 0 && f < NF) {
        int pos = g_offsets[f] + g_chunk[chunk * 256 + f] + lr;
        if (pos >= 0 && pos < N_NODES) g_nodes[pos] = i;
    }
}

// ---------------- weight pre-split to bf16 hi/lo (once) ----------------
__global__ void k_prepw(const float* __restrict__ W1, const float* __restrict__ W2,
                        const float* __restrict__ V1, const float* __restrict__ V2)
{
    int m = blockIdx.y;
    const float* src = (m == 0) ? W1 : (m == 1) ? W2 : (m == 2) ? V1 : V2;
    int i0 = (blockIdx.x * 256 + threadIdx.x) * 4;
    float4 v = *(const float4*)(src + i0);
    uint16_t* oh = g_wh[m];
    uint16_t* ol = g_wl[m];
    *(uint32_t*)&oh[i0]     = pk2(v.x, v.y);
    *(uint32_t*)&oh[i0 + 2] = pk2(v.z, v.w);
    *(uint32_t*)&ol[i0]     = pk2(bres(v.x), bres(v.y));
    *(uint32_t*)&ol[i0 + 2] = pk2(bres(v.z), bres(v.w));
}

// ------------- shared GEMM pieces -------------
#define AROW 24
#define BROW 136
#define A_HL (128 * AROW)          // 3072 halfwords per plane
#define B_HL (16 * BROW)           // 2176
#define A_PLANE_B (A_HL * 2)       // 6144 bytes
#define B_PLANE_B (B_HL * 2)       // 4352
#define ABUF_B (2 * A_PLANE_B)     // 12288 bytes per A buffer (hi+lo)
#define BBUF_B (2 * B_PLANE_B)     // 8704
#define G1_SMEM (2 * ABUF_B + 3 * BBUF_B)   // 50688
#define G2_SMEM (3 * ABUF_B + 3 * BBUF_B)   // 62976
#define NSCALAR_BLOCKS 64

// per-warp 3-term mma over one 16-k chunk. aOff/bOff = byte addr of hi plane.
__device__ __forceinline__ void mma_chunk(uint32_t aOff, uint32_t bOff, float acc[4][4][4]) {
    uint32_t ah[4][4], bh[2][4], tmp[2][4], al4[4];
#pragma unroll
    for (int mt = 0; mt < 4; mt++) ldsm4(aOff + mt * (16 * AROW * 2), ah[mt]);
#pragma unroll
    for (int st = 0; st < 2; st++) ldsm4t(bOff + st * 32, bh[st]);
#pragma unroll
    for (int mt = 0; mt < 4; mt++)
#pragma unroll
        for (int nt = 0; nt < 4; nt++)
            mma16816(acc[mt][nt], ah[mt], bh[nt >> 1][(nt & 1) * 2],
                     bh[nt >> 1][(nt & 1) * 2 + 1]);
#pragma unroll
    for (int st = 0; st < 2; st++) ldsm4t(bOff + B_PLANE_B + st * 32, tmp[st]);
#pragma unroll
    for (int mt = 0; mt < 4; mt++)
#pragma unroll
        for (int nt = 0; nt < 4; nt++)
            mma16816(acc[mt][nt], ah[mt], tmp[nt >> 1][(nt & 1) * 2],
                     tmp[nt >> 1][(nt & 1) * 2 + 1]);
#pragma unroll
    for (int mt = 0; mt < 4; mt++) {
        ldsm4(aOff + A_PLANE_B + mt * (16 * AROW * 2), al4);
#pragma unroll
        for (int nt = 0; nt < 4; nt++)
            mma16816(acc[mt][nt], al4, bh[nt >> 1][(nt & 1) * 2],
                     bh[nt >> 1][(nt & 1) * 2 + 1]);
    }
}

__device__ __forceinline__ void gloadA(const float* __restrict__ a1p,
                                       const float* __restrict__ a2p,
                                       int k0, float4& x, float4& y) {
    x = *(const float4*)(a1p + k0);
    y = *(const float4*)(a1p + k0 + 4);
    float4 u = *(const float4*)(a2p + k0);
    float4 v = *(const float4*)(a2p + k0 + 4);
    const float w = 1.f - R_MIX;
    x.x = fmaf(x.x, R_MIX, u.x * w); x.y = fmaf(x.y, R_MIX, u.y * w);
    x.z = fmaf(x.z, R_MIX, u.z * w); x.w = fmaf(x.w, R_MIX, u.w * w);
    y.x = fmaf(y.x, R_MIX, v.x * w); y.y = fmaf(y.y, R_MIX, v.y * w);
    y.z = fmaf(y.z, R_MIX, v.z * w); y.w = fmaf(y.w, R_MIX, v.w * w);
}

__device__ __forceinline__ void cvt_store8(uint16_t* hi_p, uint16_t* lo_p,
                                           const float4& x, const float4& y) {
    uint4 hv, lv;
    hv.x = pk2(x.x, x.y); hv.y = pk2(x.z, x.w);
    hv.z = pk2(y.x, y.y); hv.w = pk2(y.z, y.w);
    lv.x = pk2(bres(x.x), bres(x.y)); lv.y = pk2(bres(x.z), bres(x.w));
    lv.z = pk2(bres(y.x), bres(y.y)); lv.w = pk2(bres(y.z), bres(y.w));
    *reinterpret_cast<uint4*>(hi_p) = hv;
    *reinterpret_cast<uint4*>(lo_p) = lv;
}

// ---------------- layer-1 GEMM: fp32 A (mix) -> ssp -> bf16 hi/lo out ----------------
// A double-buffered via RF convert; B triple-buffered via cp.async (2-chunk lookahead).
__global__ __launch_bounds__(256, 2)
void k_gemm1(const float* __restrict__ A1s, const float* __restrict__ A2s,
             const float* __restrict__ A1v, const float* __restrict__ A2v,
             const uint16_t* __restrict__ Bhs, const uint16_t* __restrict__ Bls,
             const uint16_t* __restrict__ Bhv, const uint16_t* __restrict__ Blv,
             const float* __restrict__ biass,
             uint16_t* __restrict__ Csh, uint16_t* __restrict__ Csl,
             uint16_t* __restrict__ Cvh, uint16_t* __restrict__ Cvl)
{
    extern __shared__ __align__(16) uint16_t dsm[];
    uint16_t* sAp = dsm;                      // 2 bufs x 2 planes x A_HL
    const int tid = threadIdx.x, lane = tid & 31, wid = tid >> 5;
    const int warp_m = wid >> 2, warp_n = wid & 3;
    const bool isS = (blockIdx.y < NSCALAR_BLOCKS);
    const size_t rowBase = (size_t)(isS ? blockIdx.y : blockIdx.y - NSCALAR_BLOCKS) * 128;
    const int colBase = blockIdx.x * 128;
    const float* A1 = isS ? A1s : A1v;
    const float* A2 = isS ? A2s : A2v;
    const uint16_t* Bh = isS ? Bhs : Bhv;
    const uint16_t* Bl = isS ? Bls : Blv;
    const float* bias = isS ? biass : nullptr;
    uint16_t* Ch = isS ? Csh : Cvh;
    uint16_t* Cl = isS ? Csl : Cvl;

    const int am = tid >> 1, ak = (tid & 1) * 8;
    const int bk = tid >> 4, bn = (tid & 15) * 8;

    const float* a1p = A1 + (rowBase + am) * H + ak;
    const float* a2p = A2 + (rowBase + am) * H + ak;
    const uint16_t* bhp = Bh + (size_t)bk * H + colBase + bn;
    const uint16_t* blp = Bl + (size_t)bk * H + colBase + bn;

    uint32_t sA0 = (uint32_t)__cvta_generic_to_shared(dsm);
    uint32_t sB0 = sA0 + 2 * ABUF_B;
    uint32_t bDst = sB0 + (uint32_t)((bk * BROW + bn) * 2);

    const int a_row0 = warp_m * 64 + (lane & 7) + ((lane >> 3) & 1) * 8;
    const int a_kgrp = lane >> 4;
    uint32_t aBase = sA0 + (uint32_t)((a_row0 * AROW + a_kgrp * 8) * 2);
    const int b_krow = (lane & 7) + ((lane >> 3) & 1) * 8;
    const int b_ngrp = lane >> 4;
    uint32_t bBase = sB0 + (uint32_t)((b_krow * BROW + warp_n * 32 + b_ngrp * 8) * 2);

    float acc[4][4][4];
#pragma unroll
    for (int i = 0; i < 4; i++)
#pragma unroll
        for (int j = 0; j < 4; j++)
#pragma unroll
            for (int q = 0; q < 4; q++) acc[i][j][q] = 0.f;

    // prologue: B chunks 0,1 via cp.async; A chunk 0 via RF convert
    cpa16(bDst, bhp);
    cpa16(bDst + B_PLANE_B, blp);
    cpa_commit();
    cpa16(bDst + BBUF_B, bhp + (size_t)16 * H);
    cpa16(bDst + BBUF_B + B_PLANE_B, blp + (size_t)16 * H);
    cpa_commit();
    {
        float4 ax0, ay0;
        gloadA(a1p, a2p, 0, ax0, ay0);
        cvt_store8(sAp + (am * AROW + ak), sAp + A_HL + (am * AROW + ak), ax0, ay0);
    }
    cpa_wait1();
    __syncthreads();

    const int NT = H / 16;
    float4 ax, ay;
    for (int t = 0; t < NT; t++) {
        int abuf = t & 1, bbuf = t % 3;
        if (t + 2 < NT) {
            size_t k2 = (size_t)(t + 2) * 16;
            uint32_t bd = bDst + (uint32_t)(((t + 2) % 3) * BBUF_B);
            cpa16(bd, bhp + k2 * H);
            cpa16(bd + B_PLANE_B, blp + k2 * H);
            cpa_commit();
        }
        if (t + 1 < NT) gloadA(a1p, a2p, (t + 1) * 16, ax, ay);
        mma_chunk(aBase + (uint32_t)(abuf * ABUF_B),
                  bBase + (uint32_t)(bbuf * BBUF_B), acc);
        if (t + 1 < NT) {
            int anb = (t + 1) & 1;
            cvt_store8(sAp + anb * (2 * A_HL) + (am * AROW + ak),
                       sAp + anb * (2 * A_HL) + A_HL + (am * AROW + ak), ax, ay);
            if (t + 2 < NT) cpa_wait1(); else cpa_wait0();
            __syncthreads();
        }
    }

    // epilogue: bias + ssp, split to bf16 hi/lo planes
#pragma unroll
    for (int mt = 0; mt < 4; mt++) {
        size_t r0 = rowBase + warp_m * 64 + mt * 16 + (lane >> 2);
#pragma unroll
        for (int nt = 0; nt < 4; nt++) {
            int col = colBase + warp_n * 32 + nt * 8 + (lane & 3) * 2;
            float v0 = acc[mt][nt][0], v1 = acc[mt][nt][1];
            float v2 = acc[mt][nt][2], v3 = acc[mt][nt][3];
            if (bias) {
                float2 bb = *(const float2*)&bias[col];
                v0 += bb.x; v1 += bb.y; v2 += bb.x; v3 += bb.y;
            }
            v0 = sspf(v0); v1 = sspf(v1); v2 = sspf(v2); v3 = sspf(v3);
            *(uint32_t*)&Ch[r0 * H + col]       = pk2(v0, v1);
            *(uint32_t*)&Cl[r0 * H + col]       = pk2(bres(v0), bres(v1));
            *(uint32_t*)&Ch[(r0 + 8) * H + col] = pk2(v2, v3);
            *(uint32_t*)&Cl[(r0 + 8) * H + col] = pk2(bres(v2), bres(v3));
        }
    }
}

// ---------------- layer-2 GEMM: bf16 hi/lo A planes -> fp32 out ----------------
// A and B both triple-buffered via cp.async (2-chunk lookahead).
__global__ __launch_bounds__(256, 2)
void k_gemm2(const uint16_t* __restrict__ Ahs, const uint16_t* __restrict__ Als,
             const uint16_t* __restrict__ Ahv, const uint16_t* __restrict__ Alv,
             const uint16_t* __restrict__ Bhs, const uint16_t* __restrict__ Bls,
             const uint16_t* __restrict__ Bhv, const uint16_t* __restrict__ Blv,
             const float* __restrict__ biass,
             float* __restrict__ Cs, float* __restrict__ Cv)
{
    extern __shared__ __align__(16) uint16_t dsm[];
    const int tid = threadIdx.x, lane = tid & 31, wid = tid >> 5;
    const int warp_m = wid >> 2, warp_n = wid & 3;
    const bool isS = (blockIdx.y < NSCALAR_BLOCKS);
    const size_t rowBase = (size_t)(isS ? blockIdx.y : blockIdx.y - NSCALAR_BLOCKS) * 128;
    const int colBase = blockIdx.x * 128;
    const uint16_t* Ah = isS ? Ahs : Ahv;
    const uint16_t* Al = isS ? Als : Alv;
    const uint16_t* Bh = isS ? Bhs : Bhv;
    const uint16_t* Bl = isS ? Bls : Blv;
    const float* bias = isS ? biass : nullptr;
    float* Cc = isS ? Cs : Cv;

    const int am = tid >> 1, ak = (tid & 1) * 8;
    const int bk = tid >> 4, bn = (tid & 15) * 8;

    const uint16_t* ahp = Ah + (rowBase + am) * H + ak;
    const uint16_t* alp = Al + (rowBase + am) * H + ak;
    const uint16_t* bhp = Bh + (size_t)bk * H + colBase + bn;
    const uint16_t* blp = Bl + (size_t)bk * H + colBase + bn;

    uint32_t sA0 = (uint32_t)__cvta_generic_to_shared(dsm);
    uint32_t sB0 = sA0 + 3 * ABUF_B;
    uint32_t aDst = sA0 + (uint32_t)((am * AROW + ak) * 2);
    uint32_t bDst = sB0 + (uint32_t)((bk * BROW + bn) * 2);

    const int a_row0 = warp_m * 64 + (lane & 7) + ((lane >> 3) & 1) * 8;
    const int a_kgrp = lane >> 4;
    uint32_t aBase = sA0 + (uint32_t)((a_row0 * AROW + a_kgrp * 8) * 2);
    const int b_krow = (lane & 7) + ((lane >> 3) & 1) * 8;
    const int b_ngrp = lane >> 4;
    uint32_t bBase = sB0 + (uint32_t)((b_krow * BROW + warp_n * 32 + b_ngrp * 8) * 2);

    float acc[4][4][4];
#pragma unroll
    for (int i = 0; i < 4; i++)
#pragma unroll
        for (int j = 0; j < 4; j++)
#pragma unroll
            for (int q = 0; q < 4; q++) acc[i][j][q] = 0.f;

    // prologue: chunks 0 and 1 via cp.async
#pragma unroll
    for (int c = 0; c < 2; c++) {
        size_t k0 = (size_t)c * 16;
        uint32_t ad = aDst + (uint32_t)(c * ABUF_B);
        uint32_t bd = bDst + (uint32_t)(c * BBUF_B);
        cpa16(ad, ahp + k0);
        cpa16(ad + A_PLANE_B, alp + k0);
        cpa16(bd, bhp + k0 * H);
        cpa16(bd + B_PLANE_B, blp + k0 * H);
        cpa_commit();
    }
    cpa_wait1();
    __syncthreads();

    const int NT = H / 16;
    for (int t = 0; t < NT; t++) {
        int buf = t % 3;
        if (t + 2 < NT) {
            size_t k2 = (size_t)(t + 2) * 16;
            int nb2 = (t + 2) % 3;
            uint32_t ad = aDst + (uint32_t)(nb2 * ABUF_B);
            uint32_t bd = bDst + (uint32_t)(nb2 * BBUF_B);
            cpa16(ad, ahp + k2);
            cpa16(ad + A_PLANE_B, alp + k2);
            cpa16(bd, bhp + k2 * H);
            cpa16(bd + B_PLANE_B, blp + k2 * H);
            cpa_commit();
        }
        mma_chunk(aBase + (uint32_t)(buf * ABUF_B),
                  bBase + (uint32_t)(buf * BBUF_B), acc);
        if (t + 1 < NT) {
            if (t + 2 < NT) cpa_wait1(); else cpa_wait0();
            __syncthreads();
        }
    }

#pragma unroll
    for (int mt = 0; mt < 4; mt++) {
        size_t r0 = rowBase + warp_m * 64 + mt * 16 + (lane >> 2);
#pragma unroll
        for (int nt = 0; nt < 4; nt++) {
            int col = colBase + warp_n * 32 + nt * 8 + (lane & 3) * 2;
            float v0 = acc[mt][nt][0], v1 = acc[mt][nt][1];
            float v2 = acc[mt][nt][2], v3 = acc[mt][nt][3];
            if (bias) {
                float2 bb = *(const float2*)&bias[col];
                v0 += bb.x; v1 += bb.y; v2 += bb.x; v3 += bb.y;
            }
            float2 o0; o0.x = v0; o0.y = v1;
            float2 o1; o1.x = v2; o1.y = v3;
            *(float2*)&Cc[r0 * H + col] = o0;
            *(float2*)&Cc[(r0 + 8) * H + col] = o1;
        }
    }
}

// ---------------- fused per-fragment stats: mean/var + norms + pair cosine ---------
// Block per fragment. Rows loaded to smem ONCE per feature and reused for
// column mean/var (two-pass), row inv-norms, and pair dots (scaled by inv norms).
__global__ void k_frag() {
    extern __shared__ float rows[];   // MAXM * ROWSTRIDE floats
    __shared__ float inv[MAXM];
    __shared__ float rd[32];
    int f = blockIdx.x, t = threadIdx.x;
    int cnt = g_counts[f], off = g_offsets[f];
    int w = t >> 5, lane = t & 31;
    float sacc = 0.f, dacc = 0.f, svar = 0.f, vvar = 0.f;

    if (cnt >= 2 && cnt <= MAXM) {
        for (int feat = 0; feat < 4; feat++) {
            // raw rows -> smem
            for (int r = 0; r < cnt; r++) {
                int nd = g_nodes[off + r];
                const float* src = (feat == 0) ? g_si + (size_t)nd * H
                                               : g_vi + ((size_t)nd * 3 + (feat - 1)) * H;
                rows[r * ROWSTRIDE + t] = src[t];
            }
            __syncthreads();
            // column mean + variance (thread t owns column t; two-pass)
            {
                float s1 = 0.f;
                for (int r = 0; r < cnt; r++) s1 += rows[r * ROWSTRIDE + t];
                float mean = s1 / (float)cnt;
                float v = 0.f;
                for (int r = 0; r < cnt; r++) {
                    float d = rows[r * ROWSTRIDE + t] - mean;
                    v = fmaf(d, d, v);
                }
                if (feat == 0) svar += v; else vvar += v;
            }
            // row inverse L2 norms (warp w handles rows w, w+8, ...)
            for (int r = w; r < cnt; r += 8) {
                const float* rp = rows + r * ROWSTRIDE;
                float s = 0.f;
                for (int j = lane; j < H; j += 32) { float x = rp[j]; s = fmaf(x, x, s); }
                for (int o = 16; o; o >>= 1) s += __shfl_xor_sync(0xffffffffu, s, o);
                if (lane == 0) inv[r] = 1.f / fmaxf(sqrtf(s), 1e-12f);
            }
            __syncthreads();
            // pair cosine errors: dot(raw_a, raw_b) * inv_a * inv_b
            float acc = 0.f;
            for (int a = w; a < cnt - 1; a += 8) {
                const float4* ra = (const float4*)(rows + a * ROWSTRIDE);
                float ia = inv[a];
                for (int b = a + 1 + lane; b < cnt; b += 32) {
                    const float4* rb = (const float4*)(rows + b * ROWSTRIDE);
                    float dot = 0.f;
#pragma unroll 8
                    for (int k = 0; k < H / 4; k++) {
                        float4 u = ra[k], q = rb[k];
                        dot = fmaf(u.x, q.x, dot);
                        dot = fmaf(u.y, q.y, dot);
                        dot = fmaf(u.z, q.z, dot);
                        dot = fmaf(u.w, q.w, dot);
                    }
                    float e = fmaf(dot * ia, inv[b], -C_SIM);
                    acc = fmaf(e, e, acc);
                }
            }
            if (feat == 0) sacc = acc; else dacc += acc;
            __syncthreads();
        }
    } else if (cnt > MAXM) {
        // fallback (never expected): gmem-direct two-pass meanvar + one-pass pair dots
        float* mean = rows;
        float as = 0.f, a0 = 0.f, a1 = 0.f, a2 = 0.f;
        for (int m = 0; m < cnt; m++) {
            int nd = g_nodes[off + m];
            as += g_si[(size_t)nd * H + t];
            const float* vv = g_vi + (size_t)nd * 3 * H;
            a0 += vv[t]; a1 += vv[H + t]; a2 += vv[2 * H + t];
        }
        float invn = 1.f / (float)cnt;
        mean[t] = as * invn; mean[256 + t] = a0 * invn;
        mean[512 + t] = a1 * invn; mean[768 + t] = a2 * invn;
        __syncthreads();
        for (int m = 0; m < cnt; m++) {
            int nd = g_nodes[off + m];
            float d0 = g_si[(size_t)nd * H + t] - mean[t];
            svar = fmaf(d0, d0, svar);
            const float* vv = g_vi + (size_t)nd * 3 * H;
            float d1 = vv[t] - mean[256 + t];
            float d2 = vv[H + t] - mean[512 + t];
            float d3 = vv[2 * H + t] - mean[768 + t];
            vvar = fmaf(d1, d1, vvar); vvar = fmaf(d2, d2, vvar); vvar = fmaf(d3, d3, vvar);
        }
        for (int feat = 0; feat < 4; feat++) {
            float acc = 0.f;
            for (int a = w; a < cnt - 1; a += 8) {
                int na = g_nodes[off + a];
                const float* ra = (feat == 0) ? g_si + (size_t)na * H
                                              : g_vi + ((size_t)na * 3 + (feat - 1)) * H;
                for (int b = a + 1 + lane; b < cnt; b += 32) {
                    int nb = g_nodes[off + b];
                    const float* rb = (feat == 0) ? g_si + (size_t)nb * H
                                                  : g_vi + ((size_t)nb * 3 + (feat - 1)) * H;
                    float dot = 0.f, sa = 0.f, sb = 0.f;
                    for (int k = 0; k < H; k++) {
                        float x = ra[k], y = rb[k];
                        dot = fmaf(x, y, dot);
                        sa = fmaf(x, x, sa);
                        sb = fmaf(y, y, sb);
                    }
                    float e = dot / (fmaxf(sqrtf(sa), 1e-12f) * fmaxf(sqrtf(sb), 1e-12f)) - C_SIM;
                    acc = fmaf(e, e, acc);
                }
            }
            if (feat == 0) sacc = acc; else dacc += acc;
        }
    }

    // block reduce 4 values
    for (int o = 16; o; o >>= 1) {
        svar += __shfl_xor_sync(0xffffffffu, svar, o);
        vvar += __shfl_xor_sync(0xffffffffu, vvar, o);
        sacc += __shfl_xor_sync(0xffffffffu, sacc, o);
        dacc += __shfl_xor_sync(0xffffffffu, dacc, o);
    }
    if (lane == 0) { rd[w] = svar; rd[8 + w] = vvar; rd[16 + w] = sacc; rd[24 + w] = dacc; }
    __syncthreads();
    if (t == 0) {
        float a = 0.f, b = 0.f, c = 0.f, d = 0.f;
        for (int i = 0; i < 8; i++) { a += rd[i]; b += rd[8 + i]; c += rd[16 + i]; d += rd[24 + i]; }
        g_svar[f] = a; g_vvar[f] = b; g_ssim[f] = c; g_dir[f] = d;
    }
}

// ---------------- final scalar ----------------
__global__ void k_final(float* __restrict__ out) {
    int f = threadIdx.x;
    float n  = (float)g_counts[f];
    float pc = n * (n - 1.f) * 0.5f;
    float ns  = fmaxf(n, 1.f);
    float pcs = fmaxf(pc, 1.f);
    float sl = g_svar[f] / ns + g_ssim[f] / pcs;
    float vl = g_vvar[f] / ns + g_dir[f] / (3.f * pcs);
    float fl = 0.5f * sl + 0.5f * vl;
    float val  = (pc > 0.f) ? fl : 0.f;
    float cntv = (pc > 0.f) ? 1.f : 0.f;
    __shared__ float red[64];
    for (int o = 16; o; o >>= 1) {
        val  += __shfl_xor_sync(0xffffffffu, val, o);
        cntv += __shfl_xor_sync(0xffffffffu, cntv, o);
    }
    int w = f >> 5, lane = f & 31;
    if (lane == 0) { red[w] = val; red[32 + w] = cntv; }
    __syncthreads();
    if (f == 0) {
        float tot = 0.f, tc = 0.f;
        for (int i = 0; i < 8; i++) { tot += red[i]; tc += red[32 + i]; }
        out[0] = (tc > 0.f) ? tot / fmaxf(tc, 1.f) : 0.f;
    }
}

// ---------------- launch ----------------
extern "C" void kernel_launch(void* const* d_in, const int* in_sizes, int n_in,
                              void* d_out, int out_size)
{
    const float* ss = (const float*)d_in[0];
    const float* sl = (const float*)d_in[1];
    const float* vs = (const float*)d_in[2];
    const float* vl = (const float*)d_in[3];
    const float* W1 = (const float*)d_in[4];
    const float* b1 = (const float*)d_in[5];
    const float* W2 = (const float*)d_in[6];
    const float* b2 = (const float*)d_in[7];
    const float* V1 = (const float*)d_in[8];
    const float* V2 = (const float*)d_in[9];
    const int*   frag = (const int*)d_in[10];
    float* out = (float*)d_out;

    void *psi, *pvi, *pwh, *pwl, *ptsh, *ptsl, *ptvh, *ptvl;
    cudaGetSymbolAddress(&psi, g_si);
    cudaGetSymbolAddress(&pvi, g_vi);
    cudaGetSymbolAddress(&pwh, g_wh);
    cudaGetSymbolAddress(&pwl, g_wl);
    cudaGetSymbolAddress(&ptsh, g_tsh);
    cudaGetSymbolAddress(&ptsl, g_tsl);
    cudaGetSymbolAddress(&ptvh, g_tvh);
    cudaGetSymbolAddress(&ptvl, g_tvl);
    const uint16_t* wh = (const uint16_t*)pwh;
    const uint16_t* wl = (const uint16_t*)pwl;
    uint16_t* tsh = (uint16_t*)ptsh;
    uint16_t* tsl = (uint16_t*)ptsl;
    uint16_t* tvh = (uint16_t*)ptvh;
    uint16_t* tvl = (uint16_t*)ptvl;

    k_hist<<<32, 256>>>(frag);
    k_scan2<<<1, 256>>>();
    k_scatter<<<32, 256>>>(frag);
    k_prepw<<<dim3(64, 4), 256>>>(W1, W2, V1, V2);

    cudaFuncSetAttribute(k_gemm1, cudaFuncAttributeMaxDynamicSharedMemorySize, G1_SMEM);
    cudaFuncSetAttribute(k_gemm2, cudaFuncAttributeMaxDynamicSharedMemorySize, G2_SMEM);

    dim3 g(2, NSCALAR_BLOCKS + 192);
    k_gemm1<<<g, 256, G1_SMEM>>>(ss, sl, vs, vl,
                                 wh + 0 * 65536, wl + 0 * 65536,
                                 wh + 2 * 65536, wl + 2 * 65536,
                                 b1, tsh, tsl, tvh, tvl);
    k_gemm2<<<g, 256, G2_SMEM>>>(tsh, tsl, tvh, tvl,
                                 wh + 1 * 65536, wl + 1 * 65536,
                                 wh + 3 * 65536, wl + 3 * 65536,
                                 b2, (float*)psi, (float*)pvi);

    cudaFuncSetAttribute(k_frag, cudaFuncAttributeMaxDynamicSharedMemorySize,
                         MAXM * ROWSTRIDE * 4);
    k_frag<<<NF, 256, MAXM * ROWSTRIDE * 4>>>();

    k_final<<<1, 256>>>(out);
}

// round 10
// speedup vs baseline: 1.2609x; 1.2319x over previous
#include <cuda_runtime.h>
#include <cuda_bf16.h>
#include <math.h>
#include <stdint.h>

#define N_NODES 8192
#define H 256
#define NF 256
#define R_MIX 0.3f
#define C_SIM 0.8f
#define LOG2F_ 0.69314718055994530942f
#define MAXM 64
#define ROWSTRIDE 260

// ---------------- scratch (static device globals) ----------------
__device__ uint16_t g_tsh[ 8192 * 256], g_tsl[ 8192 * 256];
__device__ uint16_t g_tvh[24576 * 256], g_tvl[24576 * 256];
__device__ float g_si[ 8192 * 256];
__device__ float g_vi[24576 * 256];
__device__ uint16_t g_wh[4][65536];
__device__ uint16_t g_wl[4][65536];
__device__ int   g_chunk[256 * 256];
__device__ int   g_counts [NF];
__device__ int   g_offsets[NF + 1];
__device__ int   g_nodes  [N_NODES];
__device__ float g_svar[NF], g_vvar[NF], g_ssim[NF], g_dir[NF];

__device__ __forceinline__ float sspf(float x) {
    float ax = fabsf(x);
    return fmaxf(x, 0.f) + log1pf(__expf(-ax)) - LOG2F_;
}
__device__ __forceinline__ uint32_t pk2(float a, float b) {
    __nv_bfloat162 t = __floats2bfloat162_rn(a, b);
    return *reinterpret_cast<uint32_t*>(&t);
}
__device__ __forceinline__ float bres(float x) {
    __nv_bfloat16 h = __float2bfloat16(x);
    return x - __bfloat162float(h);
}

// ---------------- mma/ldmatrix/cp.async wrappers (sm_103-safe) ----------------
__device__ __forceinline__ void ldsm4(uint32_t addr, uint32_t* r) {
    asm volatile("ldmatrix.sync.aligned.m8n8.x4.shared.b16 {%0,%1,%2,%3}, [%4];"
                 : "=r"(r[0]), "=r"(r[1]), "=r"(r[2]), "=r"(r[3]) : "r"(addr));
}
__device__ __forceinline__ void ldsm4t(uint32_t addr, uint32_t* r) {
    asm volatile("ldmatrix.sync.aligned.m8n8.x4.trans.shared.b16 {%0,%1,%2,%3}, [%4];"
                 : "=r"(r[0]), "=r"(r[1]), "=r"(r[2]), "=r"(r[3]) : "r"(addr));
}
__device__ __forceinline__ void mma16816(float* c, const uint32_t* a, uint32_t b0, uint32_t b1) {
    asm volatile(
        "mma.sync.aligned.m16n8k16.row.col.f32.bf16.bf16.f32 "
        "{%0,%1,%2,%3},{%4,%5,%6,%7},{%8,%9},{%0,%1,%2,%3};"
        : "+f"(c[0]), "+f"(c[1]), "+f"(c[2]), "+f"(c[3])
        : "r"(a[0]), "r"(a[1]), "r"(a[2]), "r"(a[3]), "r"(b0), "r"(b1));
}
__device__ __forceinline__ void cpa16(uint32_t dst, const void* src) {
    asm volatile("cp.async.cg.shared.global [%0], [%1], 16;" :: "r"(dst), "l"(src) : "memory");
}
__device__ __forceinline__ void cpa_commit() {
    asm volatile("cp.async.commit_group;" ::: "memory");
}
__device__ __forceinline__ void cpa_wait0() {
    asm volatile("cp.async.wait_group 0;" ::: "memory");
}
__device__ __forceinline__ void cpa_wait1() {
    asm volatile("cp.async.wait_group 1;" ::: "memory");
}

// ---------------- fragment bookkeeping (deterministic counting sort) -----------
__global__ void k_hist(const int* __restrict__ frag) {
    int chunk = blockIdx.x * 8 + (threadIdx.x >> 5);
    int lane = threadIdx.x & 31;
    for (int j = lane; j < 256; j += 32) g_chunk[chunk * 256 + j] = 0;
    __syncwarp();
    __threadfence_block();
    int i = chunk * 32 + lane;
    int f = frag[i];
    unsigned mask = __match_any_sync(0xffffffffu, f);
    int lr = __popc(mask & ((1u << lane) - 1u));
    if (lr == 0 && f >= 0 && f < NF) g_chunk[chunk * 256 + f] = __popc(mask);
}

// warp-per-fragment exclusive scan over 256 chunk counts (replaces serial scan)
__global__ void k_scanw() {
    int f = blockIdx.x * 8 + (threadIdx.x >> 5);
    int lane = threadIdx.x & 31;
    int carry = 0;
#pragma unroll
    for (int i = 0; i < 8; i++) {
        int idx = (i * 32 + lane) * 256 + f;
        int v = g_chunk[idx];
        int incl = v;
#pragma unroll
        for (int o = 1; o < 32; o <<= 1) {
            int n = __shfl_up_sync(0xffffffffu, incl, o);
            if (lane >= o) incl += n;
        }
        g_chunk[idx] = carry + incl - v;
        carry += __shfl_sync(0xffffffffu, incl, 31);
    }
    if (lane == 0) g_counts[f] = carry;
}

__global__ void k_off() {
    __shared__ int s[256];
    int t = threadIdx.x;
    int v = g_counts[t];
    s[t] = v;
    __syncthreads();
    for (int d = 1; d < 256; d <<= 1) {
        int u = (t >= d) ? s[t - d] : 0;
        __syncthreads();
        s[t] += u;
        __syncthreads();
    }
    g_offsets[t] = s[t] - v;
    if (t == 255) g_offsets[256] = s[255];
}

__global__ void k_scatter(const int* __restrict__ frag) {
    int chunk = blockIdx.x * 8 + (threadIdx.x >> 5);
    int lane = threadIdx.x & 31;
    int i = chunk * 32 + lane;
    int f = frag[i];
    unsigned mask = __match_any_sync(0xffffffffu, f);
    int lr = __popc(mask & ((1u << lane) - 1u));
    if (f >= 0 && f < NF) {
        int pos = g_offsets[f] + g_chunk[chunk * 256 + f] + lr;
        if (pos >= 0 && pos < N_NODES) g_nodes[pos] = i;
    }
}

// ---------------- weight pre-split to bf16 hi/lo (once) ----------------
__global__ void k_prepw(const float* __restrict__ W1, const float* __restrict__ W2,
                        const float* __restrict__ V1, const float* __restrict__ V2)
{
    int m = blockIdx.y;
    const float* src = (m == 0) ? W1 : (m == 1) ? W2 : (m == 2) ? V1 : V2;
    int i0 = (blockIdx.x * 256 + threadIdx.x) * 4;
    float4 v = *(const float4*)(src + i0);
    uint16_t* oh = g_wh[m];
    uint16_t* ol = g_wl[m];
    *(uint32_t*)&oh[i0]     = pk2(v.x, v.y);
    *(uint32_t*)&oh[i0 + 2] = pk2(v.z, v.w);
    *(uint32_t*)&ol[i0]     = pk2(bres(v.x), bres(v.y));
    *(uint32_t*)&ol[i0 + 2] = pk2(bres(v.z), bres(v.w));
}

// ------------- shared GEMM pieces -------------
#define AROW 24
#define BROW 136
#define A_HL (128 * AROW)
#define B_HL (16 * BROW)
#define A_PLANE_B (A_HL * 2)
#define B_PLANE_B (B_HL * 2)
#define ABUF_B (2 * A_PLANE_B)
#define BBUF_B (2 * B_PLANE_B)
#define G1_SMEM (2 * ABUF_B + 3 * BBUF_B)
#define G2_SMEM (3 * ABUF_B + 3 * BBUF_B)
#define NSCALAR_BLOCKS 64

__device__ __forceinline__ void mma_chunk(uint32_t aOff, uint32_t bOff, float acc[4][4][4]) {
    uint32_t ah[4][4], bh[2][4], tmp[2][4], al4[4];
#pragma unroll
    for (int mt = 0; mt < 4; mt++) ldsm4(aOff + mt * (16 * AROW * 2), ah[mt]);
#pragma unroll
    for (int st = 0; st < 2; st++) ldsm4t(bOff + st * 32, bh[st]);
#pragma unroll
    for (int mt = 0; mt < 4; mt++)
#pragma unroll
        for (int nt = 0; nt < 4; nt++)
            mma16816(acc[mt][nt], ah[mt], bh[nt >> 1][(nt & 1) * 2],
                     bh[nt >> 1][(nt & 1) * 2 + 1]);
#pragma unroll
    for (int st = 0; st < 2; st++) ldsm4t(bOff + B_PLANE_B + st * 32, tmp[st]);
#pragma unroll
    for (int mt = 0; mt < 4; mt++)
#pragma unroll
        for (int nt = 0; nt < 4; nt++)
            mma16816(acc[mt][nt], ah[mt], tmp[nt >> 1][(nt & 1) * 2],
                     tmp[nt >> 1][(nt & 1) * 2 + 1]);
#pragma unroll
    for (int mt = 0; mt < 4; mt++) {
        ldsm4(aOff + A_PLANE_B + mt * (16 * AROW * 2), al4);
#pragma unroll
        for (int nt = 0; nt < 4; nt++)
            mma16816(acc[mt][nt], al4, bh[nt >> 1][(nt & 1) * 2],
                     bh[nt >> 1][(nt & 1) * 2 + 1]);
    }
}

__device__ __forceinline__ void gloadA(const float* __restrict__ a1p,
                                       const float* __restrict__ a2p,
                                       int k0, float4& x, float4& y) {
    x = *(const float4*)(a1p + k0);
    y = *(const float4*)(a1p + k0 + 4);
    float4 u = *(const float4*)(a2p + k0);
    float4 v = *(const float4*)(a2p + k0 + 4);
    const float w = 1.f - R_MIX;
    x.x = fmaf(x.x, R_MIX, u.x * w); x.y = fmaf(x.y, R_MIX, u.y * w);
    x.z = fmaf(x.z, R_MIX, u.z * w); x.w = fmaf(x.w, R_MIX, u.w * w);
    y.x = fmaf(y.x, R_MIX, v.x * w); y.y = fmaf(y.y, R_MIX, v.y * w);
    y.z = fmaf(y.z, R_MIX, v.z * w); y.w = fmaf(y.w, R_MIX, v.w * w);
}

__device__ __forceinline__ void cvt_store8(uint16_t* hi_p, uint16_t* lo_p,
                                           const float4& x, const float4& y) {
    uint4 hv, lv;
    hv.x = pk2(x.x, x.y); hv.y = pk2(x.z, x.w);
    hv.z = pk2(y.x, y.y); hv.w = pk2(y.z, y.w);
    lv.x = pk2(bres(x.x), bres(x.y)); lv.y = pk2(bres(x.z), bres(x.w));
    lv.z = pk2(bres(y.x), bres(y.y)); lv.w = pk2(bres(y.z), bres(y.w));
    *reinterpret_cast<uint4*>(hi_p) = hv;
    *reinterpret_cast<uint4*>(lo_p) = lv;
}

// ---------------- layer-1 GEMM ----------------
__global__ __launch_bounds__(256, 2)
void k_gemm1(const float* __restrict__ A1s, const float* __restrict__ A2s,
             const float* __restrict__ A1v, const float* __restrict__ A2v,
             const uint16_t* __restrict__ Bhs, const uint16_t* __restrict__ Bls,
             const uint16_t* __restrict__ Bhv, const uint16_t* __restrict__ Blv,
             const float* __restrict__ biass,
             uint16_t* __restrict__ Csh, uint16_t* __restrict__ Csl,
             uint16_t* __restrict__ Cvh, uint16_t* __restrict__ Cvl)
{
    extern __shared__ __align__(16) uint16_t dsm[];
    uint16_t* sAp = dsm;
    const int tid = threadIdx.x, lane = tid & 31, wid = tid >> 5;
    const int warp_m = wid >> 2, warp_n = wid & 3;
    const bool isS = (blockIdx.y < NSCALAR_BLOCKS);
    const size_t rowBase = (size_t)(isS ? blockIdx.y : blockIdx.y - NSCALAR_BLOCKS) * 128;
    const int colBase = blockIdx.x * 128;
    const float* A1 = isS ? A1s : A1v;
    const float* A2 = isS ? A2s : A2v;
    const uint16_t* Bh = isS ? Bhs : Bhv;
    const uint16_t* Bl = isS ? Bls : Blv;
    const float* bias = isS ? biass : nullptr;
    uint16_t* Ch = isS ? Csh : Cvh;
    uint16_t* Cl = isS ? Csl : Cvl;

    const int am = tid >> 1, ak = (tid & 1) * 8;
    const int bk = tid >> 4, bn = (tid & 15) * 8;

    const float* a1p = A1 + (rowBase + am) * H + ak;
    const float* a2p = A2 + (rowBase + am) * H + ak;
    const uint16_t* bhp = Bh + (size_t)bk * H + colBase + bn;
    const uint16_t* blp = Bl + (size_t)bk * H + colBase + bn;

    uint32_t sA0 = (uint32_t)__cvta_generic_to_shared(dsm);
    uint32_t sB0 = sA0 + 2 * ABUF_B;
    uint32_t bDst = sB0 + (uint32_t)((bk * BROW + bn) * 2);

    const int a_row0 = warp_m * 64 + (lane & 7) + ((lane >> 3) & 1) * 8;
    const int a_kgrp = lane >> 4;
    uint32_t aBase = sA0 + (uint32_t)((a_row0 * AROW + a_kgrp * 8) * 2);
    const int b_krow = (lane & 7) + ((lane >> 3) & 1) * 8;
    const int b_ngrp = lane >> 4;
    uint32_t bBase = sB0 + (uint32_t)((b_krow * BROW + warp_n * 32 + b_ngrp * 8) * 2);

    float acc[4][4][4];
#pragma unroll
    for (int i = 0; i < 4; i++)
#pragma unroll
        for (int j = 0; j < 4; j++)
#pragma unroll
            for (int q = 0; q < 4; q++) acc[i][j][q] = 0.f;

    cpa16(bDst, bhp);
    cpa16(bDst + B_PLANE_B, blp);
    cpa_commit();
    cpa16(bDst + BBUF_B, bhp + (size_t)16 * H);
    cpa16(bDst + BBUF_B + B_PLANE_B, blp + (size_t)16 * H);
    cpa_commit();
    {
        float4 ax0, ay0;
        gloadA(a1p, a2p, 0, ax0, ay0);
        cvt_store8(sAp + (am * AROW + ak), sAp + A_HL + (am * AROW + ak), ax0, ay0);
    }
    cpa_wait1();
    __syncthreads();

    const int NT = H / 16;
    float4 ax, ay;
    for (int t = 0; t < NT; t++) {
        int abuf = t & 1, bbuf = t % 3;
        if (t + 2 < NT) {
            size_t k2 = (size_t)(t + 2) * 16;
            uint32_t bd = bDst + (uint32_t)(((t + 2) % 3) * BBUF_B);
            cpa16(bd, bhp + k2 * H);
            cpa16(bd + B_PLANE_B, blp + k2 * H);
            cpa_commit();
        }
        if (t + 1 < NT) gloadA(a1p, a2p, (t + 1) * 16, ax, ay);
        mma_chunk(aBase + (uint32_t)(abuf * ABUF_B),
                  bBase + (uint32_t)(bbuf * BBUF_B), acc);
        if (t + 1 < NT) {
            int anb = (t + 1) & 1;
            cvt_store8(sAp + anb * (2 * A_HL) + (am * AROW + ak),
                       sAp + anb * (2 * A_HL) + A_HL + (am * AROW + ak), ax, ay);
            if (t + 2 < NT) cpa_wait1(); else cpa_wait0();
            __syncthreads();
        }
    }

#pragma unroll
    for (int mt = 0; mt < 4; mt++) {
        size_t r0 = rowBase + warp_m * 64 + mt * 16 + (lane >> 2);
#pragma unroll
        for (int nt = 0; nt < 4; nt++) {
            int col = colBase + warp_n * 32 + nt * 8 + (lane & 3) * 2;
            float v0 = acc[mt][nt][0], v1 = acc[mt][nt][1];
            float v2 = acc[mt][nt][2], v3 = acc[mt][nt][3];
            if (bias) {
                float2 bb = *(const float2*)&bias[col];
                v0 += bb.x; v1 += bb.y; v2 += bb.x; v3 += bb.y;
            }
            v0 = sspf(v0); v1 = sspf(v1); v2 = sspf(v2); v3 = sspf(v3);
            *(uint32_t*)&Ch[r0 * H + col]       = pk2(v0, v1);
            *(uint32_t*)&Cl[r0 * H + col]       = pk2(bres(v0), bres(v1));
            *(uint32_t*)&Ch[(r0 + 8) * H + col] = pk2(v2, v3);
            *(uint32_t*)&Cl[(r0 + 8) * H + col] = pk2(bres(v2), bres(v3));
        }
    }
}

// ---------------- layer-2 GEMM ----------------
__global__ __launch_bounds__(256, 2)
void k_gemm2(const uint16_t* __restrict__ Ahs, const uint16_t* __restrict__ Als,
             const uint16_t* __restrict__ Ahv, const uint16_t* __restrict__ Alv,
             const uint16_t* __restrict__ Bhs, const uint16_t* __restrict__ Bls,
             const uint16_t* __restrict__ Bhv, const uint16_t* __restrict__ Blv,
             const float* __restrict__ biass,
             float* __restrict__ Cs, float* __restrict__ Cv)
{
    extern __shared__ __align__(16) uint16_t dsm[];
    const int tid = threadIdx.x, lane = tid & 31, wid = tid >> 5;
    const int warp_m = wid >> 2, warp_n = wid & 3;
    const bool isS = (blockIdx.y < NSCALAR_BLOCKS);
    const size_t rowBase = (size_t)(isS ? blockIdx.y : blockIdx.y - NSCALAR_BLOCKS) * 128;
    const int colBase = blockIdx.x * 128;
    const uint16_t* Ah = isS ? Ahs : Ahv;
    const uint16_t* Al = isS ? Als : Alv;
    const uint16_t* Bh = isS ? Bhs : Bhv;
    const uint16_t* Bl = isS ? Bls : Blv;
    const float* bias = isS ? biass : nullptr;
    float* Cc = isS ? Cs : Cv;

    const int am = tid >> 1, ak = (tid & 1) * 8;
    const int bk = tid >> 4, bn = (tid & 15) * 8;

    const uint16_t* ahp = Ah + (rowBase + am) * H + ak;
    const uint16_t* alp = Al + (rowBase + am) * H + ak;
    const uint16_t* bhp = Bh + (size_t)bk * H + colBase + bn;
    const uint16_t* blp = Bl + (size_t)bk * H + colBase + bn;

    uint32_t sA0 = (uint32_t)__cvta_generic_to_shared(dsm);
    uint32_t sB0 = sA0 + 3 * ABUF_B;
    uint32_t aDst = sA0 + (uint32_t)((am * AROW + ak) * 2);
    uint32_t bDst = sB0 + (uint32_t)((bk * BROW + bn) * 2);

    const int a_row0 = warp_m * 64 + (lane & 7) + ((lane >> 3) & 1) * 8;
    const int a_kgrp = lane >> 4;
    uint32_t aBase = sA0 + (uint32_t)((a_row0 * AROW + a_kgrp * 8) * 2);
    const int b_krow = (lane & 7) + ((lane >> 3) & 1) * 8;
    const int b_ngrp = lane >> 4;
    uint32_t bBase = sB0 + (uint32_t)((b_krow * BROW + warp_n * 32 + b_ngrp * 8) * 2);

    float acc[4][4][4];
#pragma unroll
    for (int i = 0; i < 4; i++)
#pragma unroll
        for (int j = 0; j < 4; j++)
#pragma unroll
            for (int q = 0; q < 4; q++) acc[i][j][q] = 0.f;

#pragma unroll
    for (int c = 0; c < 2; c++) {
        size_t k0 = (size_t)c * 16;
        uint32_t ad = aDst + (uint32_t)(c * ABUF_B);
        uint32_t bd = bDst + (uint32_t)(c * BBUF_B);
        cpa16(ad, ahp + k0);
        cpa16(ad + A_PLANE_B, alp + k0);
        cpa16(bd, bhp + k0 * H);
        cpa16(bd + B_PLANE_B, blp + k0 * H);
        cpa_commit();
    }
    cpa_wait1();
    __syncthreads();

    const int NT = H / 16;
    for (int t = 0; t < NT; t++) {
        int buf = t % 3;
        if (t + 2 < NT) {
            size_t k2 = (size_t)(t + 2) * 16;
            int nb2 = (t + 2) % 3;
            uint32_t ad = aDst + (uint32_t)(nb2 * ABUF_B);
            uint32_t bd = bDst + (uint32_t)(nb2 * BBUF_B);
            cpa16(ad, ahp + k2);
            cpa16(ad + A_PLANE_B, alp + k2);
            cpa16(bd, bhp + k2 * H);
            cpa16(bd + B_PLANE_B, blp + k2 * H);
            cpa_commit();
        }
        mma_chunk(aBase + (uint32_t)(buf * ABUF_B),
                  bBase + (uint32_t)(buf * BBUF_B), acc);
        if (t + 1 < NT) {
            if (t + 2 < NT) cpa_wait1(); else cpa_wait0();
            __syncthreads();
        }
    }

#pragma unroll
    for (int mt = 0; mt < 4; mt++) {
        size_t r0 = rowBase + warp_m * 64 + mt * 16 + (lane >> 2);
#pragma unroll
        for (int nt = 0; nt < 4; nt++) {
            int col = colBase + warp_n * 32 + nt * 8 + (lane & 3) * 2;
            float v0 = acc[mt][nt][0], v1 = acc[mt][nt][1];
            float v2 = acc[mt][nt][2], v3 = acc[mt][nt][3];
            if (bias) {
                float2 bb = *(const float2*)&bias[col];
                v0 += bb.x; v1 += bb.y; v2 += bb.x; v3 += bb.y;
            }
            float2 o0; o0.x = v0; o0.y = v1;
            float2 o1; o1.x = v2; o1.y = v3;
            *(float2*)&Cc[r0 * H + col] = o0;
            *(float2*)&Cc[(r0 + 8) * H + col] = o1;
        }
    }
}

// ---------------- fused per-fragment stats (block per fragment) ----------------
// Half-warp pair distribution: warp covers a-rows {2w+half (+16k)}, b stride 16.
__global__ void k_frag() {
    extern __shared__ float rows[];   // MAXM * ROWSTRIDE floats
    __shared__ float inv[MAXM];
    __shared__ float rd[32];
    int f = blockIdx.x, t = threadIdx.x;
    int cnt = g_counts[f], off = g_offsets[f];
    int w = t >> 5, lane = t & 31;
    int half = lane >> 4, hl = lane & 15;
    float sacc = 0.f, dacc = 0.f, svar = 0.f, vvar = 0.f;

    if (cnt >= 2 && cnt <= MAXM) {
        for (int feat = 0; feat < 4; feat++) {
            for (int r = 0; r < cnt; r++) {
                int nd = g_nodes[off + r];
                const float* src = (feat == 0) ? g_si + (size_t)nd * H
                                               : g_vi + ((size_t)nd * 3 + (feat - 1)) * H;
                rows[r * ROWSTRIDE + t] = src[t];
            }
            __syncthreads();
            // column mean + variance
            {
                float s1 = 0.f;
                for (int r = 0; r < cnt; r++) s1 += rows[r * ROWSTRIDE + t];
                float mean = s1 / (float)cnt;
                float v = 0.f;
                for (int r = 0; r < cnt; r++) {
                    float d = rows[r * ROWSTRIDE + t] - mean;
                    v = fmaf(d, d, v);
                }
                if (feat == 0) svar += v; else vvar += v;
            }
            // row inverse L2 norms
            for (int r = w; r < cnt; r += 8) {
                const float* rp = rows + r * ROWSTRIDE;
                float s = 0.f;
                for (int j = lane; j < H; j += 32) { float x = rp[j]; s = fmaf(x, x, s); }
                for (int o = 16; o; o >>= 1) s += __shfl_xor_sync(0xffffffffu, s, o);
                if (lane == 0) inv[r] = 1.f / fmaxf(sqrtf(s), 1e-12f);
            }
            __syncthreads();
            // pairs: two a-rows per warp sweep (one per half-warp), b stride 16
            float acc = 0.f;
            for (int a0 = w * 2; a0 < cnt - 1; a0 += 16) {
                int a = a0 + half;
                if (a <= cnt - 2) {
                    const float4* ra = (const float4*)(rows + a * ROWSTRIDE);
                    float ia = inv[a];
                    for (int b = a + 1 + hl; b < cnt; b += 16) {
                        const float4* rb = (const float4*)(rows + b * ROWSTRIDE);
                        float dot = 0.f;
#pragma unroll 8
                        for (int k = 0; k < H / 4; k++) {
                            float4 u = ra[k], q = rb[k];
                            dot = fmaf(u.x, q.x, dot);
                            dot = fmaf(u.y, q.y, dot);
                            dot = fmaf(u.z, q.z, dot);
                            dot = fmaf(u.w, q.w, dot);
                        }
                        float e = fmaf(dot * ia, inv[b], -C_SIM);
                        acc = fmaf(e, e, acc);
                    }
                }
            }
            if (feat == 0) sacc = acc; else dacc += acc;
            __syncthreads();
        }
    } else if (cnt > MAXM) {
        // fallback (never expected): gmem-direct
        float* mean = rows;
        float as = 0.f, a0m = 0.f, a1m = 0.f, a2m = 0.f;
        for (int m = 0; m < cnt; m++) {
            int nd = g_nodes[off + m];
            as += g_si[(size_t)nd * H + t];
            const float* vv = g_vi + (size_t)nd * 3 * H;
            a0m += vv[t]; a1m += vv[H + t]; a2m += vv[2 * H + t];
        }
        float invn = 1.f / (float)cnt;
        mean[t] = as * invn; mean[256 + t] = a0m * invn;
        mean[512 + t] = a1m * invn; mean[768 + t] = a2m * invn;
        __syncthreads();
        for (int m = 0; m < cnt; m++) {
            int nd = g_nodes[off + m];
            float d0 = g_si[(size_t)nd * H + t] - mean[t];
            svar = fmaf(d0, d0, svar);
            const float* vv = g_vi + (size_t)nd * 3 * H;
            float d1 = vv[t] - mean[256 + t];
            float d2 = vv[H + t] - mean[512 + t];
            float d3 = vv[2 * H + t] - mean[768 + t];
            vvar = fmaf(d1, d1, vvar); vvar = fmaf(d2, d2, vvar); vvar = fmaf(d3, d3, vvar);
        }
        for (int feat = 0; feat < 4; feat++) {
            float acc = 0.f;
            for (int a = w; a < cnt - 1; a += 8) {
                int na = g_nodes[off + a];
                const float* ra = (feat == 0) ? g_si + (size_t)na * H
                                              : g_vi + ((size_t)na * 3 + (feat - 1)) * H;
                for (int b = a + 1 + lane; b < cnt; b += 32) {
                    int nb = g_nodes[off + b];
                    const float* rb = (feat == 0) ? g_si + (size_t)nb * H
                                                  : g_vi + ((size_t)nb * 3 + (feat - 1)) * H;
                    float dot = 0.f, sa = 0.f, sb = 0.f;
                    for (int k = 0; k < H; k++) {
                        float x = ra[k], y = rb[k];
                        dot = fmaf(x, y, dot);
                        sa = fmaf(x, x, sa);
                        sb = fmaf(y, y, sb);
                    }
                    float e = dot / (fmaxf(sqrtf(sa), 1e-12f) * fmaxf(sqrtf(sb), 1e-12f)) - C_SIM;
                    acc = fmaf(e, e, acc);
                }
            }
            if (feat == 0) sacc = acc; else dacc += acc;
        }
    }

    for (int o = 16; o; o >>= 1) {
        svar += __shfl_xor_sync(0xffffffffu, svar, o);
        vvar += __shfl_xor_sync(0xffffffffu, vvar, o);
        sacc += __shfl_xor_sync(0xffffffffu, sacc, o);
        dacc += __shfl_xor_sync(0xffffffffu, dacc, o);
    }
    if (lane == 0) { rd[w] = svar; rd[8 + w] = vvar; rd[16 + w] = sacc; rd[24 + w] = dacc; }
    __syncthreads();
    if (t == 0) {
        float a = 0.f, b = 0.f, c = 0.f, d = 0.f;
        for (int i = 0; i < 8; i++) { a += rd[i]; b += rd[8 + i]; c += rd[16 + i]; d += rd[24 + i]; }
        g_svar[f] = a; g_vvar[f] = b; g_ssim[f] = c; g_dir[f] = d;
    }
}

// ---------------- final scalar ----------------
__global__ void k_final(float* __restrict__ out) {
    int f = threadIdx.x;
    float n  = (float)g_counts[f];
    float pc = n * (n - 1.f) * 0.5f;
    float ns  = fmaxf(n, 1.f);
    float pcs = fmaxf(pc, 1.f);
    float sl = g_svar[f] / ns + g_ssim[f] / pcs;
    float vl = g_vvar[f] / ns + g_dir[f] / (3.f * pcs);
    float fl = 0.5f * sl + 0.5f * vl;
    float val  = (pc > 0.f) ? fl : 0.f;
    float cntv = (pc > 0.f) ? 1.f : 0.f;
    __shared__ float red[64];
    for (int o = 16; o; o >>= 1) {
        val  += __shfl_xor_sync(0xffffffffu, val, o);
        cntv += __shfl_xor_sync(0xffffffffu, cntv, o);
    }
    int w = f >> 5, lane = f & 31;
    if (lane == 0) { red[w] = val; red[32 + w] = cntv; }
    __syncthreads();
    if (f == 0) {
        float tot = 0.f, tc = 0.f;
        for (int i = 0; i < 8; i++) { tot += red[i]; tc += red[32 + i]; }
        out[0] = (tc > 0.f) ? tot / fmaxf(tc, 1.f) : 0.f;
    }
}

// ---------------- launch ----------------
extern "C" void kernel_launch(void* const* d_in, const int* in_sizes, int n_in,
                              void* d_out, int out_size)
{
    const float* ss = (const float*)d_in[0];
    const float* sl = (const float*)d_in[1];
    const float* vs = (const float*)d_in[2];
    const float* vl = (const float*)d_in[3];
    const float* W1 = (const float*)d_in[4];
    const float* b1 = (const float*)d_in[5];
    const float* W2 = (const float*)d_in[6];
    const float* b2 = (const float*)d_in[7];
    const float* V1 = (const float*)d_in[8];
    const float* V2 = (const float*)d_in[9];
    const int*   frag = (const int*)d_in[10];
    float* out = (float*)d_out;

    void *psi, *pvi, *pwh, *pwl, *ptsh, *ptsl, *ptvh, *ptvl;
    cudaGetSymbolAddress(&psi, g_si);
    cudaGetSymbolAddress(&pvi, g_vi);
    cudaGetSymbolAddress(&pwh, g_wh);
    cudaGetSymbolAddress(&pwl, g_wl);
    cudaGetSymbolAddress(&ptsh, g_tsh);
    cudaGetSymbolAddress(&ptsl, g_tsl);
    cudaGetSymbolAddress(&ptvh, g_tvh);
    cudaGetSymbolAddress(&ptvl, g_tvl);
    const uint16_t* wh = (const uint16_t*)pwh;
    const uint16_t* wl = (const uint16_t*)pwl;
    uint16_t* tsh = (uint16_t*)ptsh;
    uint16_t* tsl = (uint16_t*)ptsl;
    uint16_t* tvh = (uint16_t*)ptvh;
    uint16_t* tvl = (uint16_t*)ptvl;

    k_hist<<<32, 256>>>(frag);
    k_scanw<<<32, 256>>>();
    k_off<<<1, 256>>>();
    k_scatter<<<32, 256>>>(frag);
    k_prepw<<<dim3(64, 4), 256>>>(W1, W2, V1, V2);

    cudaFuncSetAttribute(k_gemm1, cudaFuncAttributeMaxDynamicSharedMemorySize, G1_SMEM);
    cudaFuncSetAttribute(k_gemm2, cudaFuncAttributeMaxDynamicSharedMemorySize, G2_SMEM);

    dim3 g(2, NSCALAR_BLOCKS + 192);
    k_gemm1<<<g, 256, G1_SMEM>>>(ss, sl, vs, vl,
                                 wh + 0 * 65536, wl + 0 * 65536,
                                 wh + 2 * 65536, wl + 2 * 65536,
                                 b1, tsh, tsl, tvh, tvl);
    k_gemm2<<<g, 256, G2_SMEM>>>(tsh, tsl, tvh, tvl,
                                 wh + 1 * 65536, wl + 1 * 65536,
                                 wh + 3 * 65536, wl + 3 * 65536,
                                 b2, (float*)psi, (float*)pvi);

    cudaFuncSetAttribute(k_frag, cudaFuncAttributeMaxDynamicSharedMemorySize,
                         MAXM * ROWSTRIDE * 4);
    k_frag<<<NF, 256, MAXM * ROWSTRIDE * 4>>>();

    k_final<<<1, 256>>>(out);
}

// round 11
// speedup vs baseline: 1.2765x; 1.0124x over previous
#include <cuda_runtime.h>
#include <cuda_bf16.h>
#include <math.h>
#include <stdint.h>

#define N_NODES 8192
#define H 256
#define NF 256
#define R_MIX 0.3f
#define C_SIM 0.8f
#define LOG2F_ 0.69314718055994530942f
#define MAXM 64
#define ROWSTRIDE 260

// ---------------- scratch (static device globals) ----------------
__device__ uint16_t g_tsh[ 8192 * 256], g_tsl[ 8192 * 256];
__device__ uint16_t g_tvh[24576 * 256], g_tvl[24576 * 256];
__device__ float g_si[ 8192 * 256];
__device__ float g_vi[24576 * 256];
__device__ uint16_t g_wh[4][65536];
__device__ uint16_t g_wl[4][65536];
__device__ int   g_counts [NF];
__device__ int   g_offsets[NF + 1];
__device__ int   g_nodes  [N_NODES];
__device__ float g_svar[NF], g_vvar[NF], g_ssim[NF], g_dir[NF];
__device__ int   g_done;   // last-block flag for fused final (self-resetting)

__device__ __forceinline__ float sspf(float x) {
    float ax = fabsf(x);
    return fmaxf(x, 0.f) + log1pf(__expf(-ax)) - LOG2F_;
}
__device__ __forceinline__ uint32_t pk2(float a, float b) {
    __nv_bfloat162 t = __floats2bfloat162_rn(a, b);
    return *reinterpret_cast<uint32_t*>(&t);
}
__device__ __forceinline__ float bres(float x) {
    __nv_bfloat16 h = __float2bfloat16(x);
    return x - __bfloat162float(h);
}

// ---------------- mma/ldmatrix/cp.async wrappers (sm_103-safe) ----------------
__device__ __forceinline__ void ldsm4(uint32_t addr, uint32_t* r) {
    asm volatile("ldmatrix.sync.aligned.m8n8.x4.shared.b16 {%0,%1,%2,%3}, [%4];"
                 : "=r"(r[0]), "=r"(r[1]), "=r"(r[2]), "=r"(r[3]) : "r"(addr));
}
__device__ __forceinline__ void ldsm4t(uint32_t addr, uint32_t* r) {
    asm volatile("ldmatrix.sync.aligned.m8n8.x4.trans.shared.b16 {%0,%1,%2,%3}, [%4];"
                 : "=r"(r[0]), "=r"(r[1]), "=r"(r[2]), "=r"(r[3]) : "r"(addr));
}
__device__ __forceinline__ void mma16816(float* c, const uint32_t* a, uint32_t b0, uint32_t b1) {
    asm volatile(
        "mma.sync.aligned.m16n8k16.row.col.f32.bf16.bf16.f32 "
        "{%0,%1,%2,%3},{%4,%5,%6,%7},{%8,%9},{%0,%1,%2,%3};"
        : "+f"(c[0]), "+f"(c[1]), "+f"(c[2]), "+f"(c[3])
        : "r"(a[0]), "r"(a[1]), "r"(a[2]), "r"(a[3]), "r"(b0), "r"(b1));
}
__device__ __forceinline__ void cpa16(uint32_t dst, const void* src) {
    asm volatile("cp.async.cg.shared.global [%0], [%1], 16;" :: "r"(dst), "l"(src) : "memory");
}
__device__ __forceinline__ void cpa_commit() {
    asm volatile("cp.async.commit_group;" ::: "memory");
}
__device__ __forceinline__ void cpa_wait0() {
    asm volatile("cp.async.wait_group 0;" ::: "memory");
}

// ---------------- fused setup: block 0 = full counting sort, blocks 1..256 = prepw ----
__global__ void k_setup(const int* __restrict__ frag,
                        const float* __restrict__ W1, const float* __restrict__ W2,
                        const float* __restrict__ V1, const float* __restrict__ V2)
{
    if (blockIdx.x == 0) {
        // deterministic counting sort of 8192 nodes, single block, 8 warps
        __shared__ int s_sc[8 * 256];   // per-warp fragment counters -> warp bases
        __shared__ int s_off[256];
        __shared__ int s_tmp[256];
        int t = threadIdx.x, w = t >> 5, l = t & 31;

        for (int j = t; j < 2048; j += 256) s_sc[j] = 0;
        __syncthreads();

        // phase 1: warp w handles chunks [w*32, w*32+32); node fragments in regs
        int fv[32], lp[32];
#pragma unroll
        for (int c = 0; c < 32; c++) fv[c] = frag[(w * 32 + c) * 32 + l];
        for (int c = 0; c < 32; c++) {
            int f = fv[c];
            bool ok = (f >= 0 && f < NF);
            unsigned mask = __match_any_sync(0xffffffffu, f);
            int rank = __popc(mask & ((1u << l) - 1u));
            int before = ok ? s_sc[w * 256 + f] : 0;
            lp[c] = before + rank;
            __syncwarp();
            if (ok && rank == 0) s_sc[w * 256 + f] = before + __popc(mask);
            __syncwarp();
        }
        __syncthreads();

        // phase 2: cross-warp exclusive scan per fragment + global offsets
        {
            int run = 0;
#pragma unroll
            for (int w2 = 0; w2 < 8; w2++) {
                int v = s_sc[w2 * 256 + t];
                s_sc[w2 * 256 + t] = run;
                run += v;
            }
            g_counts[t] = run;
            s_tmp[t] = run;
            __syncthreads();
            for (int d = 1; d < 256; d <<= 1) {
                int u = (t >= d) ? s_tmp[t - d] : 0;
                __syncthreads();
                s_tmp[t] += u;
                __syncthreads();
            }
            s_off[t] = s_tmp[t] - run;
            g_offsets[t] = s_off[t];
            if (t == 255) g_offsets[256] = s_tmp[255];
        }
        __syncthreads();

        // phase 3: scatter
        for (int c = 0; c < 32; c++) {
            int f = fv[c];
            if (f >= 0 && f < NF) {
                int pos = s_off[f] + s_sc[w * 256 + f] + lp[c];
                if (pos >= 0 && pos < N_NODES)
                    g_nodes[pos] = (w * 32 + c) * 32 + l;
            }
        }
    } else {
        // weight bf16 hi/lo pre-split
        int bb = blockIdx.x - 1;
        int m = bb >> 6;
        const float* src = (m == 0) ? W1 : (m == 1) ? W2 : (m == 2) ? V1 : V2;
        int i0 = ((bb & 63) * 256 + threadIdx.x) * 4;
        float4 v = *(const float4*)(src + i0);
        uint16_t* oh = g_wh[m];
        uint16_t* ol = g_wl[m];
        *(uint32_t*)&oh[i0]     = pk2(v.x, v.y);
        *(uint32_t*)&oh[i0 + 2] = pk2(v.z, v.w);
        *(uint32_t*)&ol[i0]     = pk2(bres(v.x), bres(v.y));
        *(uint32_t*)&ol[i0 + 2] = pk2(bres(v.z), bres(v.w));
    }
}

// ------------- shared GEMM pieces -------------
#define AROW 24
#define BROW 136
#define A_HL (128 * AROW)
#define B_HL (16 * BROW)
#define A_PLANE_B (A_HL * 2)
#define B_PLANE_B (B_HL * 2)
#define ABUF_B (2 * A_PLANE_B)     // 12288
#define BBUF_B (2 * B_PLANE_B)     // 8704
#define G_SMEM (4 * ABUF_B + 4 * BBUF_B)   // 83968
#define NSCALAR_BLOCKS 64

__device__ __forceinline__ void mma_chunk(uint32_t aOff, uint32_t bOff, float acc[4][4][4]) {
    uint32_t ah[4][4], bh[2][4], tmp[2][4], al4[4];
#pragma unroll
    for (int mt = 0; mt < 4; mt++) ldsm4(aOff + mt * (16 * AROW * 2), ah[mt]);
#pragma unroll
    for (int st = 0; st < 2; st++) ldsm4t(bOff + st * 32, bh[st]);
#pragma unroll
    for (int mt = 0; mt < 4; mt++)
#pragma unroll
        for (int nt = 0; nt < 4; nt++)
            mma16816(acc[mt][nt], ah[mt], bh[nt >> 1][(nt & 1) * 2],
                     bh[nt >> 1][(nt & 1) * 2 + 1]);
#pragma unroll
    for (int st = 0; st < 2; st++) ldsm4t(bOff + B_PLANE_B + st * 32, tmp[st]);
#pragma unroll
    for (int mt = 0; mt < 4; mt++)
#pragma unroll
        for (int nt = 0; nt < 4; nt++)
            mma16816(acc[mt][nt], ah[mt], tmp[nt >> 1][(nt & 1) * 2],
                     tmp[nt >> 1][(nt & 1) * 2 + 1]);
#pragma unroll
    for (int mt = 0; mt < 4; mt++) {
        ldsm4(aOff + A_PLANE_B + mt * (16 * AROW * 2), al4);
#pragma unroll
        for (int nt = 0; nt < 4; nt++)
            mma16816(acc[mt][nt], al4, bh[nt >> 1][(nt & 1) * 2],
                     bh[nt >> 1][(nt & 1) * 2 + 1]);
    }
}

__device__ __forceinline__ void gloadA(const float* __restrict__ a1p,
                                       const float* __restrict__ a2p,
                                       int k0, float4& x, float4& y) {
    x = *(const float4*)(a1p + k0);
    y = *(const float4*)(a1p + k0 + 4);
    float4 u = *(const float4*)(a2p + k0);
    float4 v = *(const float4*)(a2p + k0 + 4);
    const float w = 1.f - R_MIX;
    x.x = fmaf(x.x, R_MIX, u.x * w); x.y = fmaf(x.y, R_MIX, u.y * w);
    x.z = fmaf(x.z, R_MIX, u.z * w); x.w = fmaf(x.w, R_MIX, u.w * w);
    y.x = fmaf(y.x, R_MIX, v.x * w); y.y = fmaf(y.y, R_MIX, v.y * w);
    y.z = fmaf(y.z, R_MIX, v.z * w); y.w = fmaf(y.w, R_MIX, v.w * w);
}

__device__ __forceinline__ void cvt_store8(uint16_t* hi_p, uint16_t* lo_p,
                                           const float4& x, const float4& y) {
    uint4 hv, lv;
    hv.x = pk2(x.x, x.y); hv.y = pk2(x.z, x.w);
    hv.z = pk2(y.x, y.y); hv.w = pk2(y.z, y.w);
    lv.x = pk2(bres(x.x), bres(x.y)); lv.y = pk2(bres(x.z), bres(x.w));
    lv.z = pk2(bres(y.x), bres(y.y)); lv.w = pk2(bres(y.z), bres(y.w));
    *reinterpret_cast<uint4*>(hi_p) = hv;
    *reinterpret_cast<uint4*>(lo_p) = lv;
}

// ---------------- layer-1 GEMM: fp32 A (mix) -> ssp -> bf16 hi/lo out -------------
// 4 chunk-buffers, TWO chunks per barrier. B via cp.async, A via RF convert.
__global__ __launch_bounds__(256, 2)
void k_gemm1(const float* __restrict__ A1s, const float* __restrict__ A2s,
             const float* __restrict__ A1v, const float* __restrict__ A2v,
             const uint16_t* __restrict__ Bhs, const uint16_t* __restrict__ Bls,
             const uint16_t* __restrict__ Bhv, const uint16_t* __restrict__ Blv,
             const float* __restrict__ biass,
             uint16_t* __restrict__ Csh, uint16_t* __restrict__ Csl,
             uint16_t* __restrict__ Cvh, uint16_t* __restrict__ Cvl)
{
    extern __shared__ __align__(16) uint16_t dsm[];
    const int tid = threadIdx.x, lane = tid & 31, wid = tid >> 5;
    const int warp_m = wid >> 2, warp_n = wid & 3;
    const bool isS = (blockIdx.y < NSCALAR_BLOCKS);
    const size_t rowBase = (size_t)(isS ? blockIdx.y : blockIdx.y - NSCALAR_BLOCKS) * 128;
    const int colBase = blockIdx.x * 128;
    const float* A1 = isS ? A1s : A1v;
    const float* A2 = isS ? A2s : A2v;
    const uint16_t* Bh = isS ? Bhs : Bhv;
    const uint16_t* Bl = isS ? Bls : Blv;
    const float* bias = isS ? biass : nullptr;
    uint16_t* Ch = isS ? Csh : Cvh;
    uint16_t* Cl = isS ? Csl : Cvl;

    const int am = tid >> 1, ak = (tid & 1) * 8;
    const int bk = tid >> 4, bn = (tid & 15) * 8;

    const float* a1p = A1 + (rowBase + am) * H + ak;
    const float* a2p = A2 + (rowBase + am) * H + ak;
    const uint16_t* bhp = Bh + (size_t)bk * H + colBase + bn;
    const uint16_t* blp = Bl + (size_t)bk * H + colBase + bn;

    uint32_t sA0 = (uint32_t)__cvta_generic_to_shared(dsm);
    uint32_t sB0 = sA0 + 4 * ABUF_B;
    uint32_t bDst = sB0 + (uint32_t)((bk * BROW + bn) * 2);
    uint16_t* aStore = dsm + (am * AROW + ak);   // + buf*ABUF_B/2, lo at +A_HL

    const int a_row0 = warp_m * 64 + (lane & 7) + ((lane >> 3) & 1) * 8;
    const int a_kgrp = lane >> 4;
    uint32_t aBase = sA0 + (uint32_t)((a_row0 * AROW + a_kgrp * 8) * 2);
    const int b_krow = (lane & 7) + ((lane >> 3) & 1) * 8;
    const int b_ngrp = lane >> 4;
    uint32_t bBase = sB0 + (uint32_t)((b_krow * BROW + warp_n * 32 + b_ngrp * 8) * 2);

    float acc[4][4][4];
#pragma unroll
    for (int i = 0; i < 4; i++)
#pragma unroll
        for (int j = 0; j < 4; j++)
#pragma unroll
            for (int q = 0; q < 4; q++) acc[i][j][q] = 0.f;

    // prologue: B chunks 0,1 via cp.async (single group); A chunks 0,1 via RF
    cpa16(bDst, bhp);
    cpa16(bDst + B_PLANE_B, blp);
    cpa16(bDst + BBUF_B, bhp + (size_t)16 * H);
    cpa16(bDst + BBUF_B + B_PLANE_B, blp + (size_t)16 * H);
    cpa_commit();
    {
        float4 ax, ay;
        gloadA(a1p, a2p, 0, ax, ay);
        cvt_store8(aStore, aStore + A_HL, ax, ay);
        gloadA(a1p, a2p, 16, ax, ay);
        cvt_store8(aStore + ABUF_B / 2, aStore + ABUF_B / 2 + A_HL, ax, ay);
    }
    cpa_wait0();
    __syncthreads();

    const int NT = H / 16;   // 16
    for (int t = 0; t < NT; t += 2) {
        if (t + 2 < NT) {
            int c2 = t + 2, c3 = t + 3;
            size_t k2 = (size_t)c2 * 16, k3 = (size_t)c3 * 16;
            uint32_t bd2 = bDst + (uint32_t)((c2 & 3) * BBUF_B);
            uint32_t bd3 = bDst + (uint32_t)((c3 & 3) * BBUF_B);
            cpa16(bd2, bhp + k2 * H);
            cpa16(bd2 + B_PLANE_B, blp + k2 * H);
            cpa16(bd3, bhp + k3 * H);
            cpa16(bd3 + B_PLANE_B, blp + k3 * H);
            cpa_commit();
            float4 ax, ay;
            gloadA(a1p, a2p, (int)k2, ax, ay);
            cvt_store8(aStore + (c2 & 3) * (ABUF_B / 2),
                       aStore + (c2 & 3) * (ABUF_B / 2) + A_HL, ax, ay);
            gloadA(a1p, a2p, (int)k3, ax, ay);
            cvt_store8(aStore + (c3 & 3) * (ABUF_B / 2),
                       aStore + (c3 & 3) * (ABUF_B / 2) + A_HL, ax, ay);
        }
        mma_chunk(aBase + (uint32_t)((t & 3) * ABUF_B),
                  bBase + (uint32_t)((t & 3) * BBUF_B), acc);
        mma_chunk(aBase + (uint32_t)(((t + 1) & 3) * ABUF_B),
                  bBase + (uint32_t)(((t + 1) & 3) * BBUF_B), acc);
        if (t + 2 < NT) {
            cpa_wait0();
            __syncthreads();
        }
    }

    // epilogue: bias + ssp, split to bf16 hi/lo planes
#pragma unroll
    for (int mt = 0; mt < 4; mt++) {
        size_t r0 = rowBase + warp_m * 64 + mt * 16 + (lane >> 2);
#pragma unroll
        for (int nt = 0; nt < 4; nt++) {
            int col = colBase + warp_n * 32 + nt * 8 + (lane & 3) * 2;
            float v0 = acc[mt][nt][0], v1 = acc[mt][nt][1];
            float v2 = acc[mt][nt][2], v3 = acc[mt][nt][3];
            if (bias) {
                float2 bb = *(const float2*)&bias[col];
                v0 += bb.x; v1 += bb.y; v2 += bb.x; v3 += bb.y;
            }
            v0 = sspf(v0); v1 = sspf(v1); v2 = sspf(v2); v3 = sspf(v3);
            *(uint32_t*)&Ch[r0 * H + col]       = pk2(v0, v1);
            *(uint32_t*)&Cl[r0 * H + col]       = pk2(bres(v0), bres(v1));
            *(uint32_t*)&Ch[(r0 + 8) * H + col] = pk2(v2, v3);
            *(uint32_t*)&Cl[(r0 + 8) * H + col] = pk2(bres(v2), bres(v3));
        }
    }
}

// ---------------- layer-2 GEMM: bf16 hi/lo A planes -> fp32 out -------------------
// 4 chunk-buffers, TWO chunks per barrier. A and B via cp.async.
__global__ __launch_bounds__(256, 2)
void k_gemm2(const uint16_t* __restrict__ Ahs, const uint16_t* __restrict__ Als,
             const uint16_t* __restrict__ Ahv, const uint16_t* __restrict__ Alv,
             const uint16_t* __restrict__ Bhs, const uint16_t* __restrict__ Bls,
             const uint16_t* __restrict__ Bhv, const uint16_t* __restrict__ Blv,
             const float* __restrict__ biass,
             float* __restrict__ Cs, float* __restrict__ Cv)
{
    extern __shared__ __align__(16) uint16_t dsm[];
    const int tid = threadIdx.x, lane = tid & 31, wid = tid >> 5;
    const int warp_m = wid >> 2, warp_n = wid & 3;
    const bool isS = (blockIdx.y < NSCALAR_BLOCKS);
    const size_t rowBase = (size_t)(isS ? blockIdx.y : blockIdx.y - NSCALAR_BLOCKS) * 128;
    const int colBase = blockIdx.x * 128;
    const uint16_t* Ah = isS ? Ahs : Ahv;
    const uint16_t* Al = isS ? Als : Alv;
    const uint16_t* Bh = isS ? Bhs : Bhv;
    const uint16_t* Bl = isS ? Bls : Blv;
    const float* bias = isS ? biass : nullptr;
    float* Cc = isS ? Cs : Cv;

    const int am = tid >> 1, ak = (tid & 1) * 8;
    const int bk = tid >> 4, bn = (tid & 15) * 8;

    const uint16_t* ahp = Ah + (rowBase + am) * H + ak;
    const uint16_t* alp = Al + (rowBase + am) * H + ak;
    const uint16_t* bhp = Bh + (size_t)bk * H + colBase + bn;
    const uint16_t* blp = Bl + (size_t)bk * H + colBase + bn;

    uint32_t sA0 = (uint32_t)__cvta_generic_to_shared(dsm);
    uint32_t sB0 = sA0 + 4 * ABUF_B;
    uint32_t aDst = sA0 + (uint32_t)((am * AROW + ak) * 2);
    uint32_t bDst = sB0 + (uint32_t)((bk * BROW + bn) * 2);

    const int a_row0 = warp_m * 64 + (lane & 7) + ((lane >> 3) & 1) * 8;
    const int a_kgrp = lane >> 4;
    uint32_t aBase = sA0 + (uint32_t)((a_row0 * AROW + a_kgrp * 8) * 2);
    const int b_krow = (lane & 7) + ((lane >> 3) & 1) * 8;
    const int b_ngrp = lane >> 4;
    uint32_t bBase = sB0 + (uint32_t)((b_krow * BROW + warp_n * 32 + b_ngrp * 8) * 2);

    float acc[4][4][4];
#pragma unroll
    for (int i = 0; i < 4; i++)
#pragma unroll
        for (int j = 0; j < 4; j++)
#pragma unroll
            for (int q = 0; q < 4; q++) acc[i][j][q] = 0.f;

    // prologue: chunks 0,1 via cp.async (single group)
#pragma unroll
    for (int c = 0; c < 2; c++) {
        size_t k0 = (size_t)c * 16;
        uint32_t ad = aDst + (uint32_t)(c * ABUF_B);
        uint32_t bd = bDst + (uint32_t)(c * BBUF_B);
        cpa16(ad, ahp + k0);
        cpa16(ad + A_PLANE_B, alp + k0);
        cpa16(bd, bhp + k0 * H);
        cpa16(bd + B_PLANE_B, blp + k0 * H);
    }
    cpa_commit();
    cpa_wait0();
    __syncthreads();

    const int NT = H / 16;
    for (int t = 0; t < NT; t += 2) {
        if (t + 2 < NT) {
#pragma unroll
            for (int d = 2; d < 4; d++) {
                int c = t + d;
                size_t k0 = (size_t)c * 16;
                uint32_t ad = aDst + (uint32_t)((c & 3) * ABUF_B);
                uint32_t bd = bDst + (uint32_t)((c & 3) * BBUF_B);
                cpa16(ad, ahp + k0);
                cpa16(ad + A_PLANE_B, alp + k0);
                cpa16(bd, bhp + k0 * H);
                cpa16(bd + B_PLANE_B, blp + k0 * H);
            }
            cpa_commit();
        }
        mma_chunk(aBase + (uint32_t)((t & 3) * ABUF_B),
                  bBase + (uint32_t)((t & 3) * BBUF_B), acc);
        mma_chunk(aBase + (uint32_t)(((t + 1) & 3) * ABUF_B),
                  bBase + (uint32_t)(((t + 1) & 3) * BBUF_B), acc);
        if (t + 2 < NT) {
            cpa_wait0();
            __syncthreads();
        }
    }

#pragma unroll
    for (int mt = 0; mt < 4; mt++) {
        size_t r0 = rowBase + warp_m * 64 + mt * 16 + (lane >> 2);
#pragma unroll
        for (int nt = 0; nt < 4; nt++) {
            int col = colBase + warp_n * 32 + nt * 8 + (lane & 3) * 2;
            float v0 = acc[mt][nt][0], v1 = acc[mt][nt][1];
            float v2 = acc[mt][nt][2], v3 = acc[mt][nt][3];
            if (bias) {
                float2 bb = *(const float2*)&bias[col];
                v0 += bb.x; v1 += bb.y; v2 += bb.x; v3 += bb.y;
            }
            float2 o0; o0.x = v0; o0.y = v1;
            float2 o1; o1.x = v2; o1.y = v3;
            *(float2*)&Cc[r0 * H + col] = o0;
            *(float2*)&Cc[(r0 + 8) * H + col] = o1;
        }
    }
}

// ---------------- fused per-fragment stats + final reduction --------------------
__global__ void k_frag(float* __restrict__ out) {
    extern __shared__ float rows[];   // MAXM * ROWSTRIDE floats
    __shared__ float inv[MAXM];
    __shared__ float rd[32];
    __shared__ int s_last;
    int f = blockIdx.x, t = threadIdx.x;
    int cnt = g_counts[f], off = g_offsets[f];
    int w = t >> 5, lane = t & 31;
    int half = lane >> 4, hl = lane & 15;
    float sacc = 0.f, dacc = 0.f, svar = 0.f, vvar = 0.f;

    if (cnt >= 2 && cnt <= MAXM) {
        for (int feat = 0; feat < 4; feat++) {
            for (int r = 0; r < cnt; r++) {
                int nd = g_nodes[off + r];
                const float* src = (feat == 0) ? g_si + (size_t)nd * H
                                               : g_vi + ((size_t)nd * 3 + (feat - 1)) * H;
                rows[r * ROWSTRIDE + t] = src[t];
            }
            __syncthreads();
            {
                float s1 = 0.f;
                for (int r = 0; r < cnt; r++) s1 += rows[r * ROWSTRIDE + t];
                float mean = s1 / (float)cnt;
                float v = 0.f;
                for (int r = 0; r < cnt; r++) {
                    float d = rows[r * ROWSTRIDE + t] - mean;
                    v = fmaf(d, d, v);
                }
                if (feat == 0) svar += v; else vvar += v;
            }
            for (int r = w; r < cnt; r += 8) {
                const float* rp = rows + r * ROWSTRIDE;
                float s = 0.f;
                for (int j = lane; j < H; j += 32) { float x = rp[j]; s = fmaf(x, x, s); }
                for (int o = 16; o; o >>= 1) s += __shfl_xor_sync(0xffffffffu, s, o);
                if (lane == 0) inv[r] = 1.f / fmaxf(sqrtf(s), 1e-12f);
            }
            __syncthreads();
            float acc = 0.f;
            for (int a0 = w * 2; a0 < cnt - 1; a0 += 16) {
                int a = a0 + half;
                if (a <= cnt - 2) {
                    const float4* ra = (const float4*)(rows + a * ROWSTRIDE);
                    float ia = inv[a];
                    for (int b = a + 1 + hl; b < cnt; b += 16) {
                        const float4* rb = (const float4*)(rows + b * ROWSTRIDE);
                        float dot = 0.f;
#pragma unroll 8
                        for (int k = 0; k < H / 4; k++) {
                            float4 u = ra[k], q = rb[k];
                            dot = fmaf(u.x, q.x, dot);
                            dot = fmaf(u.y, q.y, dot);
                            dot = fmaf(u.z, q.z, dot);
                            dot = fmaf(u.w, q.w, dot);
                        }
                        float e = fmaf(dot * ia, inv[b], -C_SIM);
                        acc = fmaf(e, e, acc);
                    }
                }
            }
            if (feat == 0) sacc = acc; else dacc += acc;
            __syncthreads();
        }
    } else if (cnt > MAXM) {
        // fallback (never expected): gmem-direct
        float* mean = rows;
        float as = 0.f, a0m = 0.f, a1m = 0.f, a2m = 0.f;
        for (int m = 0; m < cnt; m++) {
            int nd = g_nodes[off + m];
            as += g_si[(size_t)nd * H + t];
            const float* vv = g_vi + (size_t)nd * 3 * H;
            a0m += vv[t]; a1m += vv[H + t]; a2m += vv[2 * H + t];
        }
        float invn = 1.f / (float)cnt;
        mean[t] = as * invn; mean[256 + t] = a0m * invn;
        mean[512 + t] = a1m * invn; mean[768 + t] = a2m * invn;
        __syncthreads();
        for (int m = 0; m < cnt; m++) {
            int nd = g_nodes[off + m];
            float d0 = g_si[(size_t)nd * H + t] - mean[t];
            svar = fmaf(d0, d0, svar);
            const float* vv = g_vi + (size_t)nd * 3 * H;
            float d1 = vv[t] - mean[256 + t];
            float d2 = vv[H + t] - mean[512 + t];
            float d3 = vv[2 * H + t] - mean[768 + t];
            vvar = fmaf(d1, d1, vvar); vvar = fmaf(d2, d2, vvar); vvar = fmaf(d3, d3, vvar);
        }
        for (int feat = 0; feat < 4; feat++) {
            float acc = 0.f;
            for (int a = w; a < cnt - 1; a += 8) {
                int na = g_nodes[off + a];
                const float* ra = (feat == 0) ? g_si + (size_t)na * H
                                              : g_vi + ((size_t)na * 3 + (feat - 1)) * H;
                for (int b = a + 1 + lane; b < cnt; b += 32) {
                    int nb = g_nodes[off + b];
                    const float* rb = (feat == 0) ? g_si + (size_t)nb * H
                                                  : g_vi + ((size_t)nb * 3 + (feat - 1)) * H;
                    float dot = 0.f, sa = 0.f, sb = 0.f;
                    for (int k = 0; k < H; k++) {
                        float x = ra[k], y = rb[k];
                        dot = fmaf(x, y, dot);
                        sa = fmaf(x, x, sa);
                        sb = fmaf(y, y, sb);
                    }
                    float e = dot / (fmaxf(sqrtf(sa), 1e-12f) * fmaxf(sqrtf(sb), 1e-12f)) - C_SIM;
                    acc = fmaf(e, e, acc);
                }
            }
            if (feat == 0) sacc = acc; else dacc += acc;
        }
    }

    for (int o = 16; o; o >>= 1) {
        svar += __shfl_xor_sync(0xffffffffu, svar, o);
        vvar += __shfl_xor_sync(0xffffffffu, vvar, o);
        sacc += __shfl_xor_sync(0xffffffffu, sacc, o);
        dacc += __shfl_xor_sync(0xffffffffu, dacc, o);
    }
    if (lane == 0) { rd[w] = svar; rd[8 + w] = vvar; rd[16 + w] = sacc; rd[24 + w] = dacc; }
    __syncthreads();
    if (t == 0) {
        float a = 0.f, b = 0.f, c = 0.f, d = 0.f;
        for (int i = 0; i < 8; i++) { a += rd[i]; b += rd[8 + i]; c += rd[16 + i]; d += rd[24 + i]; }
        g_svar[f] = a; g_vvar[f] = b; g_ssim[f] = c; g_dir[f] = d;
        __threadfence();
        int old = atomicAdd(&g_done, 1);
        s_last = (old == NF - 1) ? 1 : 0;
    }
    __syncthreads();

    // last block performs the final reduction (fused k_final)
    if (s_last) {
        __threadfence();
        float n  = (float)g_counts[t];
        float pc = n * (n - 1.f) * 0.5f;
        float ns  = fmaxf(n, 1.f);
        float pcs = fmaxf(pc, 1.f);
        float sl = g_svar[t] / ns + g_ssim[t] / pcs;
        float vl = g_vvar[t] / ns + g_dir[t] / (3.f * pcs);
        float fl = 0.5f * sl + 0.5f * vl;
        float val  = (pc > 0.f) ? fl : 0.f;
        float cntv = (pc > 0.f) ? 1.f : 0.f;
        for (int o = 16; o; o >>= 1) {
            val  += __shfl_xor_sync(0xffffffffu, val, o);
            cntv += __shfl_xor_sync(0xffffffffu, cntv, o);
        }
        __syncthreads();   // rd reuse
        if (lane == 0) { rd[w] = val; rd[8 + w] = cntv; }
        __syncthreads();
        if (t == 0) {
            float tot = 0.f, tc = 0.f;
            for (int i = 0; i < 8; i++) { tot += rd[i]; tc += rd[8 + i]; }
            out[0] = (tc > 0.f) ? tot / fmaxf(tc, 1.f) : 0.f;
            g_done = 0;   // reset for next graph replay
        }
    }
}

// ---------------- launch ----------------
extern "C" void kernel_launch(void* const* d_in, const int* in_sizes, int n_in,
                              void* d_out, int out_size)
{
    const float* ss = (const float*)d_in[0];
    const float* sl = (const float*)d_in[1];
    const float* vs = (const float*)d_in[2];
    const float* vl = (const float*)d_in[3];
    const float* W1 = (const float*)d_in[4];
    const float* b1 = (const float*)d_in[5];
    const float* W2 = (const float*)d_in[6];
    const float* b2 = (const float*)d_in[7];
    const float* V1 = (const float*)d_in[8];
    const float* V2 = (const float*)d_in[9];
    const int*   frag = (const int*)d_in[10];
    float* out = (float*)d_out;

    void *psi, *pvi, *pwh, *pwl, *ptsh, *ptsl, *ptvh, *ptvl;
    cudaGetSymbolAddress(&psi, g_si);
    cudaGetSymbolAddress(&pvi, g_vi);
    cudaGetSymbolAddress(&pwh, g_wh);
    cudaGetSymbolAddress(&pwl, g_wl);
    cudaGetSymbolAddress(&ptsh, g_tsh);
    cudaGetSymbolAddress(&ptsl, g_tsl);
    cudaGetSymbolAddress(&ptvh, g_tvh);
    cudaGetSymbolAddress(&ptvl, g_tvl);
    const uint16_t* wh = (const uint16_t*)pwh;
    const uint16_t* wl = (const uint16_t*)pwl;
    uint16_t* tsh = (uint16_t*)ptsh;
    uint16_t* tsl = (uint16_t*)ptsl;
    uint16_t* tvh = (uint16_t*)ptvh;
    uint16_t* tvl = (uint16_t*)ptvl;

    k_setup<<<257, 256>>>(frag, W1, W2, V1, V2);

    cudaFuncSetAttribute(k_gemm1, cudaFuncAttributeMaxDynamicSharedMemorySize, G_SMEM);
    cudaFuncSetAttribute(k_gemm2, cudaFuncAttributeMaxDynamicSharedMemorySize, G_SMEM);

    dim3 g(2, NSCALAR_BLOCKS + 192);
    k_gemm1<<<g, 256, G_SMEM>>>(ss, sl, vs, vl,
                                wh + 0 * 65536, wl + 0 * 65536,
                                wh + 2 * 65536, wl + 2 * 65536,
                                b1, tsh, tsl, tvh, tvl);
    k_gemm2<<<g, 256, G_SMEM>>>(tsh, tsl, tvh, tvl,
                                wh + 1 * 65536, wl + 1 * 65536,
                                wh + 3 * 65536, wl + 3 * 65536,
                                b2, (float*)psi, (float*)pvi);

    cudaFuncSetAttribute(k_frag, cudaFuncAttributeMaxDynamicSharedMemorySize,
                         MAXM * ROWSTRIDE * 4);
    k_frag<<<NF, 256, MAXM * ROWSTRIDE * 4>>>(out);
}

// round 12
// speedup vs baseline: 1.6350x; 1.2809x over previous
#include <cuda_runtime.h>
#include <cuda_bf16.h>
#include <math.h>
#include <stdint.h>

#define N_NODES 8192
#define H 256
#define NF 256
#define R_MIX 0.3f
#define C_SIM 0.8f
#define LOG2F_ 0.69314718055994530942f
#define MAXM 64

// ---------------- scratch (static device globals) ----------------
__device__ uint16_t g_tsh[ 8192 * 256], g_tsl[ 8192 * 256];
__device__ uint16_t g_tvh[24576 * 256], g_tvl[24576 * 256];
__device__ float g_si[ 8192 * 256];
__device__ float g_vi[24576 * 256];
__device__ uint16_t g_wh[4][65536];
__device__ uint16_t g_wl[4][65536];
__device__ int   g_counts [NF];
__device__ int   g_offsets[NF + 1];
__device__ int   g_nodes  [N_NODES];
__device__ float g_svar[NF], g_vvar[NF], g_ssim[NF], g_dir[NF];
__device__ int   g_done;

__device__ __forceinline__ float sspf(float x) {
    float ax = fabsf(x);
    return fmaxf(x, 0.f) + log1pf(__expf(-ax)) - LOG2F_;
}
__device__ __forceinline__ uint32_t pk2(float a, float b) {
    __nv_bfloat162 t = __floats2bfloat162_rn(a, b);
    return *reinterpret_cast<uint32_t*>(&t);
}
__device__ __forceinline__ float bres(float x) {
    __nv_bfloat16 h = __float2bfloat16(x);
    return x - __bfloat162float(h);
}

// ---------------- mma/ldmatrix/cp.async wrappers (sm_103-safe) ----------------
__device__ __forceinline__ void ldsm4(uint32_t addr, uint32_t* r) {
    asm volatile("ldmatrix.sync.aligned.m8n8.x4.shared.b16 {%0,%1,%2,%3}, [%4];"
                 : "=r"(r[0]), "=r"(r[1]), "=r"(r[2]), "=r"(r[3]) : "r"(addr));
}
__device__ __forceinline__ void ldsm4t(uint32_t addr, uint32_t* r) {
    asm volatile("ldmatrix.sync.aligned.m8n8.x4.trans.shared.b16 {%0,%1,%2,%3}, [%4];"
                 : "=r"(r[0]), "=r"(r[1]), "=r"(r[2]), "=r"(r[3]) : "r"(addr));
}
__device__ __forceinline__ void mma16816(float* c, const uint32_t* a, uint32_t b0, uint32_t b1) {
    asm volatile(
        "mma.sync.aligned.m16n8k16.row.col.f32.bf16.bf16.f32 "
        "{%0,%1,%2,%3},{%4,%5,%6,%7},{%8,%9},{%0,%1,%2,%3};"
        : "+f"(c[0]), "+f"(c[1]), "+f"(c[2]), "+f"(c[3])
        : "r"(a[0]), "r"(a[1]), "r"(a[2]), "r"(a[3]), "r"(b0), "r"(b1));
}
__device__ __forceinline__ void cpa16(uint32_t dst, const void* src) {
    asm volatile("cp.async.cg.shared.global [%0], [%1], 16;" :: "r"(dst), "l"(src) : "memory");
}
__device__ __forceinline__ void cpa_commit() {
    asm volatile("cp.async.commit_group;" ::: "memory");
}
__device__ __forceinline__ void cpa_wait0() {
    asm volatile("cp.async.wait_group 0;" ::: "memory");
}

// ---------------- fused setup: block 0 = counting sort, blocks 1..256 = prepw ------
__global__ void k_setup(const int* __restrict__ frag,
                        const float* __restrict__ W1, const float* __restrict__ W2,
                        const float* __restrict__ V1, const float* __restrict__ V2)
{
    if (blockIdx.x == 0) {
        __shared__ int s_sc[8 * 256];
        __shared__ int s_off[256];
        __shared__ int s_tmp[256];
        int t = threadIdx.x, w = t >> 5, l = t & 31;

        for (int j = t; j < 2048; j += 256) s_sc[j] = 0;
        __syncthreads();

        int fv[32], lp[32];
#pragma unroll
        for (int c = 0; c < 32; c++) fv[c] = frag[(w * 32 + c) * 32 + l];
        for (int c = 0; c < 32; c++) {
            int f = fv[c];
            bool ok = (f >= 0 && f < NF);
            unsigned mask = __match_any_sync(0xffffffffu, f);
            int rank = __popc(mask & ((1u << l) - 1u));
            int before = ok ? s_sc[w * 256 + f] : 0;
            lp[c] = before + rank;
            __syncwarp();
            if (ok && rank == 0) s_sc[w * 256 + f] = before + __popc(mask);
            __syncwarp();
        }
        __syncthreads();

        {
            int run = 0;
#pragma unroll
            for (int w2 = 0; w2 < 8; w2++) {
                int v = s_sc[w2 * 256 + t];
                s_sc[w2 * 256 + t] = run;
                run += v;
            }
            g_counts[t] = run;
            s_tmp[t] = run;
            __syncthreads();
            for (int d = 1; d < 256; d <<= 1) {
                int u = (t >= d) ? s_tmp[t - d] : 0;
                __syncthreads();
                s_tmp[t] += u;
                __syncthreads();
            }
            s_off[t] = s_tmp[t] - run;
            g_offsets[t] = s_off[t];
            if (t == 255) g_offsets[256] = s_tmp[255];
        }
        __syncthreads();

        for (int c = 0; c < 32; c++) {
            int f = fv[c];
            if (f >= 0 && f < NF) {
                int pos = s_off[f] + s_sc[w * 256 + f] + lp[c];
                if (pos >= 0 && pos < N_NODES)
                    g_nodes[pos] = (w * 32 + c) * 32 + l;
            }
        }
    } else {
        int bb = blockIdx.x - 1;
        int m = bb >> 6;
        const float* src = (m == 0) ? W1 : (m == 1) ? W2 : (m == 2) ? V1 : V2;
        int i0 = ((bb & 63) * 256 + threadIdx.x) * 4;
        float4 v = *(const float4*)(src + i0);
        uint16_t* oh = g_wh[m];
        uint16_t* ol = g_wl[m];
        *(uint32_t*)&oh[i0]     = pk2(v.x, v.y);
        *(uint32_t*)&oh[i0 + 2] = pk2(v.z, v.w);
        *(uint32_t*)&ol[i0]     = pk2(bres(v.x), bres(v.y));
        *(uint32_t*)&ol[i0 + 2] = pk2(bres(v.z), bres(v.w));
    }
}

// ------------- shared GEMM pieces (unchanged, proven) -------------
#define AROW 24
#define BROW 136
#define A_HL (128 * AROW)
#define B_HL (16 * BROW)
#define A_PLANE_B (A_HL * 2)
#define B_PLANE_B (B_HL * 2)
#define ABUF_B (2 * A_PLANE_B)
#define BBUF_B (2 * B_PLANE_B)
#define G_SMEM (4 * ABUF_B + 4 * BBUF_B)
#define NSCALAR_BLOCKS 64

__device__ __forceinline__ void mma_chunk(uint32_t aOff, uint32_t bOff, float acc[4][4][4]) {
    uint32_t ah[4][4], bh[2][4], tmp[2][4], al4[4];
#pragma unroll
    for (int mt = 0; mt < 4; mt++) ldsm4(aOff + mt * (16 * AROW * 2), ah[mt]);
#pragma unroll
    for (int st = 0; st < 2; st++) ldsm4t(bOff + st * 32, bh[st]);
#pragma unroll
    for (int mt = 0; mt < 4; mt++)
#pragma unroll
        for (int nt = 0; nt < 4; nt++)
            mma16816(acc[mt][nt], ah[mt], bh[nt >> 1][(nt & 1) * 2],
                     bh[nt >> 1][(nt & 1) * 2 + 1]);
#pragma unroll
    for (int st = 0; st < 2; st++) ldsm4t(bOff + B_PLANE_B + st * 32, tmp[st]);
#pragma unroll
    for (int mt = 0; mt < 4; mt++)
#pragma unroll
        for (int nt = 0; nt < 4; nt++)
            mma16816(acc[mt][nt], ah[mt], tmp[nt >> 1][(nt & 1) * 2],
                     tmp[nt >> 1][(nt & 1) * 2 + 1]);
#pragma unroll
    for (int mt = 0; mt < 4; mt++) {
        ldsm4(aOff + A_PLANE_B + mt * (16 * AROW * 2), al4);
#pragma unroll
        for (int nt = 0; nt < 4; nt++)
            mma16816(acc[mt][nt], al4, bh[nt >> 1][(nt & 1) * 2],
                     bh[nt >> 1][(nt & 1) * 2 + 1]);
    }
}

__device__ __forceinline__ void gloadA(const float* __restrict__ a1p,
                                       const float* __restrict__ a2p,
                                       int k0, float4& x, float4& y) {
    x = *(const float4*)(a1p + k0);
    y = *(const float4*)(a1p + k0 + 4);
    float4 u = *(const float4*)(a2p + k0);
    float4 v = *(const float4*)(a2p + k0 + 4);
    const float w = 1.f - R_MIX;
    x.x = fmaf(x.x, R_MIX, u.x * w); x.y = fmaf(x.y, R_MIX, u.y * w);
    x.z = fmaf(x.z, R_MIX, u.z * w); x.w = fmaf(x.w, R_MIX, u.w * w);
    y.x = fmaf(y.x, R_MIX, v.x * w); y.y = fmaf(y.y, R_MIX, v.y * w);
    y.z = fmaf(y.z, R_MIX, v.z * w); y.w = fmaf(y.w, R_MIX, v.w * w);
}

__device__ __forceinline__ void cvt_store8(uint16_t* hi_p, uint16_t* lo_p,
                                           const float4& x, const float4& y) {
    uint4 hv, lv;
    hv.x = pk2(x.x, x.y); hv.y = pk2(x.z, x.w);
    hv.z = pk2(y.x, y.y); hv.w = pk2(y.z, y.w);
    lv.x = pk2(bres(x.x), bres(x.y)); lv.y = pk2(bres(x.z), bres(x.w));
    lv.z = pk2(bres(y.x), bres(y.y)); lv.w = pk2(bres(y.z), bres(y.w));
    *reinterpret_cast<uint4*>(hi_p) = hv;
    *reinterpret_cast<uint4*>(lo_p) = lv;
}

// ---------------- layer-1 GEMM (unchanged from Round 11) ----------------
__global__ __launch_bounds__(256, 2)
void k_gemm1(const float* __restrict__ A1s, const float* __restrict__ A2s,
             const float* __restrict__ A1v, const float* __restrict__ A2v,
             const uint16_t* __restrict__ Bhs, const uint16_t* __restrict__ Bls,
             const uint16_t* __restrict__ Bhv, const uint16_t* __restrict__ Blv,
             const float* __restrict__ biass,
             uint16_t* __restrict__ Csh, uint16_t* __restrict__ Csl,
             uint16_t* __restrict__ Cvh, uint16_t* __restrict__ Cvl)
{
    extern __shared__ __align__(16) uint16_t dsm[];
    const int tid = threadIdx.x, lane = tid & 31, wid = tid >> 5;
    const int warp_m = wid >> 2, warp_n = wid & 3;
    const bool isS = (blockIdx.y < NSCALAR_BLOCKS);
    const size_t rowBase = (size_t)(isS ? blockIdx.y : blockIdx.y - NSCALAR_BLOCKS) * 128;
    const int colBase = blockIdx.x * 128;
    const float* A1 = isS ? A1s : A1v;
    const float* A2 = isS ? A2s : A2v;
    const uint16_t* Bh = isS ? Bhs : Bhv;
    const uint16_t* Bl = isS ? Bls : Blv;
    const float* bias = isS ? biass : nullptr;
    uint16_t* Ch = isS ? Csh : Cvh;
    uint16_t* Cl = isS ? Csl : Cvl;

    const int am = tid >> 1, ak = (tid & 1) * 8;
    const int bk = tid >> 4, bn = (tid & 15) * 8;

    const float* a1p = A1 + (rowBase + am) * H + ak;
    const float* a2p = A2 + (rowBase + am) * H + ak;
    const uint16_t* bhp = Bh + (size_t)bk * H + colBase + bn;
    const uint16_t* blp = Bl + (size_t)bk * H + colBase + bn;

    uint32_t sA0 = (uint32_t)__cvta_generic_to_shared(dsm);
    uint32_t sB0 = sA0 + 4 * ABUF_B;
    uint32_t bDst = sB0 + (uint32_t)((bk * BROW + bn) * 2);
    uint16_t* aStore = dsm + (am * AROW + ak);

    const int a_row0 = warp_m * 64 + (lane & 7) + ((lane >> 3) & 1) * 8;
    const int a_kgrp = lane >> 4;
    uint32_t aBase = sA0 + (uint32_t)((a_row0 * AROW + a_kgrp * 8) * 2);
    const int b_krow = (lane & 7) + ((lane >> 3) & 1) * 8;
    const int b_ngrp = lane >> 4;
    uint32_t bBase = sB0 + (uint32_t)((b_krow * BROW + warp_n * 32 + b_ngrp * 8) * 2);

    float acc[4][4][4];
#pragma unroll
    for (int i = 0; i < 4; i++)
#pragma unroll
        for (int j = 0; j < 4; j++)
#pragma unroll
            for (int q = 0; q < 4; q++) acc[i][j][q] = 0.f;

    cpa16(bDst, bhp);
    cpa16(bDst + B_PLANE_B, blp);
    cpa16(bDst + BBUF_B, bhp + (size_t)16 * H);
    cpa16(bDst + BBUF_B + B_PLANE_B, blp + (size_t)16 * H);
    cpa_commit();
    {
        float4 ax, ay;
        gloadA(a1p, a2p, 0, ax, ay);
        cvt_store8(aStore, aStore + A_HL, ax, ay);
        gloadA(a1p, a2p, 16, ax, ay);
        cvt_store8(aStore + ABUF_B / 2, aStore + ABUF_B / 2 + A_HL, ax, ay);
    }
    cpa_wait0();
    __syncthreads();

    const int NT = H / 16;
    for (int t = 0; t < NT; t += 2) {
        if (t + 2 < NT) {
            int c2 = t + 2, c3 = t + 3;
            size_t k2 = (size_t)c2 * 16, k3 = (size_t)c3 * 16;
            uint32_t bd2 = bDst + (uint32_t)((c2 & 3) * BBUF_B);
            uint32_t bd3 = bDst + (uint32_t)((c3 & 3) * BBUF_B);
            cpa16(bd2, bhp + k2 * H);
            cpa16(bd2 + B_PLANE_B, blp + k2 * H);
            cpa16(bd3, bhp + k3 * H);
            cpa16(bd3 + B_PLANE_B, blp + k3 * H);
            cpa_commit();
            float4 ax, ay;
            gloadA(a1p, a2p, (int)k2, ax, ay);
            cvt_store8(aStore + (c2 & 3) * (ABUF_B / 2),
                       aStore + (c2 & 3) * (ABUF_B / 2) + A_HL, ax, ay);
            gloadA(a1p, a2p, (int)k3, ax, ay);
            cvt_store8(aStore + (c3 & 3) * (ABUF_B / 2),
                       aStore + (c3 & 3) * (ABUF_B / 2) + A_HL, ax, ay);
        }
        mma_chunk(aBase + (uint32_t)((t & 3) * ABUF_B),
                  bBase + (uint32_t)((t & 3) * BBUF_B), acc);
        mma_chunk(aBase + (uint32_t)(((t + 1) & 3) * ABUF_B),
                  bBase + (uint32_t)(((t + 1) & 3) * BBUF_B), acc);
        if (t + 2 < NT) {
            cpa_wait0();
            __syncthreads();
        }
    }

#pragma unroll
    for (int mt = 0; mt < 4; mt++) {
        size_t r0 = rowBase + warp_m * 64 + mt * 16 + (lane >> 2);
#pragma unroll
        for (int nt = 0; nt < 4; nt++) {
            int col = colBase + warp_n * 32 + nt * 8 + (lane & 3) * 2;
            float v0 = acc[mt][nt][0], v1 = acc[mt][nt][1];
            float v2 = acc[mt][nt][2], v3 = acc[mt][nt][3];
            if (bias) {
                float2 bb = *(const float2*)&bias[col];
                v0 += bb.x; v1 += bb.y; v2 += bb.x; v3 += bb.y;
            }
            v0 = sspf(v0); v1 = sspf(v1); v2 = sspf(v2); v3 = sspf(v3);
            *(uint32_t*)&Ch[r0 * H + col]       = pk2(v0, v1);
            *(uint32_t*)&Cl[r0 * H + col]       = pk2(bres(v0), bres(v1));
            *(uint32_t*)&Ch[(r0 + 8) * H + col] = pk2(v2, v3);
            *(uint32_t*)&Cl[(r0 + 8) * H + col] = pk2(bres(v2), bres(v3));
        }
    }
}

// ---------------- layer-2 GEMM (unchanged from Round 11) ----------------
__global__ __launch_bounds__(256, 2)
void k_gemm2(const uint16_t* __restrict__ Ahs, const uint16_t* __restrict__ Als,
             const uint16_t* __restrict__ Ahv, const uint16_t* __restrict__ Alv,
             const uint16_t* __restrict__ Bhs, const uint16_t* __restrict__ Bls,
             const uint16_t* __restrict__ Bhv, const uint16_t* __restrict__ Blv,
             const float* __restrict__ biass,
             float* __restrict__ Cs, float* __restrict__ Cv)
{
    extern __shared__ __align__(16) uint16_t dsm[];
    const int tid = threadIdx.x, lane = tid & 31, wid = tid >> 5;
    const int warp_m = wid >> 2, warp_n = wid & 3;
    const bool isS = (blockIdx.y < NSCALAR_BLOCKS);
    const size_t rowBase = (size_t)(isS ? blockIdx.y : blockIdx.y - NSCALAR_BLOCKS) * 128;
    const int colBase = blockIdx.x * 128;
    const uint16_t* Ah = isS ? Ahs : Ahv;
    const uint16_t* Al = isS ? Als : Alv;
    const uint16_t* Bh = isS ? Bhs : Bhv;
    const uint16_t* Bl = isS ? Bls : Blv;
    const float* bias = isS ? biass : nullptr;
    float* Cc = isS ? Cs : Cv;

    const int am = tid >> 1, ak = (tid & 1) * 8;
    const int bk = tid >> 4, bn = (tid & 15) * 8;

    const uint16_t* ahp = Ah + (rowBase + am) * H + ak;
    const uint16_t* alp = Al + (rowBase + am) * H + ak;
    const uint16_t* bhp = Bh + (size_t)bk * H + colBase + bn;
    const uint16_t* blp = Bl + (size_t)bk * H + colBase + bn;

    uint32_t sA0 = (uint32_t)__cvta_generic_to_shared(dsm);
    uint32_t sB0 = sA0 + 4 * ABUF_B;
    uint32_t aDst = sA0 + (uint32_t)((am * AROW + ak) * 2);
    uint32_t bDst = sB0 + (uint32_t)((bk * BROW + bn) * 2);

    const int a_row0 = warp_m * 64 + (lane & 7) + ((lane >> 3) & 1) * 8;
    const int a_kgrp = lane >> 4;
    uint32_t aBase = sA0 + (uint32_t)((a_row0 * AROW + a_kgrp * 8) * 2);
    const int b_krow = (lane & 7) + ((lane >> 3) & 1) * 8;
    const int b_ngrp = lane >> 4;
    uint32_t bBase = sB0 + (uint32_t)((b_krow * BROW + warp_n * 32 + b_ngrp * 8) * 2);

    float acc[4][4][4];
#pragma unroll
    for (int i = 0; i < 4; i++)
#pragma unroll
        for (int j = 0; j < 4; j++)
#pragma unroll
            for (int q = 0; q < 4; q++) acc[i][j][q] = 0.f;

#pragma unroll
    for (int c = 0; c < 2; c++) {
        size_t k0 = (size_t)c * 16;
        uint32_t ad = aDst + (uint32_t)(c * ABUF_B);
        uint32_t bd = bDst + (uint32_t)(c * BBUF_B);
        cpa16(ad, ahp + k0);
        cpa16(ad + A_PLANE_B, alp + k0);
        cpa16(bd, bhp + k0 * H);
        cpa16(bd + B_PLANE_B, blp + k0 * H);
    }
    cpa_commit();
    cpa_wait0();
    __syncthreads();

    const int NT = H / 16;
    for (int t = 0; t < NT; t += 2) {
        if (t + 2 < NT) {
#pragma unroll
            for (int d = 2; d < 4; d++) {
                int c = t + d;
                size_t k0 = (size_t)c * 16;
                uint32_t ad = aDst + (uint32_t)((c & 3) * ABUF_B);
                uint32_t bd = bDst + (uint32_t)((c & 3) * BBUF_B);
                cpa16(ad, ahp + k0);
                cpa16(ad + A_PLANE_B, alp + k0);
                cpa16(bd, bhp + k0 * H);
                cpa16(bd + B_PLANE_B, blp + k0 * H);
            }
            cpa_commit();
        }
        mma_chunk(aBase + (uint32_t)((t & 3) * ABUF_B),
                  bBase + (uint32_t)((t & 3) * BBUF_B), acc);
        mma_chunk(aBase + (uint32_t)(((t + 1) & 3) * ABUF_B),
                  bBase + (uint32_t)(((t + 1) & 3) * BBUF_B), acc);
        if (t + 2 < NT) {
            cpa_wait0();
            __syncthreads();
        }
    }

#pragma unroll
    for (int mt = 0; mt < 4; mt++) {
        size_t r0 = rowBase + warp_m * 64 + mt * 16 + (lane >> 2);
#pragma unroll
        for (int nt = 0; nt < 4; nt++) {
            int col = colBase + warp_n * 32 + nt * 8 + (lane & 3) * 2;
            float v0 = acc[mt][nt][0], v1 = acc[mt][nt][1];
            float v2 = acc[mt][nt][2], v3 = acc[mt][nt][3];
            if (bias) {
                float2 bb = *(const float2*)&bias[col];
                v0 += bb.x; v1 += bb.y; v2 += bb.x; v3 += bb.y;
            }
            float2 o0; o0.x = v0; o0.y = v1;
            float2 o1; o1.x = v2; o1.y = v3;
            *(float2*)&Cc[r0 * H + col] = o0;
            *(float2*)&Cc[(r0 + 8) * H + col] = o1;
        }
    }
}

// ---------------- per-fragment stats via tensor-core Gram matrix -----------------
// Block per fragment. G = X X^T (3-term bf16 split). Diagonal gives norms;
// cos_ab = G_ab * rsqrt(G_aa * G_bb). Col var via one-pass sum/sumsq from gmem.
#define ZROW 72                   // halfword row stride in chunk (conflict-free ldsm)
#define ZPLANE (64 * ZROW)

__global__ void k_frag(float* __restrict__ out) {
    __shared__ __align__(16) uint16_t zh[ZPLANE];
    __shared__ __align__(16) uint16_t zl[ZPLANE];
    __shared__ float sdiag[64];
    __shared__ float rd[32];
    __shared__ int s_last;
    int f = blockIdx.x, t = threadIdx.x;
    int cnt = g_counts[f], off = g_offsets[f];
    int wid = t >> 5, lane = t & 31;
    float svar = 0.f, vvar = 0.f, serr = 0.f, derr = 0.f;

    uint32_t zh0 = (uint32_t)__cvta_generic_to_shared(zh);
    uint32_t zl0 = (uint32_t)__cvta_generic_to_shared(zl);

    if (cnt >= 2 && cnt <= MAXM) {
        const int Mt = (cnt + 15) >> 4;   // 1..4 tiles of 16
        // assign upper-triangular 16x16 tiles to warps (<=2 per warp)
        int tm[2] = {-1, -1}, tn[2] = {-1, -1};
        {
            int idx = 0;
            for (int mt = 0; mt < Mt; mt++)
                for (int nt = mt; nt < Mt; nt++) {
                    if ((idx & 7) == wid) {
                        int s = idx >> 3;
                        if (s < 2) { tm[s] = mt; tn[s] = nt; }
                    }
                    idx++;
                }
        }
        // loader geometry: row = t>>2, 16 k-floats at (t&3)*16
        const int lrow = t >> 2;
        const int lkq = (t & 3) * 16;
        int lnd = (lrow < cnt) ? g_nodes[off + lrow] : -1;

        // ldsm lane bases (halfword offsets added later per tile/ks)
        const int fr = (lane & 7) + ((lane >> 3) & 1) * 8;
        const int fk = (lane >> 4) * 8;

        for (int feat = 0; feat < 4; feat++) {
            // ---- column one-pass mean/var (thread t = column t) ----
            {
                float s1 = 0.f, s2 = 0.f;
                for (int r = 0; r < cnt; r++) {
                    int nd = g_nodes[off + r];
                    const float* src = (feat == 0) ? g_si + (size_t)nd * H
                                                   : g_vi + ((size_t)nd * 3 + (feat - 1)) * H;
                    float x = src[t];
                    s1 += x;
                    s2 = fmaf(x, x, s2);
                }
                float v = s2 - s1 * s1 / (float)cnt;
                if (feat == 0) svar += v; else vvar += v;
            }

            // ---- Gram: G = X X^T over 4 k-chunks of 64 ----
            float acc[2][2][4];
#pragma unroll
            for (int a = 0; a < 2; a++)
#pragma unroll
                for (int b = 0; b < 2; b++)
#pragma unroll
                    for (int q = 0; q < 4; q++) acc[a][b][q] = 0.f;

            for (int kc = 0; kc < 4; kc++) {
                __syncthreads();   // prior mma (or err pass) done with smem
                // load+convert chunk [64 rows x 64 k] (zeros for padded rows)
                {
                    uint16_t* ph = zh + lrow * ZROW + lkq;
                    uint16_t* pl = zl + lrow * ZROW + lkq;
                    if (lnd >= 0) {
                        const float* src = (feat == 0) ? g_si + (size_t)lnd * H
                                                       : g_vi + ((size_t)lnd * 3 + (feat - 1)) * H;
                        const float4* sp = (const float4*)(src + kc * 64 + lkq);
#pragma unroll
                        for (int j = 0; j < 4; j++) {
                            float4 v4 = sp[j];
                            uint2 hv, lv;
                            hv.x = pk2(v4.x, v4.y); hv.y = pk2(v4.z, v4.w);
                            lv.x = pk2(bres(v4.x), bres(v4.y));
                            lv.y = pk2(bres(v4.z), bres(v4.w));
                            *(uint2*)(ph + j * 4) = hv;
                            *(uint2*)(pl + j * 4) = lv;
                        }
                    } else {
                        uint2 z; z.x = 0; z.y = 0;
#pragma unroll
                        for (int j = 0; j < 4; j++) {
                            *(uint2*)(ph + j * 4) = z;
                            *(uint2*)(pl + j * 4) = z;
                        }
                    }
                }
                __syncthreads();

#pragma unroll
                for (int ti = 0; ti < 2; ti++) {
                    if (tm[ti] < 0) continue;
#pragma unroll
                    for (int ks = 0; ks < 4; ks++) {
                        uint32_t aoff = (uint32_t)(((tm[ti] * 16 + fr) * ZROW + ks * 16 + fk) * 2);
                        uint32_t boff = (uint32_t)(((tn[ti] * 16 + fr) * ZROW + ks * 16 + fk) * 2);
                        uint32_t ah[4], al[4], bh[4], bl[4];
                        ldsm4(zh0 + aoff, ah);
                        ldsm4(zl0 + aoff, al);
                        ldsm4(zh0 + boff, bh);
                        ldsm4(zl0 + boff, bl);
                        // n8-tile0 = {x,z}; tile1 = {y,w}
                        mma16816(acc[ti][0], ah, bh[0], bh[2]);
                        mma16816(acc[ti][1], ah, bh[1], bh[3]);
                        mma16816(acc[ti][0], ah, bl[0], bl[2]);
                        mma16816(acc[ti][1], ah, bl[1], bl[3]);
                        mma16816(acc[ti][0], al, bh[0], bh[2]);
                        mma16816(acc[ti][1], al, bh[1], bh[3]);
                    }
                }
            }
            __syncthreads();

            // ---- diagonal -> smem ----
            {
                int r = lane >> 2, c = (lane & 3) * 2;
#pragma unroll
                for (int ti = 0; ti < 2; ti++) {
                    if (tm[ti] < 0 || tm[ti] != tn[ti]) continue;
#pragma unroll
                    for (int hh = 0; hh < 2; hh++) {
                        int nl0 = hh * 8 + c;
                        // (m=r, n=nl0/nl0+1), (m=r+8, ...)
                        if (r == nl0)     sdiag[tm[ti] * 16 + r]     = acc[ti][hh][0];
                        if (r == nl0 + 1) sdiag[tm[ti] * 16 + r]     = acc[ti][hh][1];
                        if (r + 8 == nl0)     sdiag[tm[ti] * 16 + r + 8] = acc[ti][hh][2];
                        if (r + 8 == nl0 + 1) sdiag[tm[ti] * 16 + r + 8] = acc[ti][hh][3];
                    }
                }
            }
            __syncthreads();

            // ---- pair errors ----
            {
                float err = 0.f;
                int r = lane >> 2, c = (lane & 3) * 2;
#pragma unroll
                for (int ti = 0; ti < 2; ti++) {
                    if (tm[ti] < 0) continue;
                    int mb = tm[ti] * 16, nb = tn[ti] * 16;
#pragma unroll
                    for (int hh = 0; hh < 2; hh++) {
                        int n0 = nb + hh * 8 + c;
#pragma unroll
                        for (int q = 0; q < 4; q++) {
                            int m = mb + r + (q >> 1) * 8;
                            int n = n0 + (q & 1);
                            if (n < cnt && m < n) {
                                float rs = rsqrtf(fmaxf(sdiag[m] * sdiag[n], 1e-24f));
                                float e = fmaf(acc[ti][hh][q], rs, -C_SIM);
                                err = fmaf(e, e, err);
                            }
                        }
                    }
                }
                if (feat == 0) serr = err; else derr += err;
            }
        }
    } else if (cnt > MAXM) {
        // fallback (never expected): gmem-direct, reuse zh as float scratch for means
        float* mean = (float*)zh;
        float as = 0.f, a0m = 0.f, a1m = 0.f, a2m = 0.f;
        for (int m = 0; m < cnt; m++) {
            int nd = g_nodes[off + m];
            as += g_si[(size_t)nd * H + t];
            const float* vv = g_vi + (size_t)nd * 3 * H;
            a0m += vv[t]; a1m += vv[H + t]; a2m += vv[2 * H + t];
        }
        float invn = 1.f / (float)cnt;
        mean[t] = as * invn; mean[256 + t] = a0m * invn;
        mean[512 + t] = a1m * invn; mean[768 + t] = a2m * invn;
        __syncthreads();
        for (int m = 0; m < cnt; m++) {
            int nd = g_nodes[off + m];
            float d0 = g_si[(size_t)nd * H + t] - mean[t];
            svar = fmaf(d0, d0, svar);
            const float* vv = g_vi + (size_t)nd * 3 * H;
            float d1 = vv[t] - mean[256 + t];
            float d2 = vv[H + t] - mean[512 + t];
            float d3 = vv[2 * H + t] - mean[768 + t];
            vvar = fmaf(d1, d1, vvar); vvar = fmaf(d2, d2, vvar); vvar = fmaf(d3, d3, vvar);
        }
        for (int feat = 0; feat < 4; feat++) {
            float acc = 0.f;
            for (int a = wid; a < cnt - 1; a += 8) {
                int na = g_nodes[off + a];
                const float* ra = (feat == 0) ? g_si + (size_t)na * H
                                              : g_vi + ((size_t)na * 3 + (feat - 1)) * H;
                for (int b = a + 1 + lane; b < cnt; b += 32) {
                    int nb = g_nodes[off + b];
                    const float* rb = (feat == 0) ? g_si + (size_t)nb * H
                                                  : g_vi + ((size_t)nb * 3 + (feat - 1)) * H;
                    float dot = 0.f, sa = 0.f, sb = 0.f;
                    for (int k = 0; k < H; k++) {
                        float x = ra[k], y = rb[k];
                        dot = fmaf(x, y, dot);
                        sa = fmaf(x, x, sa);
                        sb = fmaf(y, y, sb);
                    }
                    float e = dot / (fmaxf(sqrtf(sa), 1e-12f) * fmaxf(sqrtf(sb), 1e-12f)) - C_SIM;
                    acc = fmaf(e, e, acc);
                }
            }
            if (feat == 0) serr = acc; else derr += acc;
        }
    }

    for (int o = 16; o; o >>= 1) {
        svar += __shfl_xor_sync(0xffffffffu, svar, o);
        vvar += __shfl_xor_sync(0xffffffffu, vvar, o);
        serr += __shfl_xor_sync(0xffffffffu, serr, o);
        derr += __shfl_xor_sync(0xffffffffu, derr, o);
    }
    if (lane == 0) { rd[wid] = svar; rd[8 + wid] = vvar; rd[16 + wid] = serr; rd[24 + wid] = derr; }
    __syncthreads();
    if (t == 0) {
        float a = 0.f, b = 0.f, c = 0.f, d = 0.f;
        for (int i = 0; i < 8; i++) { a += rd[i]; b += rd[8 + i]; c += rd[16 + i]; d += rd[24 + i]; }
        g_svar[f] = a; g_vvar[f] = b; g_ssim[f] = c; g_dir[f] = d;
        __threadfence();
        int old = atomicAdd(&g_done, 1);
        s_last = (old == NF - 1) ? 1 : 0;
    }
    __syncthreads();

    if (s_last) {
        __threadfence();
        float n  = (float)g_counts[t];
        float pc = n * (n - 1.f) * 0.5f;
        float ns  = fmaxf(n, 1.f);
        float pcs = fmaxf(pc, 1.f);
        float sl = g_svar[t] / ns + g_ssim[t] / pcs;
        float vl = g_vvar[t] / ns + g_dir[t] / (3.f * pcs);
        float fl = 0.5f * sl + 0.5f * vl;
        float val  = (pc > 0.f) ? fl : 0.f;
        float cntv = (pc > 0.f) ? 1.f : 0.f;
        for (int o = 16; o; o >>= 1) {
            val  += __shfl_xor_sync(0xffffffffu, val, o);
            cntv += __shfl_xor_sync(0xffffffffu, cntv, o);
        }
        __syncthreads();
        if (lane == 0) { rd[wid] = val; rd[8 + wid] = cntv; }
        __syncthreads();
        if (t == 0) {
            float tot = 0.f, tc = 0.f;
            for (int i = 0; i < 8; i++) { tot += rd[i]; tc += rd[8 + i]; }
            out[0] = (tc > 0.f) ? tot / fmaxf(tc, 1.f) : 0.f;
            g_done = 0;
        }
    }
}

// ---------------- launch ----------------
extern "C" void kernel_launch(void* const* d_in, const int* in_sizes, int n_in,
                              void* d_out, int out_size)
{
    const float* ss = (const float*)d_in[0];
    const float* sl = (const float*)d_in[1];
    const float* vs = (const float*)d_in[2];
    const float* vl = (const float*)d_in[3];
    const float* W1 = (const float*)d_in[4];
    const float* b1 = (const float*)d_in[5];
    const float* W2 = (const float*)d_in[6];
    const float* b2 = (const float*)d_in[7];
    const float* V1 = (const float*)d_in[8];
    const float* V2 = (const float*)d_in[9];
    const int*   frag = (const int*)d_in[10];
    float* out = (float*)d_out;

    void *psi, *pvi, *pwh, *pwl, *ptsh, *ptsl, *ptvh, *ptvl;
    cudaGetSymbolAddress(&psi, g_si);
    cudaGetSymbolAddress(&pvi, g_vi);
    cudaGetSymbolAddress(&pwh, g_wh);
    cudaGetSymbolAddress(&pwl, g_wl);
    cudaGetSymbolAddress(&ptsh, g_tsh);
    cudaGetSymbolAddress(&ptsl, g_tsl);
    cudaGetSymbolAddress(&ptvh, g_tvh);
    cudaGetSymbolAddress(&ptvl, g_tvl);
    const uint16_t* wh = (const uint16_t*)pwh;
    const uint16_t* wl = (const uint16_t*)pwl;
    uint16_t* tsh = (uint16_t*)ptsh;
    uint16_t* tsl = (uint16_t*)ptsl;
    uint16_t* tvh = (uint16_t*)ptvh;
    uint16_t* tvl = (uint16_t*)ptvl;

    k_setup<<<257, 256>>>(frag, W1, W2, V1, V2);

    cudaFuncSetAttribute(k_gemm1, cudaFuncAttributeMaxDynamicSharedMemorySize, G_SMEM);
    cudaFuncSetAttribute(k_gemm2, cudaFuncAttributeMaxDynamicSharedMemorySize, G_SMEM);

    dim3 g(2, NSCALAR_BLOCKS + 192);
    k_gemm1<<<g, 256, G_SMEM>>>(ss, sl, vs, vl,
                                wh + 0 * 65536, wl + 0 * 65536,
                                wh + 2 * 65536, wl + 2 * 65536,
                                b1, tsh, tsl, tvh, tvl);
    k_gemm2<<<g, 256, G_SMEM>>>(tsh, tsl, tvh, tvl,
                                wh + 1 * 65536, wl + 1 * 65536,
                                wh + 3 * 65536, wl + 3 * 65536,
                                b2, (float*)psi, (float*)pvi);

    k_frag<<<NF, 256>>>(out);
}

// round 13
// speedup vs baseline: 1.6693x; 1.0210x over previous
#include <cuda_runtime.h>
#include <cuda_bf16.h>
#include <math.h>
#include <stdint.h>

#define N_NODES 8192
#define H 256
#define NF 256
#define R_MIX 0.3f
#define C_SIM 0.8f
#define LOG2F_ 0.69314718055994530942f
#define MAXM 64

// ---------------- scratch (static device globals) ----------------
__device__ uint16_t g_tsh[ 8192 * 256], g_tsl[ 8192 * 256];
__device__ uint16_t g_tvh[24576 * 256], g_tvl[24576 * 256];
__device__ float g_si[ 8192 * 256];
__device__ float g_vi[24576 * 256];
__device__ uint16_t g_wh[4][65536];
__device__ uint16_t g_wl[4][65536];
__device__ int   g_counts [NF];
__device__ int   g_offsets[NF + 1];
__device__ int   g_nodes  [N_NODES];
__device__ float g_svar[NF], g_vvar[NF], g_ssim[NF], g_dir[NF];
__device__ int   g_done;

__device__ __forceinline__ float sspf(float x) {
    float ax = fabsf(x);
    return fmaxf(x, 0.f) + log1pf(__expf(-ax)) - LOG2F_;
}
__device__ __forceinline__ uint32_t pk2(float a, float b) {
    __nv_bfloat162 t = __floats2bfloat162_rn(a, b);
    return *reinterpret_cast<uint32_t*>(&t);
}
__device__ __forceinline__ float bres(float x) {
    __nv_bfloat16 h = __float2bfloat16(x);
    return x - __bfloat162float(h);
}
__device__ __forceinline__ float b2f(uint16_t u) {
    __nv_bfloat16 h = *reinterpret_cast<__nv_bfloat16*>(&u);
    return __bfloat162float(h);
}

// ---------------- mma/ldmatrix/cp.async wrappers (sm_103-safe) ----------------
__device__ __forceinline__ void ldsm4(uint32_t addr, uint32_t* r) {
    asm volatile("ldmatrix.sync.aligned.m8n8.x4.shared.b16 {%0,%1,%2,%3}, [%4];"
                 : "=r"(r[0]), "=r"(r[1]), "=r"(r[2]), "=r"(r[3]) : "r"(addr));
}
__device__ __forceinline__ void ldsm4t(uint32_t addr, uint32_t* r) {
    asm volatile("ldmatrix.sync.aligned.m8n8.x4.trans.shared.b16 {%0,%1,%2,%3}, [%4];"
                 : "=r"(r[0]), "=r"(r[1]), "=r"(r[2]), "=r"(r[3]) : "r"(addr));
}
__device__ __forceinline__ void mma16816(float* c, const uint32_t* a, uint32_t b0, uint32_t b1) {
    asm volatile(
        "mma.sync.aligned.m16n8k16.row.col.f32.bf16.bf16.f32 "
        "{%0,%1,%2,%3},{%4,%5,%6,%7},{%8,%9},{%0,%1,%2,%3};"
        : "+f"(c[0]), "+f"(c[1]), "+f"(c[2]), "+f"(c[3])
        : "r"(a[0]), "r"(a[1]), "r"(a[2]), "r"(a[3]), "r"(b0), "r"(b1));
}
__device__ __forceinline__ void cpa16(uint32_t dst, const void* src) {
    asm volatile("cp.async.cg.shared.global [%0], [%1], 16;" :: "r"(dst), "l"(src) : "memory");
}
__device__ __forceinline__ void cpa_commit() {
    asm volatile("cp.async.commit_group;" ::: "memory");
}
__device__ __forceinline__ void cpa_wait0() {
    asm volatile("cp.async.wait_group 0;" ::: "memory");
}

// ---------------- fused setup: block 0 = counting sort, blocks 1..256 = prepw ------
__global__ void k_setup(const int* __restrict__ frag,
                        const float* __restrict__ W1, const float* __restrict__ W2,
                        const float* __restrict__ V1, const float* __restrict__ V2)
{
    if (blockIdx.x == 0) {
        __shared__ int s_sc[8 * 256];
        __shared__ int s_off[256];
        __shared__ int s_tmp[256];
        int t = threadIdx.x, w = t >> 5, l = t & 31;

        for (int j = t; j < 2048; j += 256) s_sc[j] = 0;
        __syncthreads();

        int fv[32], lp[32];
#pragma unroll
        for (int c = 0; c < 32; c++) fv[c] = frag[(w * 32 + c) * 32 + l];
        for (int c = 0; c < 32; c++) {
            int f = fv[c];
            bool ok = (f >= 0 && f < NF);
            unsigned mask = __match_any_sync(0xffffffffu, f);
            int rank = __popc(mask & ((1u << l) - 1u));
            int before = ok ? s_sc[w * 256 + f] : 0;
            lp[c] = before + rank;
            __syncwarp();
            if (ok && rank == 0) s_sc[w * 256 + f] = before + __popc(mask);
            __syncwarp();
        }
        __syncthreads();

        {
            int run = 0;
#pragma unroll
            for (int w2 = 0; w2 < 8; w2++) {
                int v = s_sc[w2 * 256 + t];
                s_sc[w2 * 256 + t] = run;
                run += v;
            }
            g_counts[t] = run;
            s_tmp[t] = run;
            __syncthreads();
            for (int d = 1; d < 256; d <<= 1) {
                int u = (t >= d) ? s_tmp[t - d] : 0;
                __syncthreads();
                s_tmp[t] += u;
                __syncthreads();
            }
            s_off[t] = s_tmp[t] - run;
            g_offsets[t] = s_off[t];
            if (t == 255) g_offsets[256] = s_tmp[255];
        }
        __syncthreads();

        for (int c = 0; c < 32; c++) {
            int f = fv[c];
            if (f >= 0 && f < NF) {
                int pos = s_off[f] + s_sc[w * 256 + f] + lp[c];
                if (pos >= 0 && pos < N_NODES)
                    g_nodes[pos] = (w * 32 + c) * 32 + l;
            }
        }
    } else {
        int bb = blockIdx.x - 1;
        int m = bb >> 6;
        const float* src = (m == 0) ? W1 : (m == 1) ? W2 : (m == 2) ? V1 : V2;
        int i0 = ((bb & 63) * 256 + threadIdx.x) * 4;
        float4 v = *(const float4*)(src + i0);
        uint16_t* oh = g_wh[m];
        uint16_t* ol = g_wl[m];
        *(uint32_t*)&oh[i0]     = pk2(v.x, v.y);
        *(uint32_t*)&oh[i0 + 2] = pk2(v.z, v.w);
        *(uint32_t*)&ol[i0]     = pk2(bres(v.x), bres(v.y));
        *(uint32_t*)&ol[i0 + 2] = pk2(bres(v.z), bres(v.w));
    }
}

// ------------- shared GEMM pieces (unchanged, proven) -------------
#define AROW 24
#define BROW 136
#define A_HL (128 * AROW)
#define B_HL (16 * BROW)
#define A_PLANE_B (A_HL * 2)
#define B_PLANE_B (B_HL * 2)
#define ABUF_B (2 * A_PLANE_B)
#define BBUF_B (2 * B_PLANE_B)
#define G_SMEM (4 * ABUF_B + 4 * BBUF_B)
#define NSCALAR_BLOCKS 64

__device__ __forceinline__ void mma_chunk(uint32_t aOff, uint32_t bOff, float acc[4][4][4]) {
    uint32_t ah[4][4], bh[2][4], tmp[2][4], al4[4];
#pragma unroll
    for (int mt = 0; mt < 4; mt++) ldsm4(aOff + mt * (16 * AROW * 2), ah[mt]);
#pragma unroll
    for (int st = 0; st < 2; st++) ldsm4t(bOff + st * 32, bh[st]);
#pragma unroll
    for (int mt = 0; mt < 4; mt++)
#pragma unroll
        for (int nt = 0; nt < 4; nt++)
            mma16816(acc[mt][nt], ah[mt], bh[nt >> 1][(nt & 1) * 2],
                     bh[nt >> 1][(nt & 1) * 2 + 1]);
#pragma unroll
    for (int st = 0; st < 2; st++) ldsm4t(bOff + B_PLANE_B + st * 32, tmp[st]);
#pragma unroll
    for (int mt = 0; mt < 4; mt++)
#pragma unroll
        for (int nt = 0; nt < 4; nt++)
            mma16816(acc[mt][nt], ah[mt], tmp[nt >> 1][(nt & 1) * 2],
                     tmp[nt >> 1][(nt & 1) * 2 + 1]);
#pragma unroll
    for (int mt = 0; mt < 4; mt++) {
        ldsm4(aOff + A_PLANE_B + mt * (16 * AROW * 2), al4);
#pragma unroll
        for (int nt = 0; nt < 4; nt++)
            mma16816(acc[mt][nt], al4, bh[nt >> 1][(nt & 1) * 2],
                     bh[nt >> 1][(nt & 1) * 2 + 1]);
    }
}

__device__ __forceinline__ void gloadA(const float* __restrict__ a1p,
                                       const float* __restrict__ a2p,
                                       int k0, float4& x, float4& y) {
    x = *(const float4*)(a1p + k0);
    y = *(const float4*)(a1p + k0 + 4);
    float4 u = *(const float4*)(a2p + k0);
    float4 v = *(const float4*)(a2p + k0 + 4);
    const float w = 1.f - R_MIX;
    x.x = fmaf(x.x, R_MIX, u.x * w); x.y = fmaf(x.y, R_MIX, u.y * w);
    x.z = fmaf(x.z, R_MIX, u.z * w); x.w = fmaf(x.w, R_MIX, u.w * w);
    y.x = fmaf(y.x, R_MIX, v.x * w); y.y = fmaf(y.y, R_MIX, v.y * w);
    y.z = fmaf(y.z, R_MIX, v.z * w); y.w = fmaf(y.w, R_MIX, v.w * w);
}

__device__ __forceinline__ void cvt_store8(uint16_t* hi_p, uint16_t* lo_p,
                                           const float4& x, const float4& y) {
    uint4 hv, lv;
    hv.x = pk2(x.x, x.y); hv.y = pk2(x.z, x.w);
    hv.z = pk2(y.x, y.y); hv.w = pk2(y.z, y.w);
    lv.x = pk2(bres(x.x), bres(x.y)); lv.y = pk2(bres(x.z), bres(x.w));
    lv.z = pk2(bres(y.x), bres(y.y)); lv.w = pk2(bres(y.z), bres(y.w));
    *reinterpret_cast<uint4*>(hi_p) = hv;
    *reinterpret_cast<uint4*>(lo_p) = lv;
}

// ---------------- layer-1 GEMM (unchanged) ----------------
__global__ __launch_bounds__(256, 2)
void k_gemm1(const float* __restrict__ A1s, const float* __restrict__ A2s,
             const float* __restrict__ A1v, const float* __restrict__ A2v,
             const uint16_t* __restrict__ Bhs, const uint16_t* __restrict__ Bls,
             const uint16_t* __restrict__ Bhv, const uint16_t* __restrict__ Blv,
             const float* __restrict__ biass,
             uint16_t* __restrict__ Csh, uint16_t* __restrict__ Csl,
             uint16_t* __restrict__ Cvh, uint16_t* __restrict__ Cvl)
{
    extern __shared__ __align__(16) uint16_t dsm[];
    const int tid = threadIdx.x, lane = tid & 31, wid = tid >> 5;
    const int warp_m = wid >> 2, warp_n = wid & 3;
    const bool isS = (blockIdx.y < NSCALAR_BLOCKS);
    const size_t rowBase = (size_t)(isS ? blockIdx.y : blockIdx.y - NSCALAR_BLOCKS) * 128;
    const int colBase = blockIdx.x * 128;
    const float* A1 = isS ? A1s : A1v;
    const float* A2 = isS ? A2s : A2v;
    const uint16_t* Bh = isS ? Bhs : Bhv;
    const uint16_t* Bl = isS ? Bls : Blv;
    const float* bias = isS ? biass : nullptr;
    uint16_t* Ch = isS ? Csh : Cvh;
    uint16_t* Cl = isS ? Csl : Cvl;

    const int am = tid >> 1, ak = (tid & 1) * 8;
    const int bk = tid >> 4, bn = (tid & 15) * 8;

    const float* a1p = A1 + (rowBase + am) * H + ak;
    const float* a2p = A2 + (rowBase + am) * H + ak;
    const uint16_t* bhp = Bh + (size_t)bk * H + colBase + bn;
    const uint16_t* blp = Bl + (size_t)bk * H + colBase + bn;

    uint32_t sA0 = (uint32_t)__cvta_generic_to_shared(dsm);
    uint32_t sB0 = sA0 + 4 * ABUF_B;
    uint32_t bDst = sB0 + (uint32_t)((bk * BROW + bn) * 2);
    uint16_t* aStore = dsm + (am * AROW + ak);

    const int a_row0 = warp_m * 64 + (lane & 7) + ((lane >> 3) & 1) * 8;
    const int a_kgrp = lane >> 4;
    uint32_t aBase = sA0 + (uint32_t)((a_row0 * AROW + a_kgrp * 8) * 2);
    const int b_krow = (lane & 7) + ((lane >> 3) & 1) * 8;
    const int b_ngrp = lane >> 4;
    uint32_t bBase = sB0 + (uint32_t)((b_krow * BROW + warp_n * 32 + b_ngrp * 8) * 2);

    float acc[4][4][4];
#pragma unroll
    for (int i = 0; i < 4; i++)
#pragma unroll
        for (int j = 0; j < 4; j++)
#pragma unroll
            for (int q = 0; q < 4; q++) acc[i][j][q] = 0.f;

    cpa16(bDst, bhp);
    cpa16(bDst + B_PLANE_B, blp);
    cpa16(bDst + BBUF_B, bhp + (size_t)16 * H);
    cpa16(bDst + BBUF_B + B_PLANE_B, blp + (size_t)16 * H);
    cpa_commit();
    {
        float4 ax, ay;
        gloadA(a1p, a2p, 0, ax, ay);
        cvt_store8(aStore, aStore + A_HL, ax, ay);
        gloadA(a1p, a2p, 16, ax, ay);
        cvt_store8(aStore + ABUF_B / 2, aStore + ABUF_B / 2 + A_HL, ax, ay);
    }
    cpa_wait0();
    __syncthreads();

    const int NT = H / 16;
    for (int t = 0; t < NT; t += 2) {
        if (t + 2 < NT) {
            int c2 = t + 2, c3 = t + 3;
            size_t k2 = (size_t)c2 * 16, k3 = (size_t)c3 * 16;
            uint32_t bd2 = bDst + (uint32_t)((c2 & 3) * BBUF_B);
            uint32_t bd3 = bDst + (uint32_t)((c3 & 3) * BBUF_B);
            cpa16(bd2, bhp + k2 * H);
            cpa16(bd2 + B_PLANE_B, blp + k2 * H);
            cpa16(bd3, bhp + k3 * H);
            cpa16(bd3 + B_PLANE_B, blp + k3 * H);
            cpa_commit();
            float4 ax, ay;
            gloadA(a1p, a2p, (int)k2, ax, ay);
            cvt_store8(aStore + (c2 & 3) * (ABUF_B / 2),
                       aStore + (c2 & 3) * (ABUF_B / 2) + A_HL, ax, ay);
            gloadA(a1p, a2p, (int)k3, ax, ay);
            cvt_store8(aStore + (c3 & 3) * (ABUF_B / 2),
                       aStore + (c3 & 3) * (ABUF_B / 2) + A_HL, ax, ay);
        }
        mma_chunk(aBase + (uint32_t)((t & 3) * ABUF_B),
                  bBase + (uint32_t)((t & 3) * BBUF_B), acc);
        mma_chunk(aBase + (uint32_t)(((t + 1) & 3) * ABUF_B),
                  bBase + (uint32_t)(((t + 1) & 3) * BBUF_B), acc);
        if (t + 2 < NT) {
            cpa_wait0();
            __syncthreads();
        }
    }

#pragma unroll
    for (int mt = 0; mt < 4; mt++) {
        size_t r0 = rowBase + warp_m * 64 + mt * 16 + (lane >> 2);
#pragma unroll
        for (int nt = 0; nt < 4; nt++) {
            int col = colBase + warp_n * 32 + nt * 8 + (lane & 3) * 2;
            float v0 = acc[mt][nt][0], v1 = acc[mt][nt][1];
            float v2 = acc[mt][nt][2], v3 = acc[mt][nt][3];
            if (bias) {
                float2 bb = *(const float2*)&bias[col];
                v0 += bb.x; v1 += bb.y; v2 += bb.x; v3 += bb.y;
            }
            v0 = sspf(v0); v1 = sspf(v1); v2 = sspf(v2); v3 = sspf(v3);
            *(uint32_t*)&Ch[r0 * H + col]       = pk2(v0, v1);
            *(uint32_t*)&Cl[r0 * H + col]       = pk2(bres(v0), bres(v1));
            *(uint32_t*)&Ch[(r0 + 8) * H + col] = pk2(v2, v3);
            *(uint32_t*)&Cl[(r0 + 8) * H + col] = pk2(bres(v2), bres(v3));
        }
    }
}

// ---------------- layer-2 GEMM (unchanged) ----------------
__global__ __launch_bounds__(256, 2)
void k_gemm2(const uint16_t* __restrict__ Ahs, const uint16_t* __restrict__ Als,
             const uint16_t* __restrict__ Ahv, const uint16_t* __restrict__ Alv,
             const uint16_t* __restrict__ Bhs, const uint16_t* __restrict__ Bls,
             const uint16_t* __restrict__ Bhv, const uint16_t* __restrict__ Blv,
             const float* __restrict__ biass,
             float* __restrict__ Cs, float* __restrict__ Cv)
{
    extern __shared__ __align__(16) uint16_t dsm[];
    const int tid = threadIdx.x, lane = tid & 31, wid = tid >> 5;
    const int warp_m = wid >> 2, warp_n = wid & 3;
    const bool isS = (blockIdx.y < NSCALAR_BLOCKS);
    const size_t rowBase = (size_t)(isS ? blockIdx.y : blockIdx.y - NSCALAR_BLOCKS) * 128;
    const int colBase = blockIdx.x * 128;
    const uint16_t* Ah = isS ? Ahs : Ahv;
    const uint16_t* Al = isS ? Als : Alv;
    const uint16_t* Bh = isS ? Bhs : Bhv;
    const uint16_t* Bl = isS ? Bls : Blv;
    const float* bias = isS ? biass : nullptr;
    float* Cc = isS ? Cs : Cv;

    const int am = tid >> 1, ak = (tid & 1) * 8;
    const int bk = tid >> 4, bn = (tid & 15) * 8;

    const uint16_t* ahp = Ah + (rowBase + am) * H + ak;
    const uint16_t* alp = Al + (rowBase + am) * H + ak;
    const uint16_t* bhp = Bh + (size_t)bk * H + colBase + bn;
    const uint16_t* blp = Bl + (size_t)bk * H + colBase + bn;

    uint32_t sA0 = (uint32_t)__cvta_generic_to_shared(dsm);
    uint32_t sB0 = sA0 + 4 * ABUF_B;
    uint32_t aDst = sA0 + (uint32_t)((am * AROW + ak) * 2);
    uint32_t bDst = sB0 + (uint32_t)((bk * BROW + bn) * 2);

    const int a_row0 = warp_m * 64 + (lane & 7) + ((lane >> 3) & 1) * 8;
    const int a_kgrp = lane >> 4;
    uint32_t aBase = sA0 + (uint32_t)((a_row0 * AROW + a_kgrp * 8) * 2);
    const int b_krow = (lane & 7) + ((lane >> 3) & 1) * 8;
    const int b_ngrp = lane >> 4;
    uint32_t bBase = sB0 + (uint32_t)((b_krow * BROW + warp_n * 32 + b_ngrp * 8) * 2);

    float acc[4][4][4];
#pragma unroll
    for (int i = 0; i < 4; i++)
#pragma unroll
        for (int j = 0; j < 4; j++)
#pragma unroll
            for (int q = 0; q < 4; q++) acc[i][j][q] = 0.f;

#pragma unroll
    for (int c = 0; c < 2; c++) {
        size_t k0 = (size_t)c * 16;
        uint32_t ad = aDst + (uint32_t)(c * ABUF_B);
        uint32_t bd = bDst + (uint32_t)(c * BBUF_B);
        cpa16(ad, ahp + k0);
        cpa16(ad + A_PLANE_B, alp + k0);
        cpa16(bd, bhp + k0 * H);
        cpa16(bd + B_PLANE_B, blp + k0 * H);
    }
    cpa_commit();
    cpa_wait0();
    __syncthreads();

    const int NT = H / 16;
    for (int t = 0; t < NT; t += 2) {
        if (t + 2 < NT) {
#pragma unroll
            for (int d = 2; d < 4; d++) {
                int c = t + d;
                size_t k0 = (size_t)c * 16;
                uint32_t ad = aDst + (uint32_t)((c & 3) * ABUF_B);
                uint32_t bd = bDst + (uint32_t)((c & 3) * BBUF_B);
                cpa16(ad, ahp + k0);
                cpa16(ad + A_PLANE_B, alp + k0);
                cpa16(bd, bhp + k0 * H);
                cpa16(bd + B_PLANE_B, blp + k0 * H);
            }
            cpa_commit();
        }
        mma_chunk(aBase + (uint32_t)((t & 3) * ABUF_B),
                  bBase + (uint32_t)((t & 3) * BBUF_B), acc);
        mma_chunk(aBase + (uint32_t)(((t + 1) & 3) * ABUF_B),
                  bBase + (uint32_t)(((t + 1) & 3) * BBUF_B), acc);
        if (t + 2 < NT) {
            cpa_wait0();
            __syncthreads();
        }
    }

#pragma unroll
    for (int mt = 0; mt < 4; mt++) {
        size_t r0 = rowBase + warp_m * 64 + mt * 16 + (lane >> 2);
#pragma unroll
        for (int nt = 0; nt < 4; nt++) {
            int col = colBase + warp_n * 32 + nt * 8 + (lane & 3) * 2;
            float v0 = acc[mt][nt][0], v1 = acc[mt][nt][1];
            float v2 = acc[mt][nt][2], v3 = acc[mt][nt][3];
            if (bias) {
                float2 bb = *(const float2*)&bias[col];
                v0 += bb.x; v1 += bb.y; v2 += bb.x; v3 += bb.y;
            }
            float2 o0; o0.x = v0; o0.y = v1;
            float2 o1; o1.x = v2; o1.y = v3;
            *(float2*)&Cc[r0 * H + col] = o0;
            *(float2*)&Cc[(r0 + 8) * H + col] = o1;
        }
    }
}

// ---------------- per-fragment stats via tensor-core Gram matrix -----------------
// Double-buffered chunk pipeline, ONE barrier per chunk. Variance comes from the
// Gram diagonal: svar = trace(G) - ||colsum||^2/cnt (colsum from smem hi+lo planes).
#define ZROW 72
#define ZPLANE (64 * ZROW)

__global__ void k_frag(float* __restrict__ out) {
    __shared__ __align__(16) uint16_t z[2][2][ZPLANE];   // [buf][hi/lo]
    __shared__ float sdiag[64];
    __shared__ float rd[48];
    __shared__ int s_last;
    int f = blockIdx.x, t = threadIdx.x;
    int cnt = g_counts[f], off = g_offsets[f];
    int wid = t >> 5, lane = t & 31;
    float serr = 0.f, derr = 0.f;
    float tr0 = 0.f, tr123 = 0.f, cs0 = 0.f, cs123 = 0.f;

    uint32_t z0 = (uint32_t)__cvta_generic_to_shared(&z[0][0][0]);

    if (cnt >= 2 && cnt <= MAXM) {
        const int Mt = (cnt + 15) >> 4;
        int tm[2] = {-1, -1}, tn[2] = {-1, -1};
        {
            int idx = 0;
            for (int mt = 0; mt < Mt; mt++)
                for (int nt = mt; nt < Mt; nt++) {
                    if ((idx & 7) == wid) {
                        int s = idx >> 3;
                        if (s < 2) { tm[s] = mt; tn[s] = nt; }
                    }
                    idx++;
                }
        }
        const int lrow = t >> 2;
        const int lkq = (t & 3) * 16;
        int lnd = (lrow < cnt) ? g_nodes[off + lrow] : -1;
        const int fr = (lane & 7) + ((lane >> 3) & 1) * 8;
        const int fk = (lane >> 4) * 8;

        for (int feat = 0; feat < 4; feat++) {
            const float* src = (lnd >= 0)
                ? ((feat == 0) ? g_si + (size_t)lnd * H
                               : g_vi + ((size_t)lnd * 3 + (feat - 1)) * H)
                : nullptr;

            float acc[2][2][4];
#pragma unroll
            for (int a = 0; a < 2; a++)
#pragma unroll
                for (int b = 0; b < 2; b++)
#pragma unroll
                    for (int q = 0; q < 4; q++) acc[a][b][q] = 0.f;

            // prologue: chunk 0 -> buf 0
            float4 pv[4];
            if (src) {
                const float4* sp = (const float4*)(src + lkq);
#pragma unroll
                for (int j = 0; j < 4; j++) pv[j] = sp[j];
            }
            {
                uint16_t* ph = &z[0][0][lrow * ZROW + lkq];
                uint16_t* pl = &z[0][1][lrow * ZROW + lkq];
                if (src) {
#pragma unroll
                    for (int j = 0; j < 4; j++) {
                        float4 v4 = pv[j];
                        uint2 hv, lv;
                        hv.x = pk2(v4.x, v4.y); hv.y = pk2(v4.z, v4.w);
                        lv.x = pk2(bres(v4.x), bres(v4.y));
                        lv.y = pk2(bres(v4.z), bres(v4.w));
                        *(uint2*)(ph + j * 4) = hv;
                        *(uint2*)(pl + j * 4) = lv;
                    }
                } else {
                    uint2 zz; zz.x = 0; zz.y = 0;
#pragma unroll
                    for (int j = 0; j < 4; j++) {
                        *(uint2*)(ph + j * 4) = zz;
                        *(uint2*)(pl + j * 4) = zz;
                    }
                }
            }
            __syncthreads();

            for (int kc = 0; kc < 4; kc++) {
                int b = kc & 1;
                // prefetch chunk kc+1 into regs (overlaps mma below)
                if (kc < 3 && src) {
                    const float4* sp = (const float4*)(src + (kc + 1) * 64 + lkq);
#pragma unroll
                    for (int j = 0; j < 4; j++) pv[j] = sp[j];
                }
                uint32_t zhb = z0 + (uint32_t)(b * 2 * ZPLANE * 2);
                uint32_t zlb = zhb + (uint32_t)(ZPLANE * 2);
#pragma unroll
                for (int ti = 0; ti < 2; ti++) {
                    if (tm[ti] < 0) continue;
#pragma unroll
                    for (int ks = 0; ks < 4; ks++) {
                        uint32_t aoff = (uint32_t)(((tm[ti] * 16 + fr) * ZROW + ks * 16 + fk) * 2);
                        uint32_t boff = (uint32_t)(((tn[ti] * 16 + fr) * ZROW + ks * 16 + fk) * 2);
                        uint32_t ah[4], al[4], bh[4], bl[4];
                        ldsm4(zhb + aoff, ah);
                        ldsm4(zlb + aoff, al);
                        ldsm4(zhb + boff, bh);
                        ldsm4(zlb + boff, bl);
                        mma16816(acc[ti][0], ah, bh[0], bh[2]);
                        mma16816(acc[ti][1], ah, bh[1], bh[3]);
                        mma16816(acc[ti][0], ah, bl[0], bl[2]);
                        mma16816(acc[ti][1], ah, bl[1], bl[3]);
                        mma16816(acc[ti][0], al, bh[0], bh[2]);
                        mma16816(acc[ti][1], al, bh[1], bh[3]);
                    }
                }
                // column sums of this chunk (threads 0..63, column t)
                if (t < 64) {
                    float s = 0.f;
                    for (int r = 0; r < cnt; r++)
                        s += b2f(z[b][0][r * ZROW + t]) + b2f(z[b][1][r * ZROW + t]);
                    float sq = s * s;
                    if (feat == 0) cs0 += sq; else cs123 += sq;
                }
                if (kc < 3) {
                    // store prefetched chunk into the other buffer
                    int nb = b ^ 1;
                    uint16_t* ph = &z[nb][0][lrow * ZROW + lkq];
                    uint16_t* pl = &z[nb][1][lrow * ZROW + lkq];
                    if (src) {
#pragma unroll
                        for (int j = 0; j < 4; j++) {
                            float4 v4 = pv[j];
                            uint2 hv, lv;
                            hv.x = pk2(v4.x, v4.y); hv.y = pk2(v4.z, v4.w);
                            lv.x = pk2(bres(v4.x), bres(v4.y));
                            lv.y = pk2(bres(v4.z), bres(v4.w));
                            *(uint2*)(ph + j * 4) = hv;
                            *(uint2*)(pl + j * 4) = lv;
                        }
                    } else {
                        uint2 zz; zz.x = 0; zz.y = 0;
#pragma unroll
                        for (int j = 0; j < 4; j++) {
                            *(uint2*)(ph + j * 4) = zz;
                            *(uint2*)(pl + j * 4) = zz;
                        }
                    }
                    __syncthreads();
                }
            }
            __syncthreads();

            // diagonal -> smem
            {
                int r = lane >> 2, c = (lane & 3) * 2;
#pragma unroll
                for (int ti = 0; ti < 2; ti++) {
                    if (tm[ti] < 0 || tm[ti] != tn[ti]) continue;
#pragma unroll
                    for (int hh = 0; hh < 2; hh++) {
                        int nl0 = hh * 8 + c;
                        if (r == nl0)     sdiag[tm[ti] * 16 + r]     = acc[ti][hh][0];
                        if (r == nl0 + 1) sdiag[tm[ti] * 16 + r]     = acc[ti][hh][1];
                        if (r + 8 == nl0)     sdiag[tm[ti] * 16 + r + 8] = acc[ti][hh][2];
                        if (r + 8 == nl0 + 1) sdiag[tm[ti] * 16 + r + 8] = acc[ti][hh][3];
                    }
                }
            }
            __syncthreads();

            // trace contribution (variance term 1)
            if (t < cnt) {
                float d = sdiag[t];
                if (feat == 0) tr0 += d; else tr123 += d;
            }

            // pair errors
            {
                float err = 0.f;
                int r = lane >> 2, c = (lane & 3) * 2;
#pragma unroll
                for (int ti = 0; ti < 2; ti++) {
                    if (tm[ti] < 0) continue;
                    int mb = tm[ti] * 16, nb = tn[ti] * 16;
#pragma unroll
                    for (int hh = 0; hh < 2; hh++) {
                        int n0 = nb + hh * 8 + c;
#pragma unroll
                        for (int q = 0; q < 4; q++) {
                            int m = mb + r + (q >> 1) * 8;
                            int n = n0 + (q & 1);
                            if (n < cnt && m < n) {
                                float rs = rsqrtf(fmaxf(sdiag[m] * sdiag[n], 1e-24f));
                                float e = fmaf(acc[ti][hh][q], rs, -C_SIM);
                                err = fmaf(e, e, err);
                            }
                        }
                    }
                }
                if (feat == 0) serr = err; else derr += err;
            }
        }
    } else if (cnt > MAXM) {
        // fallback (never expected): gmem-direct, exact two-pass; reuse z as scratch
        float* mean = (float*)z;
        float as = 0.f, a0m = 0.f, a1m = 0.f, a2m = 0.f;
        for (int m = 0; m < cnt; m++) {
            int nd = g_nodes[off + m];
            as += g_si[(size_t)nd * H + t];
            const float* vv = g_vi + (size_t)nd * 3 * H;
            a0m += vv[t]; a1m += vv[H + t]; a2m += vv[2 * H + t];
        }
        float invn = 1.f / (float)cnt;
        mean[t] = as * invn; mean[256 + t] = a0m * invn;
        mean[512 + t] = a1m * invn; mean[768 + t] = a2m * invn;
        __syncthreads();
        for (int m = 0; m < cnt; m++) {
            int nd = g_nodes[off + m];
            float d0 = g_si[(size_t)nd * H + t] - mean[t];
            tr0 = fmaf(d0, d0, tr0);
            const float* vv = g_vi + (size_t)nd * 3 * H;
            float d1 = vv[t] - mean[256 + t];
            float d2 = vv[H + t] - mean[512 + t];
            float d3 = vv[2 * H + t] - mean[768 + t];
            tr123 = fmaf(d1, d1, tr123); tr123 = fmaf(d2, d2, tr123); tr123 = fmaf(d3, d3, tr123);
        }
        for (int feat = 0; feat < 4; feat++) {
            float acc = 0.f;
            for (int a = wid; a < cnt - 1; a += 8) {
                int na = g_nodes[off + a];
                const float* ra = (feat == 0) ? g_si + (size_t)na * H
                                              : g_vi + ((size_t)na * 3 + (feat - 1)) * H;
                for (int b = a + 1 + lane; b < cnt; b += 32) {
                    int nb = g_nodes[off + b];
                    const float* rb = (feat == 0) ? g_si + (size_t)nb * H
                                                  : g_vi + ((size_t)nb * 3 + (feat - 1)) * H;
                    float dot = 0.f, sa = 0.f, sb = 0.f;
                    for (int k = 0; k < H; k++) {
                        float x = ra[k], y = rb[k];
                        dot = fmaf(x, y, dot);
                        sa = fmaf(x, x, sa);
                        sb = fmaf(y, y, sb);
                    }
                    float e = dot / (fmaxf(sqrtf(sa), 1e-12f) * fmaxf(sqrtf(sb), 1e-12f)) - C_SIM;
                    acc = fmaf(e, e, acc);
                }
            }
            if (feat == 0) serr = acc; else derr += acc;
        }
        // cs stays 0 -> svar = tr0, vvar = tr123 (already exact deviations)
    }

    // block reduce 6 values
    for (int o = 16; o; o >>= 1) {
        tr0   += __shfl_xor_sync(0xffffffffu, tr0, o);
        tr123 += __shfl_xor_sync(0xffffffffu, tr123, o);
        cs0   += __shfl_xor_sync(0xffffffffu, cs0, o);
        cs123 += __shfl_xor_sync(0xffffffffu, cs123, o);
        serr  += __shfl_xor_sync(0xffffffffu, serr, o);
        derr  += __shfl_xor_sync(0xffffffffu, derr, o);
    }
    if (lane == 0) {
        rd[wid] = tr0; rd[8 + wid] = tr123; rd[16 + wid] = cs0;
        rd[24 + wid] = cs123; rd[32 + wid] = serr; rd[40 + wid] = derr;
    }
    __syncthreads();
    if (t == 0) {
        float a = 0.f, b = 0.f, c = 0.f, d = 0.f, e = 0.f, g = 0.f;
        for (int i = 0; i < 8; i++) {
            a += rd[i]; b += rd[8 + i]; c += rd[16 + i];
            d += rd[24 + i]; e += rd[32 + i]; g += rd[40 + i];
        }
        float invn = 1.f / (float)(cnt > 0 ? cnt : 1);
        g_svar[f] = a - c * invn;
        g_vvar[f] = b - d * invn;
        g_ssim[f] = e;
        g_dir[f]  = g;
        __threadfence();
        int old = atomicAdd(&g_done, 1);
        s_last = (old == NF - 1) ? 1 : 0;
    }
    __syncthreads();

    if (s_last) {
        __threadfence();
        float n  = (float)g_counts[t];
        float pc = n * (n - 1.f) * 0.5f;
        float ns  = fmaxf(n, 1.f);
        float pcs = fmaxf(pc, 1.f);
        float sl = g_svar[t] / ns + g_ssim[t] / pcs;
        float vl = g_vvar[t] / ns + g_dir[t] / (3.f * pcs);
        float fl = 0.5f * sl + 0.5f * vl;
        float val  = (pc > 0.f) ? fl : 0.f;
        float cntv = (pc > 0.f) ? 1.f : 0.f;
        for (int o = 16; o; o >>= 1) {
            val  += __shfl_xor_sync(0xffffffffu, val, o);
            cntv += __shfl_xor_sync(0xffffffffu, cntv, o);
        }
        __syncthreads();
        if (lane == 0) { rd[wid] = val; rd[8 + wid] = cntv; }
        __syncthreads();
        if (t == 0) {
            float tot = 0.f, tc = 0.f;
            for (int i = 0; i < 8; i++) { tot += rd[i]; tc += rd[8 + i]; }
            out[0] = (tc > 0.f) ? tot / fmaxf(tc, 1.f) : 0.f;
            g_done = 0;
        }
    }
}

// ---------------- launch ----------------
extern "C" void kernel_launch(void* const* d_in, const int* in_sizes, int n_in,
                              void* d_out, int out_size)
{
    const float* ss = (const float*)d_in[0];
    const float* sl = (const float*)d_in[1];
    const float* vs = (const float*)d_in[2];
    const float* vl = (const float*)d_in[3];
    const float* W1 = (const float*)d_in[4];
    const float* b1 = (const float*)d_in[5];
    const float* W2 = (const float*)d_in[6];
    const float* b2 = (const float*)d_in[7];
    const float* V1 = (const float*)d_in[8];
    const float* V2 = (const float*)d_in[9];
    const int*   frag = (const int*)d_in[10];
    float* out = (float*)d_out;

    void *psi, *pvi, *pwh, *pwl, *ptsh, *ptsl, *ptvh, *ptvl;
    cudaGetSymbolAddress(&psi, g_si);
    cudaGetSymbolAddress(&pvi, g_vi);
    cudaGetSymbolAddress(&pwh, g_wh);
    cudaGetSymbolAddress(&pwl, g_wl);
    cudaGetSymbolAddress(&ptsh, g_tsh);
    cudaGetSymbolAddress(&ptsl, g_tsl);
    cudaGetSymbolAddress(&ptvh, g_tvh);
    cudaGetSymbolAddress(&ptvl, g_tvl);
    const uint16_t* wh = (const uint16_t*)pwh;
    const uint16_t* wl = (const uint16_t*)pwl;
    uint16_t* tsh = (uint16_t*)ptsh;
    uint16_t* tsl = (uint16_t*)ptsl;
    uint16_t* tvh = (uint16_t*)ptvh;
    uint16_t* tvl = (uint16_t*)ptvl;

    k_setup<<<257, 256>>>(frag, W1, W2, V1, V2);

    cudaFuncSetAttribute(k_gemm1, cudaFuncAttributeMaxDynamicSharedMemorySize, G_SMEM);
    cudaFuncSetAttribute(k_gemm2, cudaFuncAttributeMaxDynamicSharedMemorySize, G_SMEM);

    dim3 g(2, NSCALAR_BLOCKS + 192);
    k_gemm1<<<g, 256, G_SMEM>>>(ss, sl, vs, vl,
                                wh + 0 * 65536, wl + 0 * 65536,
                                wh + 2 * 65536, wl + 2 * 65536,
                                b1, tsh, tsl, tvh, tvl);
    k_gemm2<<<g, 256, G_SMEM>>>(tsh, tsl, tvh, tvl,
                                wh + 1 * 65536, wl + 1 * 65536,
                                wh + 3 * 65536, wl + 3 * 65536,
                                b2, (float*)psi, (float*)pvi);

    k_frag<<<NF, 256>>>(out);
}

// round 14
// speedup vs baseline: 1.7669x; 1.0585x over previous
#include <cuda_runtime.h>
#include <cuda_bf16.h>
#include <math.h>
#include <stdint.h>

#define N_NODES 8192
#define H 256
#define NF 256
#define R_MIX 0.3f
#define C_SIM 0.8f
#define LOG2F_ 0.69314718055994530942f
#define MAXM 64

// ---------------- scratch (static device globals) ----------------
__device__ uint16_t g_tsh[ 8192 * 256], g_tsl[ 8192 * 256];   // layer-1 out (bf16 hi/lo)
__device__ uint16_t g_tvh[24576 * 256], g_tvl[24576 * 256];
__device__ uint16_t g_sih[ 8192 * 256], g_sil[ 8192 * 256];   // layer-2 out (bf16 hi/lo)
__device__ uint16_t g_vih[24576 * 256], g_vil[24576 * 256];
__device__ uint16_t g_wh[4][65536];
__device__ uint16_t g_wl[4][65536];
__device__ int   g_counts [NF];
__device__ int   g_offsets[NF + 1];
__device__ int   g_nodes  [N_NODES];
__device__ float g_svar[NF], g_vvar[NF], g_ssim[NF], g_dir[NF];
__device__ int   g_done;

__device__ __forceinline__ float sspf(float x) {
    float ax = fabsf(x);
    return fmaxf(x, 0.f) + log1pf(__expf(-ax)) - LOG2F_;
}
__device__ __forceinline__ uint32_t pk2(float a, float b) {
    __nv_bfloat162 t = __floats2bfloat162_rn(a, b);
    return *reinterpret_cast<uint32_t*>(&t);
}
__device__ __forceinline__ float bres(float x) {
    __nv_bfloat16 h = __float2bfloat16(x);
    return x - __bfloat162float(h);
}
__device__ __forceinline__ float b2f(uint16_t u) {
    __nv_bfloat16 h = *reinterpret_cast<__nv_bfloat16*>(&u);
    return __bfloat162float(h);
}

// ---------------- mma/ldmatrix/cp.async wrappers (sm_103-safe) ----------------
__device__ __forceinline__ void ldsm4(uint32_t addr, uint32_t* r) {
    asm volatile("ldmatrix.sync.aligned.m8n8.x4.shared.b16 {%0,%1,%2,%3}, [%4];"
                 : "=r"(r[0]), "=r"(r[1]), "=r"(r[2]), "=r"(r[3]) : "r"(addr));
}
__device__ __forceinline__ void ldsm4t(uint32_t addr, uint32_t* r) {
    asm volatile("ldmatrix.sync.aligned.m8n8.x4.trans.shared.b16 {%0,%1,%2,%3}, [%4];"
                 : "=r"(r[0]), "=r"(r[1]), "=r"(r[2]), "=r"(r[3]) : "r"(addr));
}
__device__ __forceinline__ void mma16816(float* c, const uint32_t* a, uint32_t b0, uint32_t b1) {
    asm volatile(
        "mma.sync.aligned.m16n8k16.row.col.f32.bf16.bf16.f32 "
        "{%0,%1,%2,%3},{%4,%5,%6,%7},{%8,%9},{%0,%1,%2,%3};"
        : "+f"(c[0]), "+f"(c[1]), "+f"(c[2]), "+f"(c[3])
        : "r"(a[0]), "r"(a[1]), "r"(a[2]), "r"(a[3]), "r"(b0), "r"(b1));
}
__device__ __forceinline__ void cpa16(uint32_t dst, const void* src) {
    asm volatile("cp.async.cg.shared.global [%0], [%1], 16;" :: "r"(dst), "l"(src) : "memory");
}
__device__ __forceinline__ void cpa16z(uint32_t dst, const void* src, int sz) {
    asm volatile("cp.async.cg.shared.global [%0], [%1], 16, %2;"
                 :: "r"(dst), "l"(src), "r"(sz) : "memory");
}
__device__ __forceinline__ void cpa_commit() {
    asm volatile("cp.async.commit_group;" ::: "memory");
}
__device__ __forceinline__ void cpa_wait0() {
    asm volatile("cp.async.wait_group 0;" ::: "memory");
}

// ---------------- fused setup: block 0 = counting sort, blocks 1..256 = prepw ------
__global__ void k_setup(const int* __restrict__ frag,
                        const float* __restrict__ W1, const float* __restrict__ W2,
                        const float* __restrict__ V1, const float* __restrict__ V2)
{
    if (blockIdx.x == 0) {
        __shared__ int s_sc[8 * 256];
        __shared__ int s_off[256];
        __shared__ int s_tmp[256];
        int t = threadIdx.x, w = t >> 5, l = t & 31;

        for (int j = t; j < 2048; j += 256) s_sc[j] = 0;
        __syncthreads();

        int fv[32], lp[32];
#pragma unroll
        for (int c = 0; c < 32; c++) fv[c] = frag[(w * 32 + c) * 32 + l];
        for (int c = 0; c < 32; c++) {
            int f = fv[c];
            bool ok = (f >= 0 && f < NF);
            unsigned mask = __match_any_sync(0xffffffffu, f);
            int rank = __popc(mask & ((1u << l) - 1u));
            int before = ok ? s_sc[w * 256 + f] : 0;
            lp[c] = before + rank;
            __syncwarp();
            if (ok && rank == 0) s_sc[w * 256 + f] = before + __popc(mask);
            __syncwarp();
        }
        __syncthreads();

        {
            int run = 0;
#pragma unroll
            for (int w2 = 0; w2 < 8; w2++) {
                int v = s_sc[w2 * 256 + t];
                s_sc[w2 * 256 + t] = run;
                run += v;
            }
            g_counts[t] = run;
            s_tmp[t] = run;
            __syncthreads();
            for (int d = 1; d < 256; d <<= 1) {
                int u = (t >= d) ? s_tmp[t - d] : 0;
                __syncthreads();
                s_tmp[t] += u;
                __syncthreads();
            }
            s_off[t] = s_tmp[t] - run;
            g_offsets[t] = s_off[t];
            if (t == 255) g_offsets[256] = s_tmp[255];
        }
        __syncthreads();

        for (int c = 0; c < 32; c++) {
            int f = fv[c];
            if (f >= 0 && f < NF) {
                int pos = s_off[f] + s_sc[w * 256 + f] + lp[c];
                if (pos >= 0 && pos < N_NODES)
                    g_nodes[pos] = (w * 32 + c) * 32 + l;
            }
        }
    } else {
        int bb = blockIdx.x - 1;
        int m = bb >> 6;
        const float* src = (m == 0) ? W1 : (m == 1) ? W2 : (m == 2) ? V1 : V2;
        int i0 = ((bb & 63) * 256 + threadIdx.x) * 4;
        float4 v = *(const float4*)(src + i0);
        uint16_t* oh = g_wh[m];
        uint16_t* ol = g_wl[m];
        *(uint32_t*)&oh[i0]     = pk2(v.x, v.y);
        *(uint32_t*)&oh[i0 + 2] = pk2(v.z, v.w);
        *(uint32_t*)&ol[i0]     = pk2(bres(v.x), bres(v.y));
        *(uint32_t*)&ol[i0 + 2] = pk2(bres(v.z), bres(v.w));
    }
}

// ------------- shared GEMM pieces (proven) -------------
#define AROW 24
#define BROW 136
#define A_HL (128 * AROW)
#define B_HL (16 * BROW)
#define A_PLANE_B (A_HL * 2)
#define B_PLANE_B (B_HL * 2)
#define ABUF_B (2 * A_PLANE_B)
#define BBUF_B (2 * B_PLANE_B)
#define G_SMEM (4 * ABUF_B + 4 * BBUF_B)
#define NSCALAR_BLOCKS 64

__device__ __forceinline__ void mma_chunk(uint32_t aOff, uint32_t bOff, float acc[4][4][4]) {
    uint32_t ah[4][4], bh[2][4], tmp[2][4], al4[4];
#pragma unroll
    for (int mt = 0; mt < 4; mt++) ldsm4(aOff + mt * (16 * AROW * 2), ah[mt]);
#pragma unroll
    for (int st = 0; st < 2; st++) ldsm4t(bOff + st * 32, bh[st]);
#pragma unroll
    for (int mt = 0; mt < 4; mt++)
#pragma unroll
        for (int nt = 0; nt < 4; nt++)
            mma16816(acc[mt][nt], ah[mt], bh[nt >> 1][(nt & 1) * 2],
                     bh[nt >> 1][(nt & 1) * 2 + 1]);
#pragma unroll
    for (int st = 0; st < 2; st++) ldsm4t(bOff + B_PLANE_B + st * 32, tmp[st]);
#pragma unroll
    for (int mt = 0; mt < 4; mt++)
#pragma unroll
        for (int nt = 0; nt < 4; nt++)
            mma16816(acc[mt][nt], ah[mt], tmp[nt >> 1][(nt & 1) * 2],
                     tmp[nt >> 1][(nt & 1) * 2 + 1]);
#pragma unroll
    for (int mt = 0; mt < 4; mt++) {
        ldsm4(aOff + A_PLANE_B + mt * (16 * AROW * 2), al4);
#pragma unroll
        for (int nt = 0; nt < 4; nt++)
            mma16816(acc[mt][nt], al4, bh[nt >> 1][(nt & 1) * 2],
                     bh[nt >> 1][(nt & 1) * 2 + 1]);
    }
}

__device__ __forceinline__ void gloadA(const float* __restrict__ a1p,
                                       const float* __restrict__ a2p,
                                       int k0, float4& x, float4& y) {
    x = *(const float4*)(a1p + k0);
    y = *(const float4*)(a1p + k0 + 4);
    float4 u = *(const float4*)(a2p + k0);
    float4 v = *(const float4*)(a2p + k0 + 4);
    const float w = 1.f - R_MIX;
    x.x = fmaf(x.x, R_MIX, u.x * w); x.y = fmaf(x.y, R_MIX, u.y * w);
    x.z = fmaf(x.z, R_MIX, u.z * w); x.w = fmaf(x.w, R_MIX, u.w * w);
    y.x = fmaf(y.x, R_MIX, v.x * w); y.y = fmaf(y.y, R_MIX, v.y * w);
    y.z = fmaf(y.z, R_MIX, v.z * w); y.w = fmaf(y.w, R_MIX, v.w * w);
}

__device__ __forceinline__ void cvt_store8(uint16_t* hi_p, uint16_t* lo_p,
                                           const float4& x, const float4& y) {
    uint4 hv, lv;
    hv.x = pk2(x.x, x.y); hv.y = pk2(x.z, x.w);
    hv.z = pk2(y.x, y.y); hv.w = pk2(y.z, y.w);
    lv.x = pk2(bres(x.x), bres(x.y)); lv.y = pk2(bres(x.z), bres(x.w));
    lv.z = pk2(bres(y.x), bres(y.y)); lv.w = pk2(bres(y.z), bres(y.w));
    *reinterpret_cast<uint4*>(hi_p) = hv;
    *reinterpret_cast<uint4*>(lo_p) = lv;
}

// ---------------- layer-1 GEMM (unchanged) ----------------
__global__ __launch_bounds__(256, 2)
void k_gemm1(const float* __restrict__ A1s, const float* __restrict__ A2s,
             const float* __restrict__ A1v, const float* __restrict__ A2v,
             const uint16_t* __restrict__ Bhs, const uint16_t* __restrict__ Bls,
             const uint16_t* __restrict__ Bhv, const uint16_t* __restrict__ Blv,
             const float* __restrict__ biass,
             uint16_t* __restrict__ Csh, uint16_t* __restrict__ Csl,
             uint16_t* __restrict__ Cvh, uint16_t* __restrict__ Cvl)
{
    extern __shared__ __align__(16) uint16_t dsm[];
    const int tid = threadIdx.x, lane = tid & 31, wid = tid >> 5;
    const int warp_m = wid >> 2, warp_n = wid & 3;
    const bool isS = (blockIdx.y < NSCALAR_BLOCKS);
    const size_t rowBase = (size_t)(isS ? blockIdx.y : blockIdx.y - NSCALAR_BLOCKS) * 128;
    const int colBase = blockIdx.x * 128;
    const float* A1 = isS ? A1s : A1v;
    const float* A2 = isS ? A2s : A2v;
    const uint16_t* Bh = isS ? Bhs : Bhv;
    const uint16_t* Bl = isS ? Bls : Blv;
    const float* bias = isS ? biass : nullptr;
    uint16_t* Ch = isS ? Csh : Cvh;
    uint16_t* Cl = isS ? Csl : Cvl;

    const int am = tid >> 1, ak = (tid & 1) * 8;
    const int bk = tid >> 4, bn = (tid & 15) * 8;

    const float* a1p = A1 + (rowBase + am) * H + ak;
    const float* a2p = A2 + (rowBase + am) * H + ak;
    const uint16_t* bhp = Bh + (size_t)bk * H + colBase + bn;
    const uint16_t* blp = Bl + (size_t)bk * H + colBase + bn;

    uint32_t sA0 = (uint32_t)__cvta_generic_to_shared(dsm);
    uint32_t sB0 = sA0 + 4 * ABUF_B;
    uint32_t bDst = sB0 + (uint32_t)((bk * BROW + bn) * 2);
    uint16_t* aStore = dsm + (am * AROW + ak);

    const int a_row0 = warp_m * 64 + (lane & 7) + ((lane >> 3) & 1) * 8;
    const int a_kgrp = lane >> 4;
    uint32_t aBase = sA0 + (uint32_t)((a_row0 * AROW + a_kgrp * 8) * 2);
    const int b_krow = (lane & 7) + ((lane >> 3) & 1) * 8;
    const int b_ngrp = lane >> 4;
    uint32_t bBase = sB0 + (uint32_t)((b_krow * BROW + warp_n * 32 + b_ngrp * 8) * 2);

    float acc[4][4][4];
#pragma unroll
    for (int i = 0; i < 4; i++)
#pragma unroll
        for (int j = 0; j < 4; j++)
#pragma unroll
            for (int q = 0; q < 4; q++) acc[i][j][q] = 0.f;

    cpa16(bDst, bhp);
    cpa16(bDst + B_PLANE_B, blp);
    cpa16(bDst + BBUF_B, bhp + (size_t)16 * H);
    cpa16(bDst + BBUF_B + B_PLANE_B, blp + (size_t)16 * H);
    cpa_commit();
    {
        float4 ax, ay;
        gloadA(a1p, a2p, 0, ax, ay);
        cvt_store8(aStore, aStore + A_HL, ax, ay);
        gloadA(a1p, a2p, 16, ax, ay);
        cvt_store8(aStore + ABUF_B / 2, aStore + ABUF_B / 2 + A_HL, ax, ay);
    }
    cpa_wait0();
    __syncthreads();

    const int NT = H / 16;
    for (int t = 0; t < NT; t += 2) {
        if (t + 2 < NT) {
            int c2 = t + 2, c3 = t + 3;
            size_t k2 = (size_t)c2 * 16, k3 = (size_t)c3 * 16;
            uint32_t bd2 = bDst + (uint32_t)((c2 & 3) * BBUF_B);
            uint32_t bd3 = bDst + (uint32_t)((c3 & 3) * BBUF_B);
            cpa16(bd2, bhp + k2 * H);
            cpa16(bd2 + B_PLANE_B, blp + k2 * H);
            cpa16(bd3, bhp + k3 * H);
            cpa16(bd3 + B_PLANE_B, blp + k3 * H);
            cpa_commit();
            float4 ax, ay;
            gloadA(a1p, a2p, (int)k2, ax, ay);
            cvt_store8(aStore + (c2 & 3) * (ABUF_B / 2),
                       aStore + (c2 & 3) * (ABUF_B / 2) + A_HL, ax, ay);
            gloadA(a1p, a2p, (int)k3, ax, ay);
            cvt_store8(aStore + (c3 & 3) * (ABUF_B / 2),
                       aStore + (c3 & 3) * (ABUF_B / 2) + A_HL, ax, ay);
        }
        mma_chunk(aBase + (uint32_t)((t & 3) * ABUF_B),
                  bBase + (uint32_t)((t & 3) * BBUF_B), acc);
        mma_chunk(aBase + (uint32_t)(((t + 1) & 3) * ABUF_B),
                  bBase + (uint32_t)(((t + 1) & 3) * BBUF_B), acc);
        if (t + 2 < NT) {
            cpa_wait0();
            __syncthreads();
        }
    }

#pragma unroll
    for (int mt = 0; mt < 4; mt++) {
        size_t r0 = rowBase + warp_m * 64 + mt * 16 + (lane >> 2);
#pragma unroll
        for (int nt = 0; nt < 4; nt++) {
            int col = colBase + warp_n * 32 + nt * 8 + (lane & 3) * 2;
            float v0 = acc[mt][nt][0], v1 = acc[mt][nt][1];
            float v2 = acc[mt][nt][2], v3 = acc[mt][nt][3];
            if (bias) {
                float2 bb = *(const float2*)&bias[col];
                v0 += bb.x; v1 += bb.y; v2 += bb.x; v3 += bb.y;
            }
            v0 = sspf(v0); v1 = sspf(v1); v2 = sspf(v2); v3 = sspf(v3);
            *(uint32_t*)&Ch[r0 * H + col]       = pk2(v0, v1);
            *(uint32_t*)&Cl[r0 * H + col]       = pk2(bres(v0), bres(v1));
            *(uint32_t*)&Ch[(r0 + 8) * H + col] = pk2(v2, v3);
            *(uint32_t*)&Cl[(r0 + 8) * H + col] = pk2(bres(v2), bres(v3));
        }
    }
}

// ---------------- layer-2 GEMM: bf16 planes in -> bf16 hi/lo planes out -----------
__global__ __launch_bounds__(256, 2)
void k_gemm2(const uint16_t* __restrict__ Ahs, const uint16_t* __restrict__ Als,
             const uint16_t* __restrict__ Ahv, const uint16_t* __restrict__ Alv,
             const uint16_t* __restrict__ Bhs, const uint16_t* __restrict__ Bls,
             const uint16_t* __restrict__ Bhv, const uint16_t* __restrict__ Blv,
             const float* __restrict__ biass,
             uint16_t* __restrict__ Csh, uint16_t* __restrict__ Csl,
             uint16_t* __restrict__ Cvh, uint16_t* __restrict__ Cvl)
{
    extern __shared__ __align__(16) uint16_t dsm[];
    const int tid = threadIdx.x, lane = tid & 31, wid = tid >> 5;
    const int warp_m = wid >> 2, warp_n = wid & 3;
    const bool isS = (blockIdx.y < NSCALAR_BLOCKS);
    const size_t rowBase = (size_t)(isS ? blockIdx.y : blockIdx.y - NSCALAR_BLOCKS) * 128;
    const int colBase = blockIdx.x * 128;
    const uint16_t* Ah = isS ? Ahs : Ahv;
    const uint16_t* Al = isS ? Als : Alv;
    const uint16_t* Bh = isS ? Bhs : Bhv;
    const uint16_t* Bl = isS ? Bls : Blv;
    const float* bias = isS ? biass : nullptr;
    uint16_t* Ch = isS ? Csh : Cvh;
    uint16_t* Cl = isS ? Csl : Cvl;

    const int am = tid >> 1, ak = (tid & 1) * 8;
    const int bk = tid >> 4, bn = (tid & 15) * 8;

    const uint16_t* ahp = Ah + (rowBase + am) * H + ak;
    const uint16_t* alp = Al + (rowBase + am) * H + ak;
    const uint16_t* bhp = Bh + (size_t)bk * H + colBase + bn;
    const uint16_t* blp = Bl + (size_t)bk * H + colBase + bn;

    uint32_t sA0 = (uint32_t)__cvta_generic_to_shared(dsm);
    uint32_t sB0 = sA0 + 4 * ABUF_B;
    uint32_t aDst = sA0 + (uint32_t)((am * AROW + ak) * 2);
    uint32_t bDst = sB0 + (uint32_t)((bk * BROW + bn) * 2);

    const int a_row0 = warp_m * 64 + (lane & 7) + ((lane >> 3) & 1) * 8;
    const int a_kgrp = lane >> 4;
    uint32_t aBase = sA0 + (uint32_t)((a_row0 * AROW + a_kgrp * 8) * 2);
    const int b_krow = (lane & 7) + ((lane >> 3) & 1) * 8;
    const int b_ngrp = lane >> 4;
    uint32_t bBase = sB0 + (uint32_t)((b_krow * BROW + warp_n * 32 + b_ngrp * 8) * 2);

    float acc[4][4][4];
#pragma unroll
    for (int i = 0; i < 4; i++)
#pragma unroll
        for (int j = 0; j < 4; j++)
#pragma unroll
            for (int q = 0; q < 4; q++) acc[i][j][q] = 0.f;

#pragma unroll
    for (int c = 0; c < 2; c++) {
        size_t k0 = (size_t)c * 16;
        uint32_t ad = aDst + (uint32_t)(c * ABUF_B);
        uint32_t bd = bDst + (uint32_t)(c * BBUF_B);
        cpa16(ad, ahp + k0);
        cpa16(ad + A_PLANE_B, alp + k0);
        cpa16(bd, bhp + k0 * H);
        cpa16(bd + B_PLANE_B, blp + k0 * H);
    }
    cpa_commit();
    cpa_wait0();
    __syncthreads();

    const int NT = H / 16;
    for (int t = 0; t < NT; t += 2) {
        if (t + 2 < NT) {
#pragma unroll
            for (int d = 2; d < 4; d++) {
                int c = t + d;
                size_t k0 = (size_t)c * 16;
                uint32_t ad = aDst + (uint32_t)((c & 3) * ABUF_B);
                uint32_t bd = bDst + (uint32_t)((c & 3) * BBUF_B);
                cpa16(ad, ahp + k0);
                cpa16(ad + A_PLANE_B, alp + k0);
                cpa16(bd, bhp + k0 * H);
                cpa16(bd + B_PLANE_B, blp + k0 * H);
            }
            cpa_commit();
        }
        mma_chunk(aBase + (uint32_t)((t & 3) * ABUF_B),
                  bBase + (uint32_t)((t & 3) * BBUF_B), acc);
        mma_chunk(aBase + (uint32_t)(((t + 1) & 3) * ABUF_B),
                  bBase + (uint32_t)(((t + 1) & 3) * BBUF_B), acc);
        if (t + 2 < NT) {
            cpa_wait0();
            __syncthreads();
        }
    }

    // epilogue: bias, split to bf16 hi/lo planes (same bytes as fp32; no cvt later)
#pragma unroll
    for (int mt = 0; mt < 4; mt++) {
        size_t r0 = rowBase + warp_m * 64 + mt * 16 + (lane >> 2);
#pragma unroll
        for (int nt = 0; nt < 4; nt++) {
            int col = colBase + warp_n * 32 + nt * 8 + (lane & 3) * 2;
            float v0 = acc[mt][nt][0], v1 = acc[mt][nt][1];
            float v2 = acc[mt][nt][2], v3 = acc[mt][nt][3];
            if (bias) {
                float2 bb = *(const float2*)&bias[col];
                v0 += bb.x; v1 += bb.y; v2 += bb.x; v3 += bb.y;
            }
            *(uint32_t*)&Ch[r0 * H + col]       = pk2(v0, v1);
            *(uint32_t*)&Cl[r0 * H + col]       = pk2(bres(v0), bres(v1));
            *(uint32_t*)&Ch[(r0 + 8) * H + col] = pk2(v2, v3);
            *(uint32_t*)&Cl[(r0 + 8) * H + col] = pk2(bres(v2), bres(v3));
        }
    }
}

// ---------------- per-fragment stats: pure cp.async Gram pipeline -----------------
// 4 chunk buffers issued up-front; variance fully Gram-derived:
// svar = trace(G) - (1^T G 1)/cnt, gram-sum taken from the mma registers.
#define ZROW 72
#define ZPLANE (64 * ZROW)
#define FRAG_SMEM (4 * 2 * ZPLANE * 2)   // 73728 bytes

__global__ void k_frag(float* __restrict__ out) {
    extern __shared__ __align__(16) uint16_t z[];
    __shared__ float sdiag[64];
    __shared__ float rd[48];
    __shared__ int s_last;
    int f = blockIdx.x, t = threadIdx.x;
    int cnt = g_counts[f], off = g_offsets[f];
    int wid = t >> 5, lane = t & 31;
    float serr = 0.f, derr = 0.f;
    float tr0 = 0.f, tr123 = 0.f, gs0 = 0.f, gs123 = 0.f;

    uint32_t z0 = (uint32_t)__cvta_generic_to_shared(z);

    if (cnt >= 2 && cnt <= MAXM) {
        const int Mt = (cnt + 15) >> 4;
        int tm[2] = {-1, -1}, tn[2] = {-1, -1};
        {
            int idx = 0;
            for (int mt = 0; mt < Mt; mt++)
                for (int nt = mt; nt < Mt; nt++) {
                    if ((idx & 7) == wid) {
                        int s = idx >> 3;
                        if (s < 2) { tm[s] = mt; tn[s] = nt; }
                    }
                    idx++;
                }
        }
        const int lrow = t >> 2;
        const int lkq = (t & 3) * 16;
        int lnd = (lrow < cnt) ? g_nodes[off + lrow] : -1;
        const int fr = (lane & 7) + ((lane >> 3) & 1) * 8;
        const int fk = (lane >> 4) * 8;
        const int sz = (lnd >= 0) ? 16 : 0;

        // issue all 4 chunks of a feature (4 commit groups, in order)
        auto issue_feat = [&](int feat) {
            const uint16_t *sh, *slo;
            if (lnd >= 0) {
                if (feat == 0) {
                    sh = g_sih + (size_t)lnd * H; slo = g_sil + (size_t)lnd * H;
                } else {
                    sh  = g_vih + ((size_t)lnd * 3 + feat - 1) * H;
                    slo = g_vil + ((size_t)lnd * 3 + feat - 1) * H;
                }
            } else { sh = g_sih; slo = g_sil; }
#pragma unroll
            for (int kc = 0; kc < 4; kc++) {
                uint32_t dst = z0 + (uint32_t)((kc * 2 * ZPLANE + lrow * ZROW + lkq) * 2);
                cpa16z(dst, sh + kc * 64 + lkq, sz);
                cpa16z(dst + 16, sh + kc * 64 + lkq + 8, sz);
                cpa16z(dst + ZPLANE * 2, slo + kc * 64 + lkq, sz);
                cpa16z(dst + ZPLANE * 2 + 16, slo + kc * 64 + lkq + 8, sz);
                cpa_commit();
            }
        };

        issue_feat(0);

        for (int feat = 0; feat < 4; feat++) {
            float acc[2][2][4];
#pragma unroll
            for (int a = 0; a < 2; a++)
#pragma unroll
                for (int b = 0; b < 2; b++)
#pragma unroll
                    for (int q = 0; q < 4; q++) acc[a][b][q] = 0.f;

            for (int kc = 0; kc < 4; kc++) {
                switch (kc) {
                    case 0: asm volatile("cp.async.wait_group 3;" ::: "memory"); break;
                    case 1: asm volatile("cp.async.wait_group 2;" ::: "memory"); break;
                    case 2: asm volatile("cp.async.wait_group 1;" ::: "memory"); break;
                    default: asm volatile("cp.async.wait_group 0;" ::: "memory"); break;
                }
                __syncthreads();
                uint32_t zhb = z0 + (uint32_t)(kc * 2 * ZPLANE * 2);
                uint32_t zlb = zhb + (uint32_t)(ZPLANE * 2);
#pragma unroll
                for (int ti = 0; ti < 2; ti++) {
                    if (tm[ti] < 0) continue;
#pragma unroll
                    for (int ks = 0; ks < 4; ks++) {
                        uint32_t aoff = (uint32_t)(((tm[ti] * 16 + fr) * ZROW + ks * 16 + fk) * 2);
                        uint32_t boff = (uint32_t)(((tn[ti] * 16 + fr) * ZROW + ks * 16 + fk) * 2);
                        uint32_t ah[4], al[4], bh[4], bl[4];
                        ldsm4(zhb + aoff, ah);
                        ldsm4(zlb + aoff, al);
                        ldsm4(zhb + boff, bh);
                        ldsm4(zlb + boff, bl);
                        mma16816(acc[ti][0], ah, bh[0], bh[2]);
                        mma16816(acc[ti][1], ah, bh[1], bh[3]);
                        mma16816(acc[ti][0], ah, bl[0], bl[2]);
                        mma16816(acc[ti][1], ah, bl[1], bl[3]);
                        mma16816(acc[ti][0], al, bh[0], bh[2]);
                        mma16816(acc[ti][1], al, bh[1], bh[3]);
                    }
                }
            }
            __syncthreads();                 // all mma done: buffers reusable
            if (feat < 3) issue_feat(feat + 1);   // overlap loads with epilogue

            // diagonal -> smem
            {
                int r = lane >> 2, c = (lane & 3) * 2;
#pragma unroll
                for (int ti = 0; ti < 2; ti++) {
                    if (tm[ti] < 0 || tm[ti] != tn[ti]) continue;
#pragma unroll
                    for (int hh = 0; hh < 2; hh++) {
                        int nl0 = hh * 8 + c;
                        if (r == nl0)     sdiag[tm[ti] * 16 + r]     = acc[ti][hh][0];
                        if (r == nl0 + 1) sdiag[tm[ti] * 16 + r]     = acc[ti][hh][1];
                        if (r + 8 == nl0)     sdiag[tm[ti] * 16 + r + 8] = acc[ti][hh][2];
                        if (r + 8 == nl0 + 1) sdiag[tm[ti] * 16 + r + 8] = acc[ti][hh][3];
                    }
                }
            }
            __syncthreads();

            // trace (variance term 1)
            if (t < cnt) {
                float d = sdiag[t];
                if (feat == 0) tr0 += d; else tr123 += d;
            }

            // pair errors + gram-sum (variance term 2: 1^T G 1)
            {
                float err = 0.f, gsum = 0.f;
                int r = lane >> 2, c = (lane & 3) * 2;
#pragma unroll
                for (int ti = 0; ti < 2; ti++) {
                    if (tm[ti] < 0) continue;
                    int mb = tm[ti] * 16, nb = tn[ti] * 16;
                    bool isDiag = (tm[ti] == tn[ti]);
#pragma unroll
                    for (int hh = 0; hh < 2; hh++) {
                        int n0 = nb + hh * 8 + c;
#pragma unroll
                        for (int q = 0; q < 4; q++) {
                            int m = mb + r + (q >> 1) * 8;
                            int n = n0 + (q & 1);
                            float v = acc[ti][hh][q];
                            if (!isDiag) {
                                gsum += 2.f * v;       // all entries strictly upper
                            } else {
                                if (m < n) gsum += 2.f * v;
                                else if (m == n) gsum += v;
                            }
                            if (n < cnt && m < n) {
                                float rs = rsqrtf(fmaxf(sdiag[m] * sdiag[n], 1e-24f));
                                float e = fmaf(v, rs, -C_SIM);
                                err = fmaf(e, e, err);
                            }
                        }
                    }
                }
                if (feat == 0) { serr = err; gs0 = gsum; }
                else { derr += err; gs123 += gsum; }
            }
        }
    } else if (cnt > MAXM) {
        // fallback (never expected): gmem-direct from bf16 planes, exact two-pass
        float* mean = (float*)z;
        float as = 0.f, a0m = 0.f, a1m = 0.f, a2m = 0.f;
        for (int m = 0; m < cnt; m++) {
            int nd = g_nodes[off + m];
            as += b2f(g_sih[(size_t)nd * H + t]) + b2f(g_sil[(size_t)nd * H + t]);
            size_t vb = (size_t)nd * 3 * H;
            a0m += b2f(g_vih[vb + t]) + b2f(g_vil[vb + t]);
            a1m += b2f(g_vih[vb + H + t]) + b2f(g_vil[vb + H + t]);
            a2m += b2f(g_vih[vb + 2 * H + t]) + b2f(g_vil[vb + 2 * H + t]);
        }
        float invn = 1.f / (float)cnt;
        mean[t] = as * invn; mean[256 + t] = a0m * invn;
        mean[512 + t] = a1m * invn; mean[768 + t] = a2m * invn;
        __syncthreads();
        for (int m = 0; m < cnt; m++) {
            int nd = g_nodes[off + m];
            float d0 = b2f(g_sih[(size_t)nd * H + t]) + b2f(g_sil[(size_t)nd * H + t]) - mean[t];
            tr0 = fmaf(d0, d0, tr0);
            size_t vb = (size_t)nd * 3 * H;
            float d1 = b2f(g_vih[vb + t]) + b2f(g_vil[vb + t]) - mean[256 + t];
            float d2 = b2f(g_vih[vb + H + t]) + b2f(g_vil[vb + H + t]) - mean[512 + t];
            float d3 = b2f(g_vih[vb + 2 * H + t]) + b2f(g_vil[vb + 2 * H + t]) - mean[768 + t];
            tr123 = fmaf(d1, d1, tr123); tr123 = fmaf(d2, d2, tr123); tr123 = fmaf(d3, d3, tr123);
        }
        for (int feat = 0; feat < 4; feat++) {
            float acc = 0.f;
            for (int a = wid; a < cnt - 1; a += 8) {
                int na = g_nodes[off + a];
                const uint16_t* rah = (feat == 0) ? g_sih + (size_t)na * H
                                                  : g_vih + ((size_t)na * 3 + feat - 1) * H;
                const uint16_t* ral = (feat == 0) ? g_sil + (size_t)na * H
                                                  : g_vil + ((size_t)na * 3 + feat - 1) * H;
                for (int b = a + 1 + lane; b < cnt; b += 32) {
                    int nb = g_nodes[off + b];
                    const uint16_t* rbh = (feat == 0) ? g_sih + (size_t)nb * H
                                                      : g_vih + ((size_t)nb * 3 + feat - 1) * H;
                    const uint16_t* rbl = (feat == 0) ? g_sil + (size_t)nb * H
                                                      : g_vil + ((size_t)nb * 3 + feat - 1) * H;
                    float dot = 0.f, sa = 0.f, sb = 0.f;
                    for (int k = 0; k < H; k++) {
                        float x = b2f(rah[k]) + b2f(ral[k]);
                        float y = b2f(rbh[k]) + b2f(rbl[k]);
                        dot = fmaf(x, y, dot);
                        sa = fmaf(x, x, sa);
                        sb = fmaf(y, y, sb);
                    }
                    float e = dot / (fmaxf(sqrtf(sa), 1e-12f) * fmaxf(sqrtf(sb), 1e-12f)) - C_SIM;
                    acc = fmaf(e, e, acc);
                }
            }
            if (feat == 0) serr = acc; else derr += acc;
        }
        // gs stays 0 -> svar = tr0 (already exact deviations)
    }

    for (int o = 16; o; o >>= 1) {
        tr0   += __shfl_xor_sync(0xffffffffu, tr0, o);
        tr123 += __shfl_xor_sync(0xffffffffu, tr123, o);
        gs0   += __shfl_xor_sync(0xffffffffu, gs0, o);
        gs123 += __shfl_xor_sync(0xffffffffu, gs123, o);
        serr  += __shfl_xor_sync(0xffffffffu, serr, o);
        derr  += __shfl_xor_sync(0xffffffffu, derr, o);
    }
    if (lane == 0) {
        rd[wid] = tr0; rd[8 + wid] = tr123; rd[16 + wid] = gs0;
        rd[24 + wid] = gs123; rd[32 + wid] = serr; rd[40 + wid] = derr;
    }
    __syncthreads();
    if (t == 0) {
        float a = 0.f, b = 0.f, c = 0.f, d = 0.f, e = 0.f, g = 0.f;
        for (int i = 0; i < 8; i++) {
            a += rd[i]; b += rd[8 + i]; c += rd[16 + i];
            d += rd[24 + i]; e += rd[32 + i]; g += rd[40 + i];
        }
        float invn = 1.f / (float)(cnt > 0 ? cnt : 1);
        g_svar[f] = a - c * invn;
        g_vvar[f] = b - d * invn;
        g_ssim[f] = e;
        g_dir[f]  = g;
        __threadfence();
        int old = atomicAdd(&g_done, 1);
        s_last = (old == NF - 1) ? 1 : 0;
    }
    __syncthreads();

    if (s_last) {
        __threadfence();
        float n  = (float)g_counts[t];
        float pc = n * (n - 1.f) * 0.5f;
        float ns  = fmaxf(n, 1.f);
        float pcs = fmaxf(pc, 1.f);
        float sl = g_svar[t] / ns + g_ssim[t] / pcs;
        float vl = g_vvar[t] / ns + g_dir[t] / (3.f * pcs);
        float fl = 0.5f * sl + 0.5f * vl;
        float val  = (pc > 0.f) ? fl : 0.f;
        float cntv = (pc > 0.f) ? 1.f : 0.f;
        for (int o = 16; o; o >>= 1) {
            val  += __shfl_xor_sync(0xffffffffu, val, o);
            cntv += __shfl_xor_sync(0xffffffffu, cntv, o);
        }
        __syncthreads();
        if (lane == 0) { rd[wid] = val; rd[8 + wid] = cntv; }
        __syncthreads();
        if (t == 0) {
            float tot = 0.f, tc = 0.f;
            for (int i = 0; i < 8; i++) { tot += rd[i]; tc += rd[8 + i]; }
            out[0] = (tc > 0.f) ? tot / fmaxf(tc, 1.f) : 0.f;
            g_done = 0;
        }
    }
}

// ---------------- launch ----------------
extern "C" void kernel_launch(void* const* d_in, const int* in_sizes, int n_in,
                              void* d_out, int out_size)
{
    const float* ss = (const float*)d_in[0];
    const float* sl = (const float*)d_in[1];
    const float* vs = (const float*)d_in[2];
    const float* vl = (const float*)d_in[3];
    const float* W1 = (const float*)d_in[4];
    const float* b1 = (const float*)d_in[5];
    const float* W2 = (const float*)d_in[6];
    const float* b2 = (const float*)d_in[7];
    const float* V1 = (const float*)d_in[8];
    const float* V2 = (const float*)d_in[9];
    const int*   frag = (const int*)d_in[10];
    float* out = (float*)d_out;

    void *pwh, *pwl, *ptsh, *ptsl, *ptvh, *ptvl, *psih, *psil, *pvih, *pvil;
    cudaGetSymbolAddress(&pwh, g_wh);
    cudaGetSymbolAddress(&pwl, g_wl);
    cudaGetSymbolAddress(&ptsh, g_tsh);
    cudaGetSymbolAddress(&ptsl, g_tsl);
    cudaGetSymbolAddress(&ptvh, g_tvh);
    cudaGetSymbolAddress(&ptvl, g_tvl);
    cudaGetSymbolAddress(&psih, g_sih);
    cudaGetSymbolAddress(&psil, g_sil);
    cudaGetSymbolAddress(&pvih, g_vih);
    cudaGetSymbolAddress(&pvil, g_vil);
    const uint16_t* wh = (const uint16_t*)pwh;
    const uint16_t* wl = (const uint16_t*)pwl;

    k_setup<<<257, 256>>>(frag, W1, W2, V1, V2);

    cudaFuncSetAttribute(k_gemm1, cudaFuncAttributeMaxDynamicSharedMemorySize, G_SMEM);
    cudaFuncSetAttribute(k_gemm2, cudaFuncAttributeMaxDynamicSharedMemorySize, G_SMEM);
    cudaFuncSetAttribute(k_frag, cudaFuncAttributeMaxDynamicSharedMemorySize, FRAG_SMEM);

    dim3 g(2, NSCALAR_BLOCKS + 192);
    k_gemm1<<<g, 256, G_SMEM>>>(ss, sl, vs, vl,
                                wh + 0 * 65536, wl + 0 * 65536,
                                wh + 2 * 65536, wl + 2 * 65536,
                                b1,
                                (uint16_t*)ptsh, (uint16_t*)ptsl,
                                (uint16_t*)ptvh, (uint16_t*)ptvl);
    k_gemm2<<<g, 256, G_SMEM>>>((uint16_t*)ptsh, (uint16_t*)ptsl,
                                (uint16_t*)ptvh, (uint16_t*)ptvl,
                                wh + 1 * 65536, wl + 1 * 65536,
                                wh + 3 * 65536, wl + 3 * 65536,
                                b2,
                                (uint16_t*)psih, (uint16_t*)psil,
                                (uint16_t*)pvih, (uint16_t*)pvil);

    k_frag<<<NF, 256, FRAG_SMEM>>>(out);
}

// round 15
// speedup vs baseline: 1.7802x; 1.0075x over previous
#include <cuda_runtime.h>
#include <cuda_bf16.h>
#include <math.h>
#include <stdint.h>

#define N_NODES 8192
#define H 256
#define NF 256
#define R_MIX 0.3f
#define C_SIM 0.8f
#define LOG2F_ 0.69314718055994530942f
#define MAXM 64

// ---------------- scratch (static device globals) ----------------
__device__ uint16_t g_tsh[ 8192 * 256], g_tsl[ 8192 * 256];   // layer-1 out (bf16 hi/lo)
__device__ uint16_t g_tvh[24576 * 256], g_tvl[24576 * 256];
__device__ uint16_t g_sih[ 8192 * 256], g_sil[ 8192 * 256];   // layer-2 out (bf16 hi/lo)
__device__ uint16_t g_vih[24576 * 256], g_vil[24576 * 256];
__device__ uint16_t g_wh[4][65536];
__device__ uint16_t g_wl[4][65536];
__device__ int   g_counts [NF];
__device__ int   g_offsets[NF + 1];
__device__ int   g_nodes  [N_NODES];
__device__ float g_svar[NF], g_vvar[NF], g_ssim[NF], g_dir[NF];
__device__ int   g_done;

__device__ __forceinline__ float sspf(float x) {
    float ax = fabsf(x);
    return fmaxf(x, 0.f) + log1pf(__expf(-ax)) - LOG2F_;
}
__device__ __forceinline__ uint32_t pk2(float a, float b) {
    __nv_bfloat162 t = __floats2bfloat162_rn(a, b);
    return *reinterpret_cast<uint32_t*>(&t);
}
__device__ __forceinline__ float bres(float x) {
    __nv_bfloat16 h = __float2bfloat16(x);
    return x - __bfloat162float(h);
}
__device__ __forceinline__ float b2f(uint16_t u) {
    __nv_bfloat16 h = *reinterpret_cast<__nv_bfloat16*>(&u);
    return __bfloat162float(h);
}

// ---------------- mma/ldmatrix/cp.async wrappers (sm_103-safe) ----------------
__device__ __forceinline__ void ldsm4(uint32_t addr, uint32_t* r) {
    asm volatile("ldmatrix.sync.aligned.m8n8.x4.shared.b16 {%0,%1,%2,%3}, [%4];"
                 : "=r"(r[0]), "=r"(r[1]), "=r"(r[2]), "=r"(r[3]) : "r"(addr));
}
__device__ __forceinline__ void ldsm4t(uint32_t addr, uint32_t* r) {
    asm volatile("ldmatrix.sync.aligned.m8n8.x4.trans.shared.b16 {%0,%1,%2,%3}, [%4];"
                 : "=r"(r[0]), "=r"(r[1]), "=r"(r[2]), "=r"(r[3]) : "r"(addr));
}
__device__ __forceinline__ void mma16816(float* c, const uint32_t* a, uint32_t b0, uint32_t b1) {
    asm volatile(
        "mma.sync.aligned.m16n8k16.row.col.f32.bf16.bf16.f32 "
        "{%0,%1,%2,%3},{%4,%5,%6,%7},{%8,%9},{%0,%1,%2,%3};"
        : "+f"(c[0]), "+f"(c[1]), "+f"(c[2]), "+f"(c[3])
        : "r"(a[0]), "r"(a[1]), "r"(a[2]), "r"(a[3]), "r"(b0), "r"(b1));
}
__device__ __forceinline__ void cpa16(uint32_t dst, const void* src) {
    asm volatile("cp.async.cg.shared.global [%0], [%1], 16;" :: "r"(dst), "l"(src) : "memory");
}
__device__ __forceinline__ void cpa16z(uint32_t dst, const void* src, int sz) {
    asm volatile("cp.async.cg.shared.global [%0], [%1], 16, %2;"
                 :: "r"(dst), "l"(src), "r"(sz) : "memory");
}
__device__ __forceinline__ void cpa_commit() {
    asm volatile("cp.async.commit_group;" ::: "memory");
}
__device__ __forceinline__ void cpa_wait0() {
    asm volatile("cp.async.wait_group 0;" ::: "memory");
}

// ---------------- fused setup: block 0 = counting sort, blocks 1..256 = prepw ------
__global__ void k_setup(const int* __restrict__ frag,
                        const float* __restrict__ W1, const float* __restrict__ W2,
                        const float* __restrict__ V1, const float* __restrict__ V2)
{
    if (blockIdx.x == 0) {
        __shared__ int s_sc[8 * 256];
        __shared__ int s_off[256];
        __shared__ int s_tmp[256];
        int t = threadIdx.x, w = t >> 5, l = t & 31;

        for (int j = t; j < 2048; j += 256) s_sc[j] = 0;
        __syncthreads();

        int fv[32], lp[32];
#pragma unroll
        for (int c = 0; c < 32; c++) fv[c] = frag[(w * 32 + c) * 32 + l];
        for (int c = 0; c < 32; c++) {
            int f = fv[c];
            bool ok = (f >= 0 && f < NF);
            unsigned mask = __match_any_sync(0xffffffffu, f);
            int rank = __popc(mask & ((1u << l) - 1u));
            int before = ok ? s_sc[w * 256 + f] : 0;
            lp[c] = before + rank;
            __syncwarp();
            if (ok && rank == 0) s_sc[w * 256 + f] = before + __popc(mask);
            __syncwarp();
        }
        __syncthreads();

        {
            int run = 0;
#pragma unroll
            for (int w2 = 0; w2 < 8; w2++) {
                int v = s_sc[w2 * 256 + t];
                s_sc[w2 * 256 + t] = run;
                run += v;
            }
            g_counts[t] = run;
            s_tmp[t] = run;
            __syncthreads();
            for (int d = 1; d < 256; d <<= 1) {
                int u = (t >= d) ? s_tmp[t - d] : 0;
                __syncthreads();
                s_tmp[t] += u;
                __syncthreads();
            }
            s_off[t] = s_tmp[t] - run;
            g_offsets[t] = s_off[t];
            if (t == 255) g_offsets[256] = s_tmp[255];
        }
        __syncthreads();

        for (int c = 0; c < 32; c++) {
            int f = fv[c];
            if (f >= 0 && f < NF) {
                int pos = s_off[f] + s_sc[w * 256 + f] + lp[c];
                if (pos >= 0 && pos < N_NODES)
                    g_nodes[pos] = (w * 32 + c) * 32 + l;
            }
        }
    } else {
        int bb = blockIdx.x - 1;
        int m = bb >> 6;
        const float* src = (m == 0) ? W1 : (m == 1) ? W2 : (m == 2) ? V1 : V2;
        int i0 = ((bb & 63) * 256 + threadIdx.x) * 4;
        float4 v = *(const float4*)(src + i0);
        uint16_t* oh = g_wh[m];
        uint16_t* ol = g_wl[m];
        *(uint32_t*)&oh[i0]     = pk2(v.x, v.y);
        *(uint32_t*)&oh[i0 + 2] = pk2(v.z, v.w);
        *(uint32_t*)&ol[i0]     = pk2(bres(v.x), bres(v.y));
        *(uint32_t*)&ol[i0 + 2] = pk2(bres(v.z), bres(v.w));
    }
}

// ------------- shared GEMM pieces (proven) -------------
#define AROW 24
#define BROW 136
#define A_HL (128 * AROW)
#define B_HL (16 * BROW)
#define A_PLANE_B (A_HL * 2)
#define B_PLANE_B (B_HL * 2)
#define ABUF_B (2 * A_PLANE_B)
#define BBUF_B (2 * B_PLANE_B)
#define G_SMEM (4 * ABUF_B + 4 * BBUF_B)
#define NSCALAR_BLOCKS 64

__device__ __forceinline__ void mma_chunk(uint32_t aOff, uint32_t bOff, float acc[4][4][4]) {
    uint32_t ah[4][4], bh[2][4], tmp[2][4], al4[4];
#pragma unroll
    for (int mt = 0; mt < 4; mt++) ldsm4(aOff + mt * (16 * AROW * 2), ah[mt]);
#pragma unroll
    for (int st = 0; st < 2; st++) ldsm4t(bOff + st * 32, bh[st]);
#pragma unroll
    for (int mt = 0; mt < 4; mt++)
#pragma unroll
        for (int nt = 0; nt < 4; nt++)
            mma16816(acc[mt][nt], ah[mt], bh[nt >> 1][(nt & 1) * 2],
                     bh[nt >> 1][(nt & 1) * 2 + 1]);
#pragma unroll
    for (int st = 0; st < 2; st++) ldsm4t(bOff + B_PLANE_B + st * 32, tmp[st]);
#pragma unroll
    for (int mt = 0; mt < 4; mt++)
#pragma unroll
        for (int nt = 0; nt < 4; nt++)
            mma16816(acc[mt][nt], ah[mt], tmp[nt >> 1][(nt & 1) * 2],
                     tmp[nt >> 1][(nt & 1) * 2 + 1]);
#pragma unroll
    for (int mt = 0; mt < 4; mt++) {
        ldsm4(aOff + A_PLANE_B + mt * (16 * AROW * 2), al4);
#pragma unroll
        for (int nt = 0; nt < 4; nt++)
            mma16816(acc[mt][nt], al4, bh[nt >> 1][(nt & 1) * 2],
                     bh[nt >> 1][(nt & 1) * 2 + 1]);
    }
}

__device__ __forceinline__ void gloadA(const float* __restrict__ a1p,
                                       const float* __restrict__ a2p,
                                       int k0, float4& x, float4& y) {
    x = *(const float4*)(a1p + k0);
    y = *(const float4*)(a1p + k0 + 4);
    float4 u = *(const float4*)(a2p + k0);
    float4 v = *(const float4*)(a2p + k0 + 4);
    const float w = 1.f - R_MIX;
    x.x = fmaf(x.x, R_MIX, u.x * w); x.y = fmaf(x.y, R_MIX, u.y * w);
    x.z = fmaf(x.z, R_MIX, u.z * w); x.w = fmaf(x.w, R_MIX, u.w * w);
    y.x = fmaf(y.x, R_MIX, v.x * w); y.y = fmaf(y.y, R_MIX, v.y * w);
    y.z = fmaf(y.z, R_MIX, v.z * w); y.w = fmaf(y.w, R_MIX, v.w * w);
}

__device__ __forceinline__ void cvt_store8(uint16_t* hi_p, uint16_t* lo_p,
                                           const float4& x, const float4& y) {
    uint4 hv, lv;
    hv.x = pk2(x.x, x.y); hv.y = pk2(x.z, x.w);
    hv.z = pk2(y.x, y.y); hv.w = pk2(y.z, y.w);
    lv.x = pk2(bres(x.x), bres(x.y)); lv.y = pk2(bres(x.z), bres(x.w));
    lv.z = pk2(bres(y.x), bres(y.y)); lv.w = pk2(bres(y.z), bres(y.w));
    *reinterpret_cast<uint4*>(hi_p) = hv;
    *reinterpret_cast<uint4*>(lo_p) = lv;
}

// ---------------- layer-1 GEMM (unchanged) ----------------
__global__ __launch_bounds__(256, 2)
void k_gemm1(const float* __restrict__ A1s, const float* __restrict__ A2s,
             const float* __restrict__ A1v, const float* __restrict__ A2v,
             const uint16_t* __restrict__ Bhs, const uint16_t* __restrict__ Bls,
             const uint16_t* __restrict__ Bhv, const uint16_t* __restrict__ Blv,
             const float* __restrict__ biass,
             uint16_t* __restrict__ Csh, uint16_t* __restrict__ Csl,
             uint16_t* __restrict__ Cvh, uint16_t* __restrict__ Cvl)
{
    extern __shared__ __align__(16) uint16_t dsm[];
    const int tid = threadIdx.x, lane = tid & 31, wid = tid >> 5;
    const int warp_m = wid >> 2, warp_n = wid & 3;
    const bool isS = (blockIdx.y < NSCALAR_BLOCKS);
    const size_t rowBase = (size_t)(isS ? blockIdx.y : blockIdx.y - NSCALAR_BLOCKS) * 128;
    const int colBase = blockIdx.x * 128;
    const float* A1 = isS ? A1s : A1v;
    const float* A2 = isS ? A2s : A2v;
    const uint16_t* Bh = isS ? Bhs : Bhv;
    const uint16_t* Bl = isS ? Bls : Blv;
    const float* bias = isS ? biass : nullptr;
    uint16_t* Ch = isS ? Csh : Cvh;
    uint16_t* Cl = isS ? Csl : Cvl;

    const int am = tid >> 1, ak = (tid & 1) * 8;
    const int bk = tid >> 4, bn = (tid & 15) * 8;

    const float* a1p = A1 + (rowBase + am) * H + ak;
    const float* a2p = A2 + (rowBase + am) * H + ak;
    const uint16_t* bhp = Bh + (size_t)bk * H + colBase + bn;
    const uint16_t* blp = Bl + (size_t)bk * H + colBase + bn;

    uint32_t sA0 = (uint32_t)__cvta_generic_to_shared(dsm);
    uint32_t sB0 = sA0 + 4 * ABUF_B;
    uint32_t bDst = sB0 + (uint32_t)((bk * BROW + bn) * 2);
    uint16_t* aStore = dsm + (am * AROW + ak);

    const int a_row0 = warp_m * 64 + (lane & 7) + ((lane >> 3) & 1) * 8;
    const int a_kgrp = lane >> 4;
    uint32_t aBase = sA0 + (uint32_t)((a_row0 * AROW + a_kgrp * 8) * 2);
    const int b_krow = (lane & 7) + ((lane >> 3) & 1) * 8;
    const int b_ngrp = lane >> 4;
    uint32_t bBase = sB0 + (uint32_t)((b_krow * BROW + warp_n * 32 + b_ngrp * 8) * 2);

    float acc[4][4][4];
#pragma unroll
    for (int i = 0; i < 4; i++)
#pragma unroll
        for (int j = 0; j < 4; j++)
#pragma unroll
            for (int q = 0; q < 4; q++) acc[i][j][q] = 0.f;

    cpa16(bDst, bhp);
    cpa16(bDst + B_PLANE_B, blp);
    cpa16(bDst + BBUF_B, bhp + (size_t)16 * H);
    cpa16(bDst + BBUF_B + B_PLANE_B, blp + (size_t)16 * H);
    cpa_commit();
    {
        float4 ax, ay;
        gloadA(a1p, a2p, 0, ax, ay);
        cvt_store8(aStore, aStore + A_HL, ax, ay);
        gloadA(a1p, a2p, 16, ax, ay);
        cvt_store8(aStore + ABUF_B / 2, aStore + ABUF_B / 2 + A_HL, ax, ay);
    }
    cpa_wait0();
    __syncthreads();

    const int NT = H / 16;
    for (int t = 0; t < NT; t += 2) {
        if (t + 2 < NT) {
            int c2 = t + 2, c3 = t + 3;
            size_t k2 = (size_t)c2 * 16, k3 = (size_t)c3 * 16;
            uint32_t bd2 = bDst + (uint32_t)((c2 & 3) * BBUF_B);
            uint32_t bd3 = bDst + (uint32_t)((c3 & 3) * BBUF_B);
            cpa16(bd2, bhp + k2 * H);
            cpa16(bd2 + B_PLANE_B, blp + k2 * H);
            cpa16(bd3, bhp + k3 * H);
            cpa16(bd3 + B_PLANE_B, blp + k3 * H);
            cpa_commit();
            float4 ax, ay;
            gloadA(a1p, a2p, (int)k2, ax, ay);
            cvt_store8(aStore + (c2 & 3) * (ABUF_B / 2),
                       aStore + (c2 & 3) * (ABUF_B / 2) + A_HL, ax, ay);
            gloadA(a1p, a2p, (int)k3, ax, ay);
            cvt_store8(aStore + (c3 & 3) * (ABUF_B / 2),
                       aStore + (c3 & 3) * (ABUF_B / 2) + A_HL, ax, ay);
        }
        mma_chunk(aBase + (uint32_t)((t & 3) * ABUF_B),
                  bBase + (uint32_t)((t & 3) * BBUF_B), acc);
        mma_chunk(aBase + (uint32_t)(((t + 1) & 3) * ABUF_B),
                  bBase + (uint32_t)(((t + 1) & 3) * BBUF_B), acc);
        if (t + 2 < NT) {
            cpa_wait0();
            __syncthreads();
        }
    }

#pragma unroll
    for (int mt = 0; mt < 4; mt++) {
        size_t r0 = rowBase + warp_m * 64 + mt * 16 + (lane >> 2);
#pragma unroll
        for (int nt = 0; nt < 4; nt++) {
            int col = colBase + warp_n * 32 + nt * 8 + (lane & 3) * 2;
            float v0 = acc[mt][nt][0], v1 = acc[mt][nt][1];
            float v2 = acc[mt][nt][2], v3 = acc[mt][nt][3];
            if (bias) {
                float2 bb = *(const float2*)&bias[col];
                v0 += bb.x; v1 += bb.y; v2 += bb.x; v3 += bb.y;
            }
            v0 = sspf(v0); v1 = sspf(v1); v2 = sspf(v2); v3 = sspf(v3);
            *(uint32_t*)&Ch[r0 * H + col]       = pk2(v0, v1);
            *(uint32_t*)&Cl[r0 * H + col]       = pk2(bres(v0), bres(v1));
            *(uint32_t*)&Ch[(r0 + 8) * H + col] = pk2(v2, v3);
            *(uint32_t*)&Cl[(r0 + 8) * H + col] = pk2(bres(v2), bres(v3));
        }
    }
}

// ---------------- layer-2 GEMM: bf16 planes in -> bf16 hi/lo planes out -----------
__global__ __launch_bounds__(256, 2)
void k_gemm2(const uint16_t* __restrict__ Ahs, const uint16_t* __restrict__ Als,
             const uint16_t* __restrict__ Ahv, const uint16_t* __restrict__ Alv,
             const uint16_t* __restrict__ Bhs, const uint16_t* __restrict__ Bls,
             const uint16_t* __restrict__ Bhv, const uint16_t* __restrict__ Blv,
             const float* __restrict__ biass,
             uint16_t* __restrict__ Csh, uint16_t* __restrict__ Csl,
             uint16_t* __restrict__ Cvh, uint16_t* __restrict__ Cvl)
{
    extern __shared__ __align__(16) uint16_t dsm[];
    const int tid = threadIdx.x, lane = tid & 31, wid = tid >> 5;
    const int warp_m = wid >> 2, warp_n = wid & 3;
    const bool isS = (blockIdx.y < NSCALAR_BLOCKS);
    const size_t rowBase = (size_t)(isS ? blockIdx.y : blockIdx.y - NSCALAR_BLOCKS) * 128;
    const int colBase = blockIdx.x * 128;
    const uint16_t* Ah = isS ? Ahs : Ahv;
    const uint16_t* Al = isS ? Als : Alv;
    const uint16_t* Bh = isS ? Bhs : Bhv;
    const uint16_t* Bl = isS ? Bls : Blv;
    const float* bias = isS ? biass : nullptr;
    uint16_t* Ch = isS ? Csh : Cvh;
    uint16_t* Cl = isS ? Csl : Cvl;

    const int am = tid >> 1, ak = (tid & 1) * 8;
    const int bk = tid >> 4, bn = (tid & 15) * 8;

    const uint16_t* ahp = Ah + (rowBase + am) * H + ak;
    const uint16_t* alp = Al + (rowBase + am) * H + ak;
    const uint16_t* bhp = Bh + (size_t)bk * H + colBase + bn;
    const uint16_t* blp = Bl + (size_t)bk * H + colBase + bn;

    uint32_t sA0 = (uint32_t)__cvta_generic_to_shared(dsm);
    uint32_t sB0 = sA0 + 4 * ABUF_B;
    uint32_t aDst = sA0 + (uint32_t)((am * AROW + ak) * 2);
    uint32_t bDst = sB0 + (uint32_t)((bk * BROW + bn) * 2);

    const int a_row0 = warp_m * 64 + (lane & 7) + ((lane >> 3) & 1) * 8;
    const int a_kgrp = lane >> 4;
    uint32_t aBase = sA0 + (uint32_t)((a_row0 * AROW + a_kgrp * 8) * 2);
    const int b_krow = (lane & 7) + ((lane >> 3) & 1) * 8;
    const int b_ngrp = lane >> 4;
    uint32_t bBase = sB0 + (uint32_t)((b_krow * BROW + warp_n * 32 + b_ngrp * 8) * 2);

    float acc[4][4][4];
#pragma unroll
    for (int i = 0; i < 4; i++)
#pragma unroll
        for (int j = 0; j < 4; j++)
#pragma unroll
            for (int q = 0; q < 4; q++) acc[i][j][q] = 0.f;

#pragma unroll
    for (int c = 0; c < 2; c++) {
        size_t k0 = (size_t)c * 16;
        uint32_t ad = aDst + (uint32_t)(c * ABUF_B);
        uint32_t bd = bDst + (uint32_t)(c * BBUF_B);
        cpa16(ad, ahp + k0);
        cpa16(ad + A_PLANE_B, alp + k0);
        cpa16(bd, bhp + k0 * H);
        cpa16(bd + B_PLANE_B, blp + k0 * H);
    }
    cpa_commit();
    cpa_wait0();
    __syncthreads();

    const int NT = H / 16;
    for (int t = 0; t < NT; t += 2) {
        if (t + 2 < NT) {
#pragma unroll
            for (int d = 2; d < 4; d++) {
                int c = t + d;
                size_t k0 = (size_t)c * 16;
                uint32_t ad = aDst + (uint32_t)((c & 3) * ABUF_B);
                uint32_t bd = bDst + (uint32_t)((c & 3) * BBUF_B);
                cpa16(ad, ahp + k0);
                cpa16(ad + A_PLANE_B, alp + k0);
                cpa16(bd, bhp + k0 * H);
                cpa16(bd + B_PLANE_B, blp + k0 * H);
            }
            cpa_commit();
        }
        mma_chunk(aBase + (uint32_t)((t & 3) * ABUF_B),
                  bBase + (uint32_t)((t & 3) * BBUF_B), acc);
        mma_chunk(aBase + (uint32_t)(((t + 1) & 3) * ABUF_B),
                  bBase + (uint32_t)(((t + 1) & 3) * BBUF_B), acc);
        if (t + 2 < NT) {
            cpa_wait0();
            __syncthreads();
        }
    }

#pragma unroll
    for (int mt = 0; mt < 4; mt++) {
        size_t r0 = rowBase + warp_m * 64 + mt * 16 + (lane >> 2);
#pragma unroll
        for (int nt = 0; nt < 4; nt++) {
            int col = colBase + warp_n * 32 + nt * 8 + (lane & 3) * 2;
            float v0 = acc[mt][nt][0], v1 = acc[mt][nt][1];
            float v2 = acc[mt][nt][2], v3 = acc[mt][nt][3];
            if (bias) {
                float2 bb = *(const float2*)&bias[col];
                v0 += bb.x; v1 += bb.y; v2 += bb.x; v3 += bb.y;
            }
            *(uint32_t*)&Ch[r0 * H + col]       = pk2(v0, v1);
            *(uint32_t*)&Cl[r0 * H + col]       = pk2(bres(v0), bres(v1));
            *(uint32_t*)&Ch[(r0 + 8) * H + col] = pk2(v2, v3);
            *(uint32_t*)&Cl[(r0 + 8) * H + col] = pk2(bres(v2), bres(v3));
        }
    }
}

// ---------------- per-fragment stats: 2-buffer 16-unit Gram pipeline --------------
// units = 4 features x 4 chunks, flat-pipelined with lookahead 2 across feature
// boundaries. smem 36.9KB -> 2 CTAs/SM -> single wave of 256 blocks.
#define ZROW 72
#define ZPLANE (64 * ZROW)
#define FRAG_SMEM (2 * 2 * ZPLANE * 2)   // 36864 bytes

__global__ __launch_bounds__(256, 2)
void k_frag(float* __restrict__ out) {
    extern __shared__ __align__(16) uint16_t z[];
    __shared__ float sdiag[64];
    __shared__ float rd[48];
    __shared__ int s_last;
    int f = blockIdx.x, t = threadIdx.x;
    int cnt = g_counts[f], off = g_offsets[f];
    int wid = t >> 5, lane = t & 31;
    float serr = 0.f, derr = 0.f;
    float tr0 = 0.f, tr123 = 0.f, gs0 = 0.f, gs123 = 0.f;

    uint32_t z0 = (uint32_t)__cvta_generic_to_shared(z);

    if (cnt >= 2 && cnt <= MAXM) {
        const int Mt = (cnt + 15) >> 4;
        int tm[2] = {-1, -1}, tn[2] = {-1, -1};
        {
            int idx = 0;
            for (int mt = 0; mt < Mt; mt++)
                for (int nt = mt; nt < Mt; nt++) {
                    if ((idx & 7) == wid) {
                        int s = idx >> 3;
                        if (s < 2) { tm[s] = mt; tn[s] = nt; }
                    }
                    idx++;
                }
        }
        const int lrow = t >> 2;
        const int lkq = (t & 3) * 16;
        int lnd = (lrow < cnt) ? g_nodes[off + lrow] : -1;
        const int fr = (lane & 7) + ((lane >> 3) & 1) * 8;
        const int fk = (lane >> 4) * 8;
        const int sz = (lnd >= 0) ? 16 : 0;

        // issue one 64x64 chunk unit u (feat = u>>2, kc = u&3) into buffer u&1
        auto issue_unit = [&](int u) {
            int feat = u >> 2, kc = u & 3;
            const uint16_t *sh, *slo;
            if (lnd >= 0) {
                if (feat == 0) {
                    sh = g_sih + (size_t)lnd * H; slo = g_sil + (size_t)lnd * H;
                } else {
                    sh  = g_vih + ((size_t)lnd * 3 + feat - 1) * H;
                    slo = g_vil + ((size_t)lnd * 3 + feat - 1) * H;
                }
            } else { sh = g_sih; slo = g_sil; }
            uint32_t dst = z0 + (uint32_t)(((u & 1) * 2 * ZPLANE + lrow * ZROW + lkq) * 2);
            cpa16z(dst, sh + kc * 64 + lkq, sz);
            cpa16z(dst + 16, sh + kc * 64 + lkq + 8, sz);
            cpa16z(dst + ZPLANE * 2, slo + kc * 64 + lkq, sz);
            cpa16z(dst + ZPLANE * 2 + 16, slo + kc * 64 + lkq + 8, sz);
            cpa_commit();
        };

        issue_unit(0);
        issue_unit(1);

        float acc[2][2][4];
        for (int u = 0; u < 16; u++) {
            int kc = u & 3;
            if (kc == 0) {
#pragma unroll
                for (int a = 0; a < 2; a++)
#pragma unroll
                    for (int b = 0; b < 2; b++)
#pragma unroll
                        for (int q = 0; q < 4; q++) acc[a][b][q] = 0.f;
            }
            if (u < 15) asm volatile("cp.async.wait_group 1;" ::: "memory");
            else        asm volatile("cp.async.wait_group 0;" ::: "memory");
            __syncthreads();

            uint32_t zhb = z0 + (uint32_t)((u & 1) * 2 * ZPLANE * 2);
            uint32_t zlb = zhb + (uint32_t)(ZPLANE * 2);
#pragma unroll
            for (int ti = 0; ti < 2; ti++) {
                if (tm[ti] < 0) continue;
#pragma unroll
                for (int ks = 0; ks < 4; ks++) {
                    uint32_t aoff = (uint32_t)(((tm[ti] * 16 + fr) * ZROW + ks * 16 + fk) * 2);
                    uint32_t boff = (uint32_t)(((tn[ti] * 16 + fr) * ZROW + ks * 16 + fk) * 2);
                    uint32_t ah[4], al[4], bh[4], bl[4];
                    ldsm4(zhb + aoff, ah);
                    ldsm4(zlb + aoff, al);
                    ldsm4(zhb + boff, bh);
                    ldsm4(zlb + boff, bl);
                    mma16816(acc[ti][0], ah, bh[0], bh[2]);
                    mma16816(acc[ti][1], ah, bh[1], bh[3]);
                    mma16816(acc[ti][0], ah, bl[0], bl[2]);
                    mma16816(acc[ti][1], ah, bl[1], bl[3]);
                    mma16816(acc[ti][0], al, bh[0], bh[2]);
                    mma16816(acc[ti][1], al, bh[1], bh[3]);
                }
            }
            __syncthreads();                     // buffer u&1 free for reuse
            if (u + 2 < 16) issue_unit(u + 2);   // refill; overlaps epilogue below

            if (kc == 3) {
                int feat = u >> 2;
                // diagonal -> smem
                {
                    int r = lane >> 2, c = (lane & 3) * 2;
#pragma unroll
                    for (int ti = 0; ti < 2; ti++) {
                        if (tm[ti] < 0 || tm[ti] != tn[ti]) continue;
#pragma unroll
                        for (int hh = 0; hh < 2; hh++) {
                            int nl0 = hh * 8 + c;
                            if (r == nl0)     sdiag[tm[ti] * 16 + r]     = acc[ti][hh][0];
                            if (r == nl0 + 1) sdiag[tm[ti] * 16 + r]     = acc[ti][hh][1];
                            if (r + 8 == nl0)     sdiag[tm[ti] * 16 + r + 8] = acc[ti][hh][2];
                            if (r + 8 == nl0 + 1) sdiag[tm[ti] * 16 + r + 8] = acc[ti][hh][3];
                        }
                    }
                }
                __syncthreads();

                // trace (variance term 1)
                if (t < cnt) {
                    float d = sdiag[t];
                    if (feat == 0) tr0 += d; else tr123 += d;
                }

                // pair errors + gram-sum (variance term 2)
                {
                    float err = 0.f, gsum = 0.f;
                    int r = lane >> 2, c = (lane & 3) * 2;
#pragma unroll
                    for (int ti = 0; ti < 2; ti++) {
                        if (tm[ti] < 0) continue;
                        int mb = tm[ti] * 16, nb = tn[ti] * 16;
                        bool isDiag = (tm[ti] == tn[ti]);
#pragma unroll
                        for (int hh = 0; hh < 2; hh++) {
                            int n0 = nb + hh * 8 + c;
#pragma unroll
                            for (int q = 0; q < 4; q++) {
                                int m = mb + r + (q >> 1) * 8;
                                int n = n0 + (q & 1);
                                float v = acc[ti][hh][q];
                                if (!isDiag) {
                                    gsum += 2.f * v;
                                } else {
                                    if (m < n) gsum += 2.f * v;
                                    else if (m == n) gsum += v;
                                }
                                if (n < cnt && m < n) {
                                    float rs = rsqrtf(fmaxf(sdiag[m] * sdiag[n], 1e-24f));
                                    float e = fmaf(v, rs, -C_SIM);
                                    err = fmaf(e, e, err);
                                }
                            }
                        }
                    }
                    if (feat == 0) { serr = err; gs0 = gsum; }
                    else { derr += err; gs123 += gsum; }
                }
                __syncthreads();   // sdiag safe for next feature
            }
        }
    } else if (cnt > MAXM) {
        // fallback (never expected): gmem-direct from bf16 planes, exact two-pass
        float* mean = (float*)z;
        float as = 0.f, a0m = 0.f, a1m = 0.f, a2m = 0.f;
        for (int m = 0; m < cnt; m++) {
            int nd = g_nodes[off + m];
            as += b2f(g_sih[(size_t)nd * H + t]) + b2f(g_sil[(size_t)nd * H + t]);
            size_t vb = (size_t)nd * 3 * H;
            a0m += b2f(g_vih[vb + t]) + b2f(g_vil[vb + t]);
            a1m += b2f(g_vih[vb + H + t]) + b2f(g_vil[vb + H + t]);
            a2m += b2f(g_vih[vb + 2 * H + t]) + b2f(g_vil[vb + 2 * H + t]);
        }
        float invn = 1.f / (float)cnt;
        mean[t] = as * invn; mean[256 + t] = a0m * invn;
        mean[512 + t] = a1m * invn; mean[768 + t] = a2m * invn;
        __syncthreads();
        for (int m = 0; m < cnt; m++) {
            int nd = g_nodes[off + m];
            float d0 = b2f(g_sih[(size_t)nd * H + t]) + b2f(g_sil[(size_t)nd * H + t]) - mean[t];
            tr0 = fmaf(d0, d0, tr0);
            size_t vb = (size_t)nd * 3 * H;
            float d1 = b2f(g_vih[vb + t]) + b2f(g_vil[vb + t]) - mean[256 + t];
            float d2 = b2f(g_vih[vb + H + t]) + b2f(g_vil[vb + H + t]) - mean[512 + t];
            float d3 = b2f(g_vih[vb + 2 * H + t]) + b2f(g_vil[vb + 2 * H + t]) - mean[768 + t];
            tr123 = fmaf(d1, d1, tr123); tr123 = fmaf(d2, d2, tr123); tr123 = fmaf(d3, d3, tr123);
        }
        for (int feat = 0; feat < 4; feat++) {
            float acc = 0.f;
            for (int a = wid; a < cnt - 1; a += 8) {
                int na = g_nodes[off + a];
                const uint16_t* rah = (feat == 0) ? g_sih + (size_t)na * H
                                                  : g_vih + ((size_t)na * 3 + feat - 1) * H;
                const uint16_t* ral = (feat == 0) ? g_sil + (size_t)na * H
                                                  : g_vil + ((size_t)na * 3 + feat - 1) * H;
                for (int b = a + 1 + lane; b < cnt; b += 32) {
                    int nb = g_nodes[off + b];
                    const uint16_t* rbh = (feat == 0) ? g_sih + (size_t)nb * H
                                                      : g_vih + ((size_t)nb * 3 + feat - 1) * H;
                    const uint16_t* rbl = (feat == 0) ? g_sil + (size_t)nb * H
                                                      : g_vil + ((size_t)nb * 3 + feat - 1) * H;
                    float dot = 0.f, sa = 0.f, sb = 0.f;
                    for (int k = 0; k < H; k++) {
                        float x = b2f(rah[k]) + b2f(ral[k]);
                        float y = b2f(rbh[k]) + b2f(rbl[k]);
                        dot = fmaf(x, y, dot);
                        sa = fmaf(x, x, sa);
                        sb = fmaf(y, y, sb);
                    }
                    float e = dot / (fmaxf(sqrtf(sa), 1e-12f) * fmaxf(sqrtf(sb), 1e-12f)) - C_SIM;
                    acc = fmaf(e, e, acc);
                }
            }
            if (feat == 0) serr = acc; else derr += acc;
        }
    }

    for (int o = 16; o; o >>= 1) {
        tr0   += __shfl_xor_sync(0xffffffffu, tr0, o);
        tr123 += __shfl_xor_sync(0xffffffffu, tr123, o);
        gs0   += __shfl_xor_sync(0xffffffffu, gs0, o);
        gs123 += __shfl_xor_sync(0xffffffffu, gs123, o);
        serr  += __shfl_xor_sync(0xffffffffu, serr, o);
        derr  += __shfl_xor_sync(0xffffffffu, derr, o);
    }
    if (lane == 0) {
        rd[wid] = tr0; rd[8 + wid] = tr123; rd[16 + wid] = gs0;
        rd[24 + wid] = gs123; rd[32 + wid] = serr; rd[40 + wid] = derr;
    }
    __syncthreads();
    if (t == 0) {
        float a = 0.f, b = 0.f, c = 0.f, d = 0.f, e = 0.f, g = 0.f;
        for (int i = 0; i < 8; i++) {
            a += rd[i]; b += rd[8 + i]; c += rd[16 + i];
            d += rd[24 + i]; e += rd[32 + i]; g += rd[40 + i];
        }
        float invn = 1.f / (float)(cnt > 0 ? cnt : 1);
        g_svar[f] = a - c * invn;
        g_vvar[f] = b - d * invn;
        g_ssim[f] = e;
        g_dir[f]  = g;
        __threadfence();
        int old = atomicAdd(&g_done, 1);
        s_last = (old == NF - 1) ? 1 : 0;
    }
    __syncthreads();

    if (s_last) {
        __threadfence();
        float n  = (float)g_counts[t];
        float pc = n * (n - 1.f) * 0.5f;
        float ns  = fmaxf(n, 1.f);
        float pcs = fmaxf(pc, 1.f);
        float sl = g_svar[t] / ns + g_ssim[t] / pcs;
        float vl = g_vvar[t] / ns + g_dir[t] / (3.f * pcs);
        float fl = 0.5f * sl + 0.5f * vl;
        float val  = (pc > 0.f) ? fl : 0.f;
        float cntv = (pc > 0.f) ? 1.f : 0.f;
        for (int o = 16; o; o >>= 1) {
            val  += __shfl_xor_sync(0xffffffffu, val, o);
            cntv += __shfl_xor_sync(0xffffffffu, cntv, o);
        }
        __syncthreads();
        if (lane == 0) { rd[wid] = val; rd[8 + wid] = cntv; }
        __syncthreads();
        if (t == 0) {
            float tot = 0.f, tc = 0.f;
            for (int i = 0; i < 8; i++) { tot += rd[i]; tc += rd[8 + i]; }
            out[0] = (tc > 0.f) ? tot / fmaxf(tc, 1.f) : 0.f;
            g_done = 0;
        }
    }
}

// ---------------- launch ----------------
extern "C" void kernel_launch(void* const* d_in, const int* in_sizes, int n_in,
                              void* d_out, int out_size)
{
    const float* ss = (const float*)d_in[0];
    const float* sl = (const float*)d_in[1];
    const float* vs = (const float*)d_in[2];
    const float* vl = (const float*)d_in[3];
    const float* W1 = (const float*)d_in[4];
    const float* b1 = (const float*)d_in[5];
    const float* W2 = (const float*)d_in[6];
    const float* b2 = (const float*)d_in[7];
    const float* V1 = (const float*)d_in[8];
    const float* V2 = (const float*)d_in[9];
    const int*   frag = (const int*)d_in[10];
    float* out = (float*)d_out;

    void *pwh, *pwl, *ptsh, *ptsl, *ptvh, *ptvl, *psih, *psil, *pvih, *pvil;
    cudaGetSymbolAddress(&pwh, g_wh);
    cudaGetSymbolAddress(&pwl, g_wl);
    cudaGetSymbolAddress(&ptsh, g_tsh);
    cudaGetSymbolAddress(&ptsl, g_tsl);
    cudaGetSymbolAddress(&ptvh, g_tvh);
    cudaGetSymbolAddress(&ptvl, g_tvl);
    cudaGetSymbolAddress(&psih, g_sih);
    cudaGetSymbolAddress(&psil, g_sil);
    cudaGetSymbolAddress(&pvih, g_vih);
    cudaGetSymbolAddress(&pvil, g_vil);
    const uint16_t* wh = (const uint16_t*)pwh;
    const uint16_t* wl = (const uint16_t*)pwl;

    k_setup<<<257, 256>>>(frag, W1, W2, V1, V2);

    cudaFuncSetAttribute(k_gemm1, cudaFuncAttributeMaxDynamicSharedMemorySize, G_SMEM);
    cudaFuncSetAttribute(k_gemm2, cudaFuncAttributeMaxDynamicSharedMemorySize, G_SMEM);
    cudaFuncSetAttribute(k_frag, cudaFuncAttributeMaxDynamicSharedMemorySize, FRAG_SMEM);

    dim3 g(2, NSCALAR_BLOCKS + 192);
    k_gemm1<<<g, 256, G_SMEM>>>(ss, sl, vs, vl,
                                wh + 0 * 65536, wl + 0 * 65536,
                                wh + 2 * 65536, wl + 2 * 65536,
                                b1,
                                (uint16_t*)ptsh, (uint16_t*)ptsl,
                                (uint16_t*)ptvh, (uint16_t*)ptvl);
    k_gemm2<<<g, 256, G_SMEM>>>((uint16_t*)ptsh, (uint16_t*)ptsl,
                                (uint16_t*)ptvh, (uint16_t*)ptvl,
                                wh + 1 * 65536, wl + 1 * 65536,
                                wh + 3 * 65536, wl + 3 * 65536,
                                b2,
                                (uint16_t*)psih, (uint16_t*)psil,
                                (uint16_t*)pvih, (uint16_t*)pvil);

    k_frag<<<NF, 256, FRAG_SMEM>>>(out);
}